// round 8
// baseline (speedup 1.0000x reference)
#include <cuda_runtime.h>
#include <cuda_bf16.h>
#include <cstdint>

// Problem constants
static constexpr int BATCH = 4;
static constexpr int SEQ   = 2048;
static constexpr int DM    = 1024;
static constexpr int NH    = 16;
static constexpr int DH    = 64;
static constexpr int ROWS  = BATCH * SEQ;        // 8192
static constexpr size_t NX = (size_t)ROWS * DM;  // 8388608
static constexpr size_t NW = (size_t)DM * DM;    // 1048576

// Scratch (device globals: allocation-free)
__device__ __nv_bfloat16 g_xh[NX];
__device__ __nv_bfloat16 g_xl[NX];
__device__ __nv_bfloat16 g_Wh[4 * NW];   // Wq|Wk|Wv|Wo
__device__ __nv_bfloat16 g_Wl[4 * NW];
__device__ __nv_bfloat16 g_qkvh[3 * NX]; // Q|K|V hi
__device__ __nv_bfloat16 g_qkvl[3 * NX]; // Q|K|V lo
__device__ __nv_bfloat16 g_th[NX];
__device__ __nv_bfloat16 g_tl[NX];

// ---------------------------------------------------------------------------
// Helpers
// ---------------------------------------------------------------------------
__device__ __forceinline__ uint32_t smem_u32(const void* p) {
    uint32_t a;
    asm("{ .reg .u64 t; cvta.to.shared.u64 t, %1; cvt.u32.u64 %0, t; }"
        : "=r"(a) : "l"(p));
    return a;
}
__device__ __forceinline__ uint32_t sw128(uint32_t off) {
    return off ^ ((off >> 3) & 0x70);
}
__device__ __forceinline__ void cp_async16(uint32_t saddr, const void* gaddr) {
    asm volatile("cp.async.cg.shared.global [%0], [%1], 16;"
                 :: "r"(saddr), "l"(gaddr));
}
#define CP_COMMIT() asm volatile("cp.async.commit_group;")
#define CP_WAIT(n)  asm volatile("cp.async.wait_group %0;" :: "n"(n))

__device__ __forceinline__ void ldsm_x4(uint32_t (&r)[4], uint32_t addr) {
    asm volatile("ldmatrix.sync.aligned.m8n8.x4.shared.b16 {%0,%1,%2,%3}, [%4];"
                 : "=r"(r[0]), "=r"(r[1]), "=r"(r[2]), "=r"(r[3]) : "r"(addr));
}
__device__ __forceinline__ void ldsm_x4_t(uint32_t (&r)[4], uint32_t addr) {
    asm volatile("ldmatrix.sync.aligned.m8n8.x4.trans.shared.b16 {%0,%1,%2,%3}, [%4];"
                 : "=r"(r[0]), "=r"(r[1]), "=r"(r[2]), "=r"(r[3]) : "r"(addr));
}
__device__ __forceinline__ void mma_bf16(float (&d)[4], const uint32_t (&a)[4],
                                         const uint32_t* b) {
    asm volatile(
        "mma.sync.aligned.m16n8k16.row.col.f32.bf16.bf16.f32 "
        "{%0,%1,%2,%3}, {%4,%5,%6,%7}, {%8,%9}, {%0,%1,%2,%3};"
        : "+f"(d[0]), "+f"(d[1]), "+f"(d[2]), "+f"(d[3])
        : "r"(a[0]), "r"(a[1]), "r"(a[2]), "r"(a[3]), "r"(b[0]), "r"(b[1]));
}

__device__ __forceinline__ void split_store_pair(float a, float b,
                                                 __nv_bfloat16* hp, __nv_bfloat16* lp) {
    __nv_bfloat162 h2 = __float22bfloat162_rn(make_float2(a, b));
    float2 hf = __bfloat1622float2(h2);
    __nv_bfloat162 l2 = __float22bfloat162_rn(make_float2(a - hf.x, b - hf.y));
    *reinterpret_cast<uint32_t*>(hp) = *reinterpret_cast<const uint32_t*>(&h2);
    *reinterpret_cast<uint32_t*>(lp) = *reinterpret_cast<const uint32_t*>(&l2);
}
__device__ __forceinline__ void pack_split(float a, float b, uint32_t& ph, uint32_t& pl) {
    __nv_bfloat162 h2 = __float22bfloat162_rn(make_float2(a, b));
    float2 hf = __bfloat1622float2(h2);
    __nv_bfloat162 l2 = __float22bfloat162_rn(make_float2(a - hf.x, b - hf.y));
    ph = *reinterpret_cast<const uint32_t*>(&h2);
    pl = *reinterpret_cast<const uint32_t*>(&l2);
}

// ---------------------------------------------------------------------------
// fp32 -> (hi, lo) bf16 split
// ---------------------------------------------------------------------------
__global__ __launch_bounds__(256) void split_bf16_kernel(
    const float* __restrict__ src, __nv_bfloat16* __restrict__ hi,
    __nv_bfloat16* __restrict__ lo, int n4)
{
    int i = blockIdx.x * blockDim.x + threadIdx.x;
    if (i >= n4) return;
    float4 v = reinterpret_cast<const float4*>(src)[i];
    __nv_bfloat162 h0 = __float22bfloat162_rn(make_float2(v.x, v.y));
    __nv_bfloat162 h1 = __float22bfloat162_rn(make_float2(v.z, v.w));
    float2 f0 = __bfloat1622float2(h0), f1 = __bfloat1622float2(h1);
    __nv_bfloat162 l0 = __float22bfloat162_rn(make_float2(v.x - f0.x, v.y - f0.y));
    __nv_bfloat162 l1 = __float22bfloat162_rn(make_float2(v.z - f1.x, v.w - f1.y));
    uint2 hv, lv;
    hv.x = *reinterpret_cast<uint32_t*>(&h0); hv.y = *reinterpret_cast<uint32_t*>(&h1);
    lv.x = *reinterpret_cast<uint32_t*>(&l0); lv.y = *reinterpret_cast<uint32_t*>(&l1);
    reinterpret_cast<uint2*>(hi)[i] = hv;
    reinterpret_cast<uint2*>(lo)[i] = lv;
}

// ---------------------------------------------------------------------------
// bf16-split GEMM (NT), K = 1024 fixed. 128x256 CTA tile, BK=32,
// 3-stage cp.async ring (48KB/stage), 256 threads, warp tile 64x64 (2m x 4n).
// ---------------------------------------------------------------------------
static constexpr int A_TILE_B  = 128 * 128;            // 16 KB
static constexpr int B_TILE_B  = 256 * 128;            // 32 KB
static constexpr int STAGE_B   = A_TILE_B + B_TILE_B;  // 48 KB
static constexpr int GSTAGES   = 3;
static constexpr int GEMM_SMEM = GSTAGES * STAGE_B;    // 147456

template <bool SPLIT_OUT>
__global__ __launch_bounds__(256, 1) void gemm_mma_split_kernel(
    const __nv_bfloat16* __restrict__ Ah, const __nv_bfloat16* __restrict__ Al,
    const __nv_bfloat16* __restrict__ Bh, const __nv_bfloat16* __restrict__ Bl,
    float* __restrict__ C, __nv_bfloat16* __restrict__ Ch,
    __nv_bfloat16* __restrict__ Cl)
{
    extern __shared__ char smem[];
    const uint32_t sbase = smem_u32(smem);
    constexpr int K   = DM;
    constexpr int NKT = K / 32;

    const int tid   = threadIdx.x;
    const int wid   = tid >> 5;
    const int lane  = tid & 31;
    const int warpm = wid >> 2;          // 0..1 (64 rows each)
    const int warpn = wid & 3;           // 0..3 (64 cols each)
    const int row0  = blockIdx.y * 128;
    const int col0  = blockIdx.x * 256;

    auto load_stage = [&](int s, int kt) {
        const uint32_t As = sbase + s * STAGE_B;
        const uint32_t Bs = As + A_TILE_B;
        const size_t kofs = (size_t)kt * 32;
        const __nv_bfloat16* Ah0 = Ah + (size_t)row0 * K + kofs;
        const __nv_bfloat16* Al0 = Al + (size_t)row0 * K + kofs;
        const __nv_bfloat16* Bh0 = Bh + (size_t)col0 * K + kofs;
        const __nv_bfloat16* Bl0 = Bl + (size_t)col0 * K + kofs;
        #pragma unroll
        for (int t = 0; t < 4; t++) {        // A: 128 rows x 8 chunks
            int v = t * 256 + tid;
            int r = v >> 3;
            int c = v & 7;
            uint32_t soff = sw128((uint32_t)(r * 128 + c * 16));
            cp_async16(As + soff, (c < 4 ? Ah0 : Al0) + (size_t)r * K + (c & 3) * 8);
        }
        #pragma unroll
        for (int t = 0; t < 8; t++) {        // B: 256 rows x 8 chunks
            int v = t * 256 + tid;
            int r = v >> 3;
            int c = v & 7;
            uint32_t soff = sw128((uint32_t)(r * 128 + c * 16));
            cp_async16(Bs + soff, (c < 4 ? Bh0 : Bl0) + (size_t)r * K + (c & 3) * 8);
        }
    };

    float acc[4][8][4];
    #pragma unroll
    for (int i = 0; i < 4; i++)
        #pragma unroll
        for (int j = 0; j < 8; j++)
            #pragma unroll
            for (int k = 0; k < 4; k++) acc[i][j][k] = 0.0f;

    load_stage(0, 0); CP_COMMIT();
    load_stage(1, 1); CP_COMMIT();

    for (int kt = 0; kt < NKT; kt++) {
        CP_WAIT(1);
        __syncthreads();

        const uint32_t As = sbase + (kt % 3) * STAGE_B;
        const uint32_t Bs = As + A_TILE_B;

        #pragma unroll
        for (int kc = 0; kc < 2; kc++) {
            const int jh = kc * 2;
            const int jl = 4 + kc * 2;

            // Ah + Bh -> hh
            uint32_t Ahf[4][4], Bhf[8][2];
            #pragma unroll
            for (int mt = 0; mt < 4; mt++) {
                int row = warpm * 64 + mt * 16 + (lane & 15);
                ldsm_x4(Ahf[mt], As + sw128((uint32_t)(row * 128 + (jh + (lane >> 4)) * 16)));
            }
            #pragma unroll
            for (int p = 0; p < 4; p++) {
                int row = warpn * 64 + p * 16 + ((lane >> 4) << 3) + (lane & 7);
                uint32_t t4[4];
                ldsm_x4(t4, Bs + sw128((uint32_t)(row * 128 + (jh + ((lane >> 3) & 1)) * 16)));
                Bhf[p * 2][0]     = t4[0]; Bhf[p * 2][1]     = t4[1];
                Bhf[p * 2 + 1][0] = t4[2]; Bhf[p * 2 + 1][1] = t4[3];
            }
            #pragma unroll
            for (int mt = 0; mt < 4; mt++)
                #pragma unroll
                for (int nt = 0; nt < 8; nt++)
                    mma_bf16(acc[mt][nt], Ahf[mt], Bhf[nt]);

            // Bl -> hl
            uint32_t Blf[8][2];
            #pragma unroll
            for (int p = 0; p < 4; p++) {
                int row = warpn * 64 + p * 16 + ((lane >> 4) << 3) + (lane & 7);
                uint32_t t4[4];
                ldsm_x4(t4, Bs + sw128((uint32_t)(row * 128 + (jl + ((lane >> 3) & 1)) * 16)));
                Blf[p * 2][0]     = t4[0]; Blf[p * 2][1]     = t4[1];
                Blf[p * 2 + 1][0] = t4[2]; Blf[p * 2 + 1][1] = t4[3];
            }
            #pragma unroll
            for (int mt = 0; mt < 4; mt++)
                #pragma unroll
                for (int nt = 0; nt < 8; nt++)
                    mma_bf16(acc[mt][nt], Ahf[mt], Blf[nt]);

            // Al -> lh
            uint32_t Alf[4][4];
            #pragma unroll
            for (int mt = 0; mt < 4; mt++) {
                int row = warpm * 64 + mt * 16 + (lane & 15);
                ldsm_x4(Alf[mt], As + sw128((uint32_t)(row * 128 + (jl + (lane >> 4)) * 16)));
            }
            #pragma unroll
            for (int mt = 0; mt < 4; mt++)
                #pragma unroll
                for (int nt = 0; nt < 8; nt++)
                    mma_bf16(acc[mt][nt], Alf[mt], Bhf[nt]);
        }

        if (kt + 2 < NKT) load_stage((kt + 2) % 3, kt + 2);
        CP_COMMIT();
    }

    const int g = lane >> 2;
    const int t = lane & 3;
    if (SPLIT_OUT) {
        const int mat  = col0 >> 10;     // 256 | 1024, tile never spans matrices
        const int colb = col0 & 1023;
        __nv_bfloat16* ch = Ch + (size_t)mat * NX;
        __nv_bfloat16* cl = Cl + (size_t)mat * NX;
        #pragma unroll
        for (int mt = 0; mt < 4; mt++)
            #pragma unroll
            for (int nt = 0; nt < 8; nt++) {
                int row = row0 + warpm * 64 + mt * 16 + g;
                int col = colb + warpn * 64 + nt * 8 + t * 2;
                split_store_pair(acc[mt][nt][0], acc[mt][nt][1],
                                 ch + (size_t)row * DM + col, cl + (size_t)row * DM + col);
                split_store_pair(acc[mt][nt][2], acc[mt][nt][3],
                                 ch + (size_t)(row + 8) * DM + col,
                                 cl + (size_t)(row + 8) * DM + col);
            }
    } else {
        #pragma unroll
        for (int mt = 0; mt < 4; mt++)
            #pragma unroll
            for (int nt = 0; nt < 8; nt++) {
                int row = row0 + warpm * 64 + mt * 16 + g;
                int col = col0 + warpn * 64 + nt * 8 + t * 2;
                float2 v0 = make_float2(acc[mt][nt][0], acc[mt][nt][1]);
                float2 v1 = make_float2(acc[mt][nt][2], acc[mt][nt][3]);
                *reinterpret_cast<float2*>(&C[(size_t)row * DM + col])       = v0;
                *reinterpret_cast<float2*>(&C[(size_t)(row + 8) * DM + col]) = v1;
            }
    }
}

// ---------------------------------------------------------------------------
// Tensor-core flash attention (split-bf16, causal), BM=128, BN=64.
// 4 warps x 32 rows each (2 m-tiles/warp) -> K/V fragments amortized 2x.
// Q reloaded from smem per tile (cuts register peak). 128 threads.
// SMEM = Q 32KB + 2 stages x 32KB = 96KB -> 2 CTAs/SM.
// ---------------------------------------------------------------------------
static constexpr int ATTN_SMEM = 32768 + 2 * 32768;   // 98304
static constexpr float SCALE_L2E = 0.125f * 1.4426950408889634f;

__global__ __launch_bounds__(128) void flash_attn_mma_kernel(
    const __nv_bfloat16* __restrict__ qh, const __nv_bfloat16* __restrict__ ql,
    const __nv_bfloat16* __restrict__ kh, const __nv_bfloat16* __restrict__ kl,
    const __nv_bfloat16* __restrict__ vh, const __nv_bfloat16* __restrict__ vl,
    __nv_bfloat16* __restrict__ th, __nv_bfloat16* __restrict__ tl)
{
    extern __shared__ char smem[];
    const uint32_t sbase = smem_u32(smem);

    const int tid  = threadIdx.x;
    const int wid  = tid >> 5;        // 0..3, owns rows [wid*32, wid*32+31]
    const int lane = tid & 31;
    const int g    = lane >> 2;
    const int t    = lane & 3;

    const int qb = (SEQ / 128 - 1) - blockIdx.x;   // heavy blocks first
    const int bh = blockIdx.y;
    const int b  = bh >> 4;
    const int h  = bh & 15;
    const int q0 = qb * 128;
    const int bofs = b * SEQ;
    const int NT = 2 * qb + 2;                      // kv tiles of 64
    const int rw0 = q0 + wid * 32;                  // warp's first row

    auto load_q = [&]() {
        #pragma unroll
        for (int term = 0; term < 2; term++) {
            const __nv_bfloat16* src = term ? ql : qh;
            #pragma unroll
            for (int tt = 0; tt < 8; tt++) {
                int v = tt * 128 + tid;     // 128 rows x 8 chunks
                int r = v >> 3;
                int c = v & 7;
                cp_async16(sbase + term * 16384 + sw128((uint32_t)(r * 128 + c * 16)),
                           src + (size_t)(bofs + q0 + r) * DM + h * 64 + c * 8);
            }
        }
    };
    auto load_kv = [&](int stage, int kt2) {
        const int kv = kt2 * 64;
        const uint32_t base = sbase + 32768 + stage * 32768;
        const __nv_bfloat16* bufs[4] = {kh, kl, vh, vl};
        #pragma unroll
        for (int buf = 0; buf < 4; buf++) {
            #pragma unroll
            for (int tt = 0; tt < 4; tt++) {
                int v = tt * 128 + tid;
                int r = v >> 3;             // 0..63
                int c = v & 7;
                cp_async16(base + buf * 8192 + sw128((uint32_t)(r * 128 + c * 16)),
                           bufs[buf] + (size_t)(bofs + kv + r) * DM + h * 64 + c * 8);
            }
        }
    };

    load_q();
    load_kv(0, 0); CP_COMMIT();
    load_kv(1, NT > 1 ? 1 : 0); CP_COMMIT();
    CP_WAIT(1);
    __syncthreads();

    float m[4], l[4];                   // [mt*2 + (upper rows)]
    #pragma unroll
    for (int i = 0; i < 4; i++) { m[i] = -1e30f; l[i] = 0.0f; }
    float oacc[2][8][4];
    #pragma unroll
    for (int mt = 0; mt < 2; mt++)
        #pragma unroll
        for (int nt = 0; nt < 8; nt++)
            #pragma unroll
            for (int c = 0; c < 4; c++) oacc[mt][nt][c] = 0.0f;

    for (int kt = 0; kt < NT; kt++) {
        if (kt + 1 < NT) { CP_WAIT(1); } else { CP_WAIT(0); }
        __syncthreads();

        const int kv0 = kt * 64;
        const bool active = kv0 <= rw0 + 31;
        if (active) {
            const uint32_t stg = sbase + 32768 + (kt & 1) * 32768;

            // ---- S = (Qh+Ql) @ (Kh+Kl)^T, 2 m-tiles sharing K fragments ----
            float sacc[2][8][4];
            #pragma unroll
            for (int mt = 0; mt < 2; mt++)
                #pragma unroll
                for (int nt = 0; nt < 8; nt++)
                    #pragma unroll
                    for (int c = 0; c < 4; c++) sacc[mt][nt][c] = 0.0f;

            #pragma unroll
            for (int j = 0; j < 4; j++) {
                uint32_t kf[2][8][2];
                #pragma unroll
                for (int term = 0; term < 2; term++) {
                    const uint32_t kb = stg + term * 8192;
                    #pragma unroll
                    for (int np = 0; np < 4; np++) {
                        int row   = np * 16 + ((lane >> 4) << 3) + (lane & 7);
                        int chunk = j * 2 + ((lane >> 3) & 1);
                        uint32_t t4[4];
                        ldsm_x4(t4, kb + sw128((uint32_t)(row * 128 + chunk * 16)));
                        kf[term][np * 2][0]     = t4[0];
                        kf[term][np * 2][1]     = t4[1];
                        kf[term][np * 2 + 1][0] = t4[2];
                        kf[term][np * 2 + 1][1] = t4[3];
                    }
                }
                #pragma unroll
                for (int mt = 0; mt < 2; mt++) {
                    uint32_t qfh[4], qfl[4];
                    int qrow   = wid * 32 + mt * 16 + (lane & 15);
                    int qchunk = j * 2 + (lane >> 4);
                    ldsm_x4(qfh, sbase + sw128((uint32_t)(qrow * 128 + qchunk * 16)));
                    ldsm_x4(qfl, sbase + 16384 + sw128((uint32_t)(qrow * 128 + qchunk * 16)));
                    #pragma unroll
                    for (int nt = 0; nt < 8; nt++) {
                        mma_bf16(sacc[mt][nt], qfh, kf[0][nt]);
                        mma_bf16(sacc[mt][nt], qfh, kf[1][nt]);
                        mma_bf16(sacc[mt][nt], qfl, kf[0][nt]);
                    }
                }
            }

            // ---- scale + causal mask + online softmax (per m-tile) ----
            #pragma unroll
            for (int mt = 0; mt < 2; mt++) {
                const int rowg = rw0 + mt * 16 + g;
                const bool needmask = (kv0 + 63) > (rw0 + mt * 16);
                #pragma unroll
                for (int nt = 0; nt < 8; nt++) {
                    #pragma unroll
                    for (int c = 0; c < 4; c++) {
                        float s = sacc[mt][nt][c] * SCALE_L2E;
                        if (needmask) {
                            int col = kv0 + nt * 8 + t * 2 + (c & 1);
                            int row = (c < 2) ? rowg : rowg + 8;
                            if (col > row) s = -1e30f;
                        }
                        sacc[mt][nt][c] = s;
                    }
                }

                float mx0 = -1e30f, mx1 = -1e30f;
                #pragma unroll
                for (int nt = 0; nt < 8; nt++) {
                    mx0 = fmaxf(mx0, fmaxf(sacc[mt][nt][0], sacc[mt][nt][1]));
                    mx1 = fmaxf(mx1, fmaxf(sacc[mt][nt][2], sacc[mt][nt][3]));
                }
                mx0 = fmaxf(mx0, __shfl_xor_sync(0xffffffffu, mx0, 1));
                mx0 = fmaxf(mx0, __shfl_xor_sync(0xffffffffu, mx0, 2));
                mx1 = fmaxf(mx1, __shfl_xor_sync(0xffffffffu, mx1, 1));
                mx1 = fmaxf(mx1, __shfl_xor_sync(0xffffffffu, mx1, 2));
                const int i0 = mt * 2, i1 = mt * 2 + 1;
                float mnew0 = fmaxf(m[i0], mx0), mnew1 = fmaxf(m[i1], mx1);
                float a0 = exp2f(m[i0] - mnew0), a1 = exp2f(m[i1] - mnew1);
                m[i0] = mnew0; m[i1] = mnew1;

                float rs0 = 0.0f, rs1 = 0.0f;
                #pragma unroll
                for (int nt = 0; nt < 8; nt++) {
                    float p0 = exp2f(sacc[mt][nt][0] - mnew0);
                    float p1 = exp2f(sacc[mt][nt][1] - mnew0);
                    float p2 = exp2f(sacc[mt][nt][2] - mnew1);
                    float p3 = exp2f(sacc[mt][nt][3] - mnew1);
                    sacc[mt][nt][0] = p0; sacc[mt][nt][1] = p1;
                    sacc[mt][nt][2] = p2; sacc[mt][nt][3] = p3;
                    rs0 += p0 + p1; rs1 += p2 + p3;
                }
                rs0 += __shfl_xor_sync(0xffffffffu, rs0, 1);
                rs0 += __shfl_xor_sync(0xffffffffu, rs0, 2);
                rs1 += __shfl_xor_sync(0xffffffffu, rs1, 1);
                rs1 += __shfl_xor_sync(0xffffffffu, rs1, 2);
                l[i0] = l[i0] * a0 + rs0;
                l[i1] = l[i1] * a1 + rs1;
                #pragma unroll
                for (int nt = 0; nt < 8; nt++) {
                    oacc[mt][nt][0] *= a0; oacc[mt][nt][1] *= a0;
                    oacc[mt][nt][2] *= a1; oacc[mt][nt][3] *= a1;
                }
            }

            // ---- O += (Ph+Pl) @ (Vh+Vl), 2 m-tiles sharing V fragments ----
            #pragma unroll
            for (int pj = 0; pj < 4; pj++) {
                uint32_t vf[2][8][2];
                #pragma unroll
                for (int term = 0; term < 2; term++) {
                    const uint32_t vb = stg + 16384 + term * 8192;
                    #pragma unroll
                    for (int np = 0; np < 4; np++) {
                        int kvrow = pj * 16 + (lane & 15);
                        int dby   = np * 32 + ((lane >> 4) * 16);
                        uint32_t t4[4];
                        ldsm_x4_t(t4, vb + sw128((uint32_t)(kvrow * 128 + dby)));
                        vf[term][np * 2][0]     = t4[0];
                        vf[term][np * 2][1]     = t4[1];
                        vf[term][np * 2 + 1][0] = t4[2];
                        vf[term][np * 2 + 1][1] = t4[3];
                    }
                }
                #pragma unroll
                for (int mt = 0; mt < 2; mt++) {
                    const float* se = sacc[mt][2 * pj];
                    const float* so = sacc[mt][2 * pj + 1];
                    uint32_t ph[4], pl[4];
                    pack_split(se[0], se[1], ph[0], pl[0]);
                    pack_split(se[2], se[3], ph[1], pl[1]);
                    pack_split(so[0], so[1], ph[2], pl[2]);
                    pack_split(so[2], so[3], ph[3], pl[3]);
                    #pragma unroll
                    for (int nt = 0; nt < 8; nt++) {
                        mma_bf16(oacc[mt][nt], ph, vf[0][nt]);
                        mma_bf16(oacc[mt][nt], ph, vf[1][nt]);
                        mma_bf16(oacc[mt][nt], pl, vf[0][nt]);
                    }
                }
            }
        }

        __syncthreads();
        if (kt + 2 < NT) { load_kv(kt & 1, kt + 2); CP_COMMIT(); }
        else CP_COMMIT();
    }

    // ---- epilogue: normalize + split-write T ----
    #pragma unroll
    for (int mt = 0; mt < 2; mt++) {
        const int rowg = rw0 + mt * 16 + g;
        const float inv0 = 1.0f / l[mt * 2];
        const float inv1 = 1.0f / l[mt * 2 + 1];
        const size_t rb0 = (size_t)(bofs + q0 + (rowg - q0)) * DM + h * 64;
        const size_t rb1 = rb0 + (size_t)8 * DM;
        #pragma unroll
        for (int nt = 0; nt < 8; nt++) {
            int col = nt * 8 + t * 2;
            split_store_pair(oacc[mt][nt][0] * inv0, oacc[mt][nt][1] * inv0,
                             th + rb0 + col, tl + rb0 + col);
            split_store_pair(oacc[mt][nt][2] * inv1, oacc[mt][nt][3] * inv1,
                             th + rb1 + col, tl + rb1 + col);
        }
    }
}

// ---------------------------------------------------------------------------
// Launcher
// ---------------------------------------------------------------------------
extern "C" void kernel_launch(void* const* d_in, const int* in_sizes, int n_in,
                              void* d_out, int out_size)
{
    const float* x   = (const float*)d_in[0];
    const float* W_q = (const float*)d_in[1];
    const float* W_k = (const float*)d_in[2];
    const float* W_v = (const float*)d_in[3];
    const float* W_o = (const float*)d_in[4];
    float* out = (float*)d_out;

    __nv_bfloat16 *xh, *xl, *Wh, *Wl, *qkvh, *qkvl, *th, *tl;
    cudaGetSymbolAddress((void**)&xh, g_xh);
    cudaGetSymbolAddress((void**)&xl, g_xl);
    cudaGetSymbolAddress((void**)&Wh, g_Wh);
    cudaGetSymbolAddress((void**)&Wl, g_Wl);
    cudaGetSymbolAddress((void**)&qkvh, g_qkvh);
    cudaGetSymbolAddress((void**)&qkvl, g_qkvl);
    cudaGetSymbolAddress((void**)&th, g_th);
    cudaGetSymbolAddress((void**)&tl, g_tl);

    cudaFuncSetAttribute(gemm_mma_split_kernel<true>,
                         cudaFuncAttributeMaxDynamicSharedMemorySize, GEMM_SMEM);
    cudaFuncSetAttribute(gemm_mma_split_kernel<false>,
                         cudaFuncAttributeMaxDynamicSharedMemorySize, GEMM_SMEM);
    cudaFuncSetAttribute(flash_attn_mma_kernel,
                         cudaFuncAttributeMaxDynamicSharedMemorySize, ATTN_SMEM);

    const int nx4 = (int)(NX / 4), nw4 = (int)(NW / 4);
    split_bf16_kernel<<<(nx4 + 255) / 256, 256>>>(x, xh, xl, nx4);
    split_bf16_kernel<<<(nw4 + 255) / 256, 256>>>(W_q, Wh + 0 * NW, Wl + 0 * NW, nw4);
    split_bf16_kernel<<<(nw4 + 255) / 256, 256>>>(W_k, Wh + 1 * NW, Wl + 1 * NW, nw4);
    split_bf16_kernel<<<(nw4 + 255) / 256, 256>>>(W_v, Wh + 2 * NW, Wl + 2 * NW, nw4);
    split_bf16_kernel<<<(nw4 + 255) / 256, 256>>>(W_o, Wh + 3 * NW, Wl + 3 * NW, nw4);

    dim3 qkv_grid(3 * DM / 256, ROWS / 128);   // (12, 64)
    gemm_mma_split_kernel<true><<<qkv_grid, 256, GEMM_SMEM>>>(
        xh, xl, Wh, Wl, nullptr, qkvh, qkvl);

    dim3 attn_grid(SEQ / 128, BATCH * NH);     // (16, 64)
    flash_attn_mma_kernel<<<attn_grid, 128, ATTN_SMEM>>>(
        qkvh, qkvl, qkvh + NX, qkvl + NX, qkvh + 2 * NX, qkvl + 2 * NX, th, tl);

    dim3 o_grid(DM / 256, ROWS / 128);         // (4, 64)
    gemm_mma_split_kernel<false><<<o_grid, 256, GEMM_SMEM>>>(
        th, tl, Wh + 3 * NW, Wl + 3 * NW, out, nullptr, nullptr);
}

// round 10
// speedup vs baseline: 1.0245x; 1.0245x over previous
#include <cuda_runtime.h>
#include <cuda_bf16.h>
#include <cstdint>

// Problem constants
static constexpr int BATCH = 4;
static constexpr int SEQ   = 2048;
static constexpr int DM    = 1024;
static constexpr int NH    = 16;
static constexpr int DH    = 64;
static constexpr int ROWS  = BATCH * SEQ;        // 8192
static constexpr size_t NX = (size_t)ROWS * DM;  // 8388608
static constexpr size_t NW = (size_t)DM * DM;    // 1048576

// Scratch (device globals: allocation-free)
__device__ __nv_bfloat16 g_xh[NX];
__device__ __nv_bfloat16 g_xl[NX];
__device__ __nv_bfloat16 g_Wh[4 * NW];   // Wq|Wk|Wv|Wo
__device__ __nv_bfloat16 g_Wl[4 * NW];
__device__ __nv_bfloat16 g_qkvh[3 * NX]; // Q|K|V hi
__device__ __nv_bfloat16 g_qkvl[3 * NX]; // Q|K|V lo
__device__ __nv_bfloat16 g_th[NX];
__device__ __nv_bfloat16 g_tl[NX];

// ---------------------------------------------------------------------------
// Helpers
// ---------------------------------------------------------------------------
__device__ __forceinline__ uint32_t smem_u32(const void* p) {
    uint32_t a;
    asm("{ .reg .u64 t; cvta.to.shared.u64 t, %1; cvt.u32.u64 %0, t; }"
        : "=r"(a) : "l"(p));
    return a;
}
__device__ __forceinline__ uint32_t sw128(uint32_t off) {
    return off ^ ((off >> 3) & 0x70);
}
__device__ __forceinline__ void cp_async16(uint32_t saddr, const void* gaddr) {
    asm volatile("cp.async.cg.shared.global [%0], [%1], 16;"
                 :: "r"(saddr), "l"(gaddr));
}
#define CP_COMMIT() asm volatile("cp.async.commit_group;")
#define CP_WAIT(n)  asm volatile("cp.async.wait_group %0;" :: "n"(n))

__device__ __forceinline__ void ldsm_x4(uint32_t (&r)[4], uint32_t addr) {
    asm volatile("ldmatrix.sync.aligned.m8n8.x4.shared.b16 {%0,%1,%2,%3}, [%4];"
                 : "=r"(r[0]), "=r"(r[1]), "=r"(r[2]), "=r"(r[3]) : "r"(addr));
}
__device__ __forceinline__ void ldsm_x4_t(uint32_t (&r)[4], uint32_t addr) {
    asm volatile("ldmatrix.sync.aligned.m8n8.x4.trans.shared.b16 {%0,%1,%2,%3}, [%4];"
                 : "=r"(r[0]), "=r"(r[1]), "=r"(r[2]), "=r"(r[3]) : "r"(addr));
}
__device__ __forceinline__ void mma_bf16(float (&d)[4], const uint32_t (&a)[4],
                                         const uint32_t* b) {
    asm volatile(
        "mma.sync.aligned.m16n8k16.row.col.f32.bf16.bf16.f32 "
        "{%0,%1,%2,%3}, {%4,%5,%6,%7}, {%8,%9}, {%0,%1,%2,%3};"
        : "+f"(d[0]), "+f"(d[1]), "+f"(d[2]), "+f"(d[3])
        : "r"(a[0]), "r"(a[1]), "r"(a[2]), "r"(a[3]), "r"(b[0]), "r"(b[1]));
}

__device__ __forceinline__ void split_store_pair(float a, float b,
                                                 __nv_bfloat16* hp, __nv_bfloat16* lp) {
    __nv_bfloat162 h2 = __float22bfloat162_rn(make_float2(a, b));
    float2 hf = __bfloat1622float2(h2);
    __nv_bfloat162 l2 = __float22bfloat162_rn(make_float2(a - hf.x, b - hf.y));
    *reinterpret_cast<uint32_t*>(hp) = *reinterpret_cast<const uint32_t*>(&h2);
    *reinterpret_cast<uint32_t*>(lp) = *reinterpret_cast<const uint32_t*>(&l2);
}
__device__ __forceinline__ void pack_split(float a, float b, uint32_t& ph, uint32_t& pl) {
    __nv_bfloat162 h2 = __float22bfloat162_rn(make_float2(a, b));
    float2 hf = __bfloat1622float2(h2);
    __nv_bfloat162 l2 = __float22bfloat162_rn(make_float2(a - hf.x, b - hf.y));
    ph = *reinterpret_cast<const uint32_t*>(&h2);
    pl = *reinterpret_cast<const uint32_t*>(&l2);
}

// ---------------------------------------------------------------------------
// fp32 -> (hi, lo) bf16 split (single source)
// ---------------------------------------------------------------------------
__global__ __launch_bounds__(256) void split_bf16_kernel(
    const float* __restrict__ src, __nv_bfloat16* __restrict__ hi,
    __nv_bfloat16* __restrict__ lo, int n4)
{
    int i = blockIdx.x * blockDim.x + threadIdx.x;
    if (i >= n4) return;
    float4 v = reinterpret_cast<const float4*>(src)[i];
    __nv_bfloat162 h0 = __float22bfloat162_rn(make_float2(v.x, v.y));
    __nv_bfloat162 h1 = __float22bfloat162_rn(make_float2(v.z, v.w));
    float2 f0 = __bfloat1622float2(h0), f1 = __bfloat1622float2(h1);
    __nv_bfloat162 l0 = __float22bfloat162_rn(make_float2(v.x - f0.x, v.y - f0.y));
    __nv_bfloat162 l1 = __float22bfloat162_rn(make_float2(v.z - f1.x, v.w - f1.y));
    uint2 hv, lv;
    hv.x = *reinterpret_cast<uint32_t*>(&h0); hv.y = *reinterpret_cast<uint32_t*>(&h1);
    lv.x = *reinterpret_cast<uint32_t*>(&l0); lv.y = *reinterpret_cast<uint32_t*>(&l1);
    reinterpret_cast<uint2*>(hi)[i] = hv;
    reinterpret_cast<uint2*>(lo)[i] = lv;
}

// fp32 -> (hi,lo) for the 4 weight matrices in ONE launch
__global__ __launch_bounds__(256) void split_w4_kernel(
    const float* __restrict__ w0, const float* __restrict__ w1,
    const float* __restrict__ w2, const float* __restrict__ w3,
    __nv_bfloat16* __restrict__ hi, __nv_bfloat16* __restrict__ lo)
{
    const int nw4 = (int)(NW / 4);
    int i = blockIdx.x * blockDim.x + threadIdx.x;
    if (i >= 4 * nw4) return;
    const int mat = i / nw4;
    const int j   = i - mat * nw4;
    const float* src = (mat == 0) ? w0 : (mat == 1) ? w1 : (mat == 2) ? w2 : w3;
    float4 v = reinterpret_cast<const float4*>(src)[j];
    __nv_bfloat162 h0 = __float22bfloat162_rn(make_float2(v.x, v.y));
    __nv_bfloat162 h1 = __float22bfloat162_rn(make_float2(v.z, v.w));
    float2 f0 = __bfloat1622float2(h0), f1 = __bfloat1622float2(h1);
    __nv_bfloat162 l0 = __float22bfloat162_rn(make_float2(v.x - f0.x, v.y - f0.y));
    __nv_bfloat162 l1 = __float22bfloat162_rn(make_float2(v.z - f1.x, v.w - f1.y));
    uint2 hv, lv;
    hv.x = *reinterpret_cast<uint32_t*>(&h0); hv.y = *reinterpret_cast<uint32_t*>(&h1);
    lv.x = *reinterpret_cast<uint32_t*>(&l0); lv.y = *reinterpret_cast<uint32_t*>(&l1);
    reinterpret_cast<uint2*>(hi)[i] = hv;
    reinterpret_cast<uint2*>(lo)[i] = lv;
}

// ---------------------------------------------------------------------------
// bf16-split GEMM (NT), K = 1024 fixed — R7-proven version (128x128, 4 stages)
// ---------------------------------------------------------------------------
static constexpr int TILE_B    = 128 * 128;
static constexpr int STAGE_B   = 2 * TILE_B;
static constexpr int GSTAGES   = 4;
static constexpr int GEMM_SMEM = GSTAGES * STAGE_B;   // 131072

template <bool SPLIT_OUT>
__global__ __launch_bounds__(256, 1) void gemm_mma_split_kernel(
    const __nv_bfloat16* __restrict__ Ah, const __nv_bfloat16* __restrict__ Al,
    const __nv_bfloat16* __restrict__ Bh, const __nv_bfloat16* __restrict__ Bl,
    float* __restrict__ C, __nv_bfloat16* __restrict__ Ch,
    __nv_bfloat16* __restrict__ Cl)
{
    extern __shared__ char smem[];
    const uint32_t sbase = smem_u32(smem);
    constexpr int K   = DM;
    constexpr int NKT = K / 32;

    const int tid   = threadIdx.x;
    const int wid   = tid >> 5;
    const int lane  = tid & 31;
    const int warpm = wid >> 2;
    const int warpn = wid & 3;
    const int row0  = blockIdx.y * 128;
    const int col0  = blockIdx.x * 128;

    auto load_stage = [&](int s, int kt) {
        const uint32_t As = sbase + s * STAGE_B;
        const uint32_t Bs = As + TILE_B;
        const size_t kofs = (size_t)kt * 32;
        const __nv_bfloat16* Ah0 = Ah + (size_t)row0 * K + kofs;
        const __nv_bfloat16* Al0 = Al + (size_t)row0 * K + kofs;
        const __nv_bfloat16* Bh0 = Bh + (size_t)col0 * K + kofs;
        const __nv_bfloat16* Bl0 = Bl + (size_t)col0 * K + kofs;
        #pragma unroll
        for (int t = 0; t < 4; t++) {
            int v = t * 256 + tid;
            int r = v >> 3;
            int c = v & 7;
            uint32_t soff = sw128((uint32_t)(r * 128 + c * 16));
            cp_async16(As + soff, (c < 4 ? Ah0 : Al0) + (size_t)r * K + (c & 3) * 8);
            cp_async16(Bs + soff, (c < 4 ? Bh0 : Bl0) + (size_t)r * K + (c & 3) * 8);
        }
    };

    float acc[4][4][4];
    #pragma unroll
    for (int i = 0; i < 4; i++)
        #pragma unroll
        for (int j = 0; j < 4; j++)
            #pragma unroll
            for (int k = 0; k < 4; k++) acc[i][j][k] = 0.0f;

    load_stage(0, 0); CP_COMMIT();
    load_stage(1, 1); CP_COMMIT();
    load_stage(2, 2); CP_COMMIT();

    for (int kt = 0; kt < NKT; kt++) {
        CP_WAIT(2);
        __syncthreads();

        const uint32_t As = sbase + (kt & 3) * STAGE_B;
        const uint32_t Bs = As + TILE_B;

        #pragma unroll
        for (int kc = 0; kc < 2; kc++) {
            const int jh = kc * 2;
            const int jl = 4 + kc * 2;

            uint32_t Ahf[4][4], Bhf[4][2];
            #pragma unroll
            for (int mt = 0; mt < 4; mt++) {
                int row = warpm * 64 + mt * 16 + (lane & 15);
                ldsm_x4(Ahf[mt], As + sw128((uint32_t)(row * 128 + (jh + (lane >> 4)) * 16)));
            }
            #pragma unroll
            for (int p = 0; p < 2; p++) {
                int row = warpn * 32 + p * 16 + ((lane >> 4) << 3) + (lane & 7);
                uint32_t t4[4];
                ldsm_x4(t4, Bs + sw128((uint32_t)(row * 128 + (jh + ((lane >> 3) & 1)) * 16)));
                Bhf[p * 2][0]     = t4[0]; Bhf[p * 2][1]     = t4[1];
                Bhf[p * 2 + 1][0] = t4[2]; Bhf[p * 2 + 1][1] = t4[3];
            }
            #pragma unroll
            for (int mt = 0; mt < 4; mt++)
                #pragma unroll
                for (int nt = 0; nt < 4; nt++)
                    mma_bf16(acc[mt][nt], Ahf[mt], Bhf[nt]);

            uint32_t Blf[4][2];
            #pragma unroll
            for (int p = 0; p < 2; p++) {
                int row = warpn * 32 + p * 16 + ((lane >> 4) << 3) + (lane & 7);
                uint32_t t4[4];
                ldsm_x4(t4, Bs + sw128((uint32_t)(row * 128 + (jl + ((lane >> 3) & 1)) * 16)));
                Blf[p * 2][0]     = t4[0]; Blf[p * 2][1]     = t4[1];
                Blf[p * 2 + 1][0] = t4[2]; Blf[p * 2 + 1][1] = t4[3];
            }
            #pragma unroll
            for (int mt = 0; mt < 4; mt++)
                #pragma unroll
                for (int nt = 0; nt < 4; nt++)
                    mma_bf16(acc[mt][nt], Ahf[mt], Blf[nt]);

            uint32_t Alf[4][4];
            #pragma unroll
            for (int mt = 0; mt < 4; mt++) {
                int row = warpm * 64 + mt * 16 + (lane & 15);
                ldsm_x4(Alf[mt], As + sw128((uint32_t)(row * 128 + (jl + (lane >> 4)) * 16)));
            }
            #pragma unroll
            for (int mt = 0; mt < 4; mt++)
                #pragma unroll
                for (int nt = 0; nt < 4; nt++)
                    mma_bf16(acc[mt][nt], Alf[mt], Bhf[nt]);
        }

        if (kt + 3 < NKT) load_stage((kt + 3) & 3, kt + 3);
        CP_COMMIT();
    }

    const int g = lane >> 2;
    const int t = lane & 3;
    if (SPLIT_OUT) {
        const int mat  = col0 >> 10;
        const int colb = col0 & 1023;
        __nv_bfloat16* ch = Ch + (size_t)mat * NX;
        __nv_bfloat16* cl = Cl + (size_t)mat * NX;
        #pragma unroll
        for (int mt = 0; mt < 4; mt++)
            #pragma unroll
            for (int nt = 0; nt < 4; nt++) {
                int row = row0 + warpm * 64 + mt * 16 + g;
                int col = colb + warpn * 32 + nt * 8 + t * 2;
                split_store_pair(acc[mt][nt][0], acc[mt][nt][1],
                                 ch + (size_t)row * DM + col, cl + (size_t)row * DM + col);
                split_store_pair(acc[mt][nt][2], acc[mt][nt][3],
                                 ch + (size_t)(row + 8) * DM + col,
                                 cl + (size_t)(row + 8) * DM + col);
            }
    } else {
        #pragma unroll
        for (int mt = 0; mt < 4; mt++)
            #pragma unroll
            for (int nt = 0; nt < 4; nt++) {
                int row = row0 + warpm * 64 + mt * 16 + g;
                int col = col0 + warpn * 32 + nt * 8 + t * 2;
                float2 v0 = make_float2(acc[mt][nt][0], acc[mt][nt][1]);
                float2 v1 = make_float2(acc[mt][nt][2], acc[mt][nt][3]);
                *reinterpret_cast<float2*>(&C[(size_t)row * DM + col])       = v0;
                *reinterpret_cast<float2*>(&C[(size_t)(row + 8) * DM + col]) = v1;
            }
    }
}

// ---------------------------------------------------------------------------
// Tensor-core flash attention (split-bf16, causal), BM=64, BN=64.
// R7-proven structure (4 warps x 16 rows, 128 thr, 2 CTAs/SM), full 3-term P@V.
// ---------------------------------------------------------------------------
static constexpr int ATTN_SMEM = 16384 + 2 * 32768;   // 81920
static constexpr float SCALE_L2E = 0.125f * 1.4426950408889634f;

__global__ __launch_bounds__(128) void flash_attn_mma_kernel(
    const __nv_bfloat16* __restrict__ qh, const __nv_bfloat16* __restrict__ ql,
    const __nv_bfloat16* __restrict__ kh, const __nv_bfloat16* __restrict__ kl,
    const __nv_bfloat16* __restrict__ vh, const __nv_bfloat16* __restrict__ vl,
    __nv_bfloat16* __restrict__ th, __nv_bfloat16* __restrict__ tl)
{
    extern __shared__ char smem[];
    const uint32_t sbase = smem_u32(smem);

    const int tid  = threadIdx.x;
    const int wid  = tid >> 5;        // 0..3
    const int lane = tid & 31;
    const int g    = lane >> 2;
    const int t    = lane & 3;

    const int qb = (SEQ / 64 - 1) - blockIdx.x;    // heavy blocks first
    const int bh = blockIdx.y;
    const int b  = bh >> 4;
    const int h  = bh & 15;
    const int q0 = qb * 64;
    const int bofs = b * SEQ;
    const int NT = qb + 1;                          // kv tiles of 64
    const int rowg = q0 + wid * 16 + g;

    auto load_q = [&]() {
        #pragma unroll
        for (int term = 0; term < 2; term++) {
            const __nv_bfloat16* src = term ? ql : qh;
            #pragma unroll
            for (int tt = 0; tt < 4; tt++) {
                int v = tt * 128 + tid;
                int r = v >> 3;
                int c = v & 7;
                cp_async16(sbase + term * 8192 + sw128((uint32_t)(r * 128 + c * 16)),
                           src + (size_t)(bofs + q0 + r) * DM + h * 64 + c * 8);
            }
        }
    };
    auto load_kv = [&](int stage, int kt2) {
        const int kv = kt2 * 64;
        const uint32_t base = sbase + 16384 + stage * 32768;
        const __nv_bfloat16* bufs[4] = {kh, kl, vh, vl};
        #pragma unroll
        for (int buf = 0; buf < 4; buf++) {
            #pragma unroll
            for (int tt = 0; tt < 4; tt++) {
                int v = tt * 128 + tid;
                int r = v >> 3;
                int c = v & 7;
                cp_async16(base + buf * 8192 + sw128((uint32_t)(r * 128 + c * 16)),
                           bufs[buf] + (size_t)(bofs + kv + r) * DM + h * 64 + c * 8);
            }
        }
    };

    load_q();
    load_kv(0, 0); CP_COMMIT();
    load_kv(1, NT > 1 ? 1 : 0); CP_COMMIT();
    CP_WAIT(1);
    __syncthreads();

    uint32_t qf[2][4][4];
    #pragma unroll
    for (int term = 0; term < 2; term++) {
        const uint32_t qbse = sbase + term * 8192;
        #pragma unroll
        for (int j = 0; j < 4; j++) {
            int row   = wid * 16 + (lane & 15);
            int chunk = j * 2 + (lane >> 4);
            ldsm_x4(qf[term][j], qbse + sw128((uint32_t)(row * 128 + chunk * 16)));
        }
    }

    float m0 = -1e30f, m1 = -1e30f, l0 = 0.0f, l1 = 0.0f;
    float oacc[8][4];
    #pragma unroll
    for (int nt = 0; nt < 8; nt++)
        #pragma unroll
        for (int c = 0; c < 4; c++) oacc[nt][c] = 0.0f;

    for (int kt = 0; kt < NT; kt++) {
        if (kt + 1 < NT) { CP_WAIT(1); } else { CP_WAIT(0); }
        __syncthreads();

        const int kv0 = kt * 64;
        const uint32_t stg = sbase + 16384 + (kt & 1) * 32768;

        // ---- S = (Qh+Ql) @ (Kh+Kl)^T ----
        float sacc[8][4];
        #pragma unroll
        for (int nt = 0; nt < 8; nt++)
            #pragma unroll
            for (int c = 0; c < 4; c++) sacc[nt][c] = 0.0f;

        #pragma unroll
        for (int j = 0; j < 4; j++) {
            uint32_t kf[2][8][2];
            #pragma unroll
            for (int term = 0; term < 2; term++) {
                const uint32_t kb = stg + term * 8192;
                #pragma unroll
                for (int np = 0; np < 4; np++) {
                    int row   = np * 16 + ((lane >> 4) << 3) + (lane & 7);
                    int chunk = j * 2 + ((lane >> 3) & 1);
                    uint32_t t4[4];
                    ldsm_x4(t4, kb + sw128((uint32_t)(row * 128 + chunk * 16)));
                    kf[term][np * 2][0]     = t4[0];
                    kf[term][np * 2][1]     = t4[1];
                    kf[term][np * 2 + 1][0] = t4[2];
                    kf[term][np * 2 + 1][1] = t4[3];
                }
            }
            #pragma unroll
            for (int nt = 0; nt < 8; nt++) {
                mma_bf16(sacc[nt], qf[0][j], kf[0][nt]);
                mma_bf16(sacc[nt], qf[0][j], kf[1][nt]);
                mma_bf16(sacc[nt], qf[1][j], kf[0][nt]);
            }
        }

        // ---- scale to log2 domain + causal mask (diagonal tile only) ----
        const bool lastt = (kt == NT - 1);
        #pragma unroll
        for (int nt = 0; nt < 8; nt++) {
            #pragma unroll
            for (int c = 0; c < 4; c++) {
                float s = sacc[nt][c] * SCALE_L2E;
                if (lastt) {
                    int col = kv0 + nt * 8 + t * 2 + (c & 1);
                    int row = (c < 2) ? rowg : rowg + 8;
                    if (col > row) s = -1e30f;
                }
                sacc[nt][c] = s;
            }
        }

        // ---- online softmax (base-2) ----
        float mx0 = -1e30f, mx1 = -1e30f;
        #pragma unroll
        for (int nt = 0; nt < 8; nt++) {
            mx0 = fmaxf(mx0, fmaxf(sacc[nt][0], sacc[nt][1]));
            mx1 = fmaxf(mx1, fmaxf(sacc[nt][2], sacc[nt][3]));
        }
        mx0 = fmaxf(mx0, __shfl_xor_sync(0xffffffffu, mx0, 1));
        mx0 = fmaxf(mx0, __shfl_xor_sync(0xffffffffu, mx0, 2));
        mx1 = fmaxf(mx1, __shfl_xor_sync(0xffffffffu, mx1, 1));
        mx1 = fmaxf(mx1, __shfl_xor_sync(0xffffffffu, mx1, 2));
        float mnew0 = fmaxf(m0, mx0), mnew1 = fmaxf(m1, mx1);
        float a0 = exp2f(m0 - mnew0), a1 = exp2f(m1 - mnew1);
        m0 = mnew0; m1 = mnew1;

        float rs0 = 0.0f, rs1 = 0.0f;
        #pragma unroll
        for (int nt = 0; nt < 8; nt++) {
            float p0 = exp2f(sacc[nt][0] - mnew0);
            float p1 = exp2f(sacc[nt][1] - mnew0);
            float p2 = exp2f(sacc[nt][2] - mnew1);
            float p3 = exp2f(sacc[nt][3] - mnew1);
            sacc[nt][0] = p0; sacc[nt][1] = p1;
            sacc[nt][2] = p2; sacc[nt][3] = p3;
            rs0 += p0 + p1; rs1 += p2 + p3;
        }
        rs0 += __shfl_xor_sync(0xffffffffu, rs0, 1);
        rs0 += __shfl_xor_sync(0xffffffffu, rs0, 2);
        rs1 += __shfl_xor_sync(0xffffffffu, rs1, 1);
        rs1 += __shfl_xor_sync(0xffffffffu, rs1, 2);
        l0 = l0 * a0 + rs0;
        l1 = l1 * a1 + rs1;
        #pragma unroll
        for (int nt = 0; nt < 8; nt++) {
            oacc[nt][0] *= a0; oacc[nt][1] *= a0;
            oacc[nt][2] *= a1; oacc[nt][3] *= a1;
        }

        // ---- O += (Ph+Pl) @ (Vh+Vl)  (full 3 terms — precision-required) ----
        #pragma unroll
        for (int pj = 0; pj < 4; pj++) {
            const float* se = sacc[2 * pj];
            const float* so = sacc[2 * pj + 1];
            uint32_t ph[4], pl[4];
            pack_split(se[0], se[1], ph[0], pl[0]);
            pack_split(se[2], se[3], ph[1], pl[1]);
            pack_split(so[0], so[1], ph[2], pl[2]);
            pack_split(so[2], so[3], ph[3], pl[3]);

            uint32_t vf[2][8][2];
            #pragma unroll
            for (int term = 0; term < 2; term++) {
                const uint32_t vb = stg + 16384 + term * 8192;
                #pragma unroll
                for (int np = 0; np < 4; np++) {
                    int kvrow = pj * 16 + (lane & 15);
                    int dby   = np * 32 + ((lane >> 4) * 16);
                    uint32_t t4[4];
                    ldsm_x4_t(t4, vb + sw128((uint32_t)(kvrow * 128 + dby)));
                    vf[term][np * 2][0]     = t4[0];
                    vf[term][np * 2][1]     = t4[1];
                    vf[term][np * 2 + 1][0] = t4[2];
                    vf[term][np * 2 + 1][1] = t4[3];
                }
            }
            #pragma unroll
            for (int nt = 0; nt < 8; nt++) {
                mma_bf16(oacc[nt], ph, vf[0][nt]);
                mma_bf16(oacc[nt], ph, vf[1][nt]);
                mma_bf16(oacc[nt], pl, vf[0][nt]);
            }
        }

        __syncthreads();
        if (kt + 2 < NT) { load_kv(kt & 1, kt + 2); CP_COMMIT(); }
        else CP_COMMIT();
    }

    // ---- epilogue: normalize + split-write T ----
    const float inv0 = 1.0f / l0, inv1 = 1.0f / l1;
    const size_t rb0 = (size_t)(bofs + rowg) * DM + h * 64;
    const size_t rb1 = rb0 + (size_t)8 * DM;
    #pragma unroll
    for (int nt = 0; nt < 8; nt++) {
        int col = nt * 8 + t * 2;
        split_store_pair(oacc[nt][0] * inv0, oacc[nt][1] * inv0,
                         th + rb0 + col, tl + rb0 + col);
        split_store_pair(oacc[nt][2] * inv1, oacc[nt][3] * inv1,
                         th + rb1 + col, tl + rb1 + col);
    }
}

// ---------------------------------------------------------------------------
// Launcher — attention at launch index 3 (the one ncu captures)
// ---------------------------------------------------------------------------
extern "C" void kernel_launch(void* const* d_in, const int* in_sizes, int n_in,
                              void* d_out, int out_size)
{
    const float* x   = (const float*)d_in[0];
    const float* W_q = (const float*)d_in[1];
    const float* W_k = (const float*)d_in[2];
    const float* W_v = (const float*)d_in[3];
    const float* W_o = (const float*)d_in[4];
    float* out = (float*)d_out;

    __nv_bfloat16 *xh, *xl, *Wh, *Wl, *qkvh, *qkvl, *th, *tl;
    cudaGetSymbolAddress((void**)&xh, g_xh);
    cudaGetSymbolAddress((void**)&xl, g_xl);
    cudaGetSymbolAddress((void**)&Wh, g_Wh);
    cudaGetSymbolAddress((void**)&Wl, g_Wl);
    cudaGetSymbolAddress((void**)&qkvh, g_qkvh);
    cudaGetSymbolAddress((void**)&qkvl, g_qkvl);
    cudaGetSymbolAddress((void**)&th, g_th);
    cudaGetSymbolAddress((void**)&tl, g_tl);

    cudaFuncSetAttribute(gemm_mma_split_kernel<true>,
                         cudaFuncAttributeMaxDynamicSharedMemorySize, GEMM_SMEM);
    cudaFuncSetAttribute(gemm_mma_split_kernel<false>,
                         cudaFuncAttributeMaxDynamicSharedMemorySize, GEMM_SMEM);
    cudaFuncSetAttribute(flash_attn_mma_kernel,
                         cudaFuncAttributeMaxDynamicSharedMemorySize, ATTN_SMEM);

    const int nx4 = (int)(NX / 4);
    const int nw4all = (int)(NW);          // 4 * (NW/4)

    // launch 0: x split
    split_bf16_kernel<<<(nx4 + 255) / 256, 256>>>(x, xh, xl, nx4);
    // launch 1: all 4 weight splits fused
    split_w4_kernel<<<(nw4all + 255) / 256, 256>>>(W_q, W_k, W_v, W_o, Wh, Wl);

    // launch 2: fused QKV GEMM
    dim3 qkv_grid(3 * DM / 128, ROWS / 128);   // (24, 64)
    gemm_mma_split_kernel<true><<<qkv_grid, 256, GEMM_SMEM>>>(
        xh, xl, Wh, Wl, nullptr, qkvh, qkvl);

    // launch 3: attention  (<-- profiled launch)
    dim3 attn_grid(SEQ / 64, BATCH * NH);      // (32, 64)
    flash_attn_mma_kernel<<<attn_grid, 128, ATTN_SMEM>>>(
        qkvh, qkvl, qkvh + NX, qkvl + NX, qkvh + 2 * NX, qkvl + 2 * NX, th, tl);

    // launch 4: output projection
    dim3 o_grid(DM / 128, ROWS / 128);         // (8, 64)
    gemm_mma_split_kernel<false><<<o_grid, 256, GEMM_SMEM>>>(
        th, tl, Wh + 3 * NW, Wl + 3 * NW, out, nullptr, nullptr);
}

// round 11
// speedup vs baseline: 1.0635x; 1.0380x over previous
#include <cuda_runtime.h>
#include <cuda_bf16.h>
#include <cstdint>

// Problem constants
static constexpr int BATCH = 4;
static constexpr int SEQ   = 2048;
static constexpr int DM    = 1024;
static constexpr int NH    = 16;
static constexpr int DH    = 64;
static constexpr int ROWS  = BATCH * SEQ;        // 8192
static constexpr size_t NX = (size_t)ROWS * DM;  // 8388608
static constexpr size_t NW = (size_t)DM * DM;    // 1048576

// Scratch (device globals: allocation-free)
__device__ __nv_bfloat16 g_xh[NX];
__device__ __nv_bfloat16 g_xl[NX];
__device__ __nv_bfloat16 g_Wh[4 * NW];   // Wq|Wk|Wv|Wo
__device__ __nv_bfloat16 g_Wl[4 * NW];
__device__ __nv_bfloat16 g_qkvh[3 * NX]; // Q|K|V hi
__device__ __nv_bfloat16 g_qkvl[3 * NX]; // Q|K|V lo
__device__ __nv_bfloat16 g_th[NX];
__device__ __nv_bfloat16 g_tl[NX];

// ---------------------------------------------------------------------------
// Helpers
// ---------------------------------------------------------------------------
__device__ __forceinline__ uint32_t smem_u32(const void* p) {
    uint32_t a;
    asm("{ .reg .u64 t; cvta.to.shared.u64 t, %1; cvt.u32.u64 %0, t; }"
        : "=r"(a) : "l"(p));
    return a;
}
__device__ __forceinline__ uint32_t sw128(uint32_t off) {
    return off ^ ((off >> 3) & 0x70);
}
__device__ __forceinline__ void cp_async16(uint32_t saddr, const void* gaddr) {
    asm volatile("cp.async.cg.shared.global [%0], [%1], 16;"
                 :: "r"(saddr), "l"(gaddr));
}
#define CP_COMMIT() asm volatile("cp.async.commit_group;")
#define CP_WAIT(n)  asm volatile("cp.async.wait_group %0;" :: "n"(n))

__device__ __forceinline__ void ldsm_x4(uint32_t (&r)[4], uint32_t addr) {
    asm volatile("ldmatrix.sync.aligned.m8n8.x4.shared.b16 {%0,%1,%2,%3}, [%4];"
                 : "=r"(r[0]), "=r"(r[1]), "=r"(r[2]), "=r"(r[3]) : "r"(addr));
}
__device__ __forceinline__ void ldsm_x4_t(uint32_t (&r)[4], uint32_t addr) {
    asm volatile("ldmatrix.sync.aligned.m8n8.x4.trans.shared.b16 {%0,%1,%2,%3}, [%4];"
                 : "=r"(r[0]), "=r"(r[1]), "=r"(r[2]), "=r"(r[3]) : "r"(addr));
}
__device__ __forceinline__ void mma_bf16(float (&d)[4], const uint32_t (&a)[4],
                                         const uint32_t* b) {
    asm volatile(
        "mma.sync.aligned.m16n8k16.row.col.f32.bf16.bf16.f32 "
        "{%0,%1,%2,%3}, {%4,%5,%6,%7}, {%8,%9}, {%0,%1,%2,%3};"
        : "+f"(d[0]), "+f"(d[1]), "+f"(d[2]), "+f"(d[3])
        : "r"(a[0]), "r"(a[1]), "r"(a[2]), "r"(a[3]), "r"(b[0]), "r"(b[1]));
}

__device__ __forceinline__ void split_store_pair(float a, float b,
                                                 __nv_bfloat16* hp, __nv_bfloat16* lp) {
    __nv_bfloat162 h2 = __float22bfloat162_rn(make_float2(a, b));
    float2 hf = __bfloat1622float2(h2);
    __nv_bfloat162 l2 = __float22bfloat162_rn(make_float2(a - hf.x, b - hf.y));
    *reinterpret_cast<uint32_t*>(hp) = *reinterpret_cast<const uint32_t*>(&h2);
    *reinterpret_cast<uint32_t*>(lp) = *reinterpret_cast<const uint32_t*>(&l2);
}
__device__ __forceinline__ void pack_split(float a, float b, uint32_t& ph, uint32_t& pl) {
    __nv_bfloat162 h2 = __float22bfloat162_rn(make_float2(a, b));
    float2 hf = __bfloat1622float2(h2);
    __nv_bfloat162 l2 = __float22bfloat162_rn(make_float2(a - hf.x, b - hf.y));
    ph = *reinterpret_cast<const uint32_t*>(&h2);
    pl = *reinterpret_cast<const uint32_t*>(&l2);
}

// ---------------------------------------------------------------------------
// fp32 -> (hi, lo) bf16 split (single source)
// ---------------------------------------------------------------------------
__global__ __launch_bounds__(256) void split_bf16_kernel(
    const float* __restrict__ src, __nv_bfloat16* __restrict__ hi,
    __nv_bfloat16* __restrict__ lo, int n4)
{
    int i = blockIdx.x * blockDim.x + threadIdx.x;
    if (i >= n4) return;
    float4 v = reinterpret_cast<const float4*>(src)[i];
    __nv_bfloat162 h0 = __float22bfloat162_rn(make_float2(v.x, v.y));
    __nv_bfloat162 h1 = __float22bfloat162_rn(make_float2(v.z, v.w));
    float2 f0 = __bfloat1622float2(h0), f1 = __bfloat1622float2(h1);
    __nv_bfloat162 l0 = __float22bfloat162_rn(make_float2(v.x - f0.x, v.y - f0.y));
    __nv_bfloat162 l1 = __float22bfloat162_rn(make_float2(v.z - f1.x, v.w - f1.y));
    uint2 hv, lv;
    hv.x = *reinterpret_cast<uint32_t*>(&h0); hv.y = *reinterpret_cast<uint32_t*>(&h1);
    lv.x = *reinterpret_cast<uint32_t*>(&l0); lv.y = *reinterpret_cast<uint32_t*>(&l1);
    reinterpret_cast<uint2*>(hi)[i] = hv;
    reinterpret_cast<uint2*>(lo)[i] = lv;
}

// fp32 -> (hi,lo) for the 4 weight matrices in ONE launch
__global__ __launch_bounds__(256) void split_w4_kernel(
    const float* __restrict__ w0, const float* __restrict__ w1,
    const float* __restrict__ w2, const float* __restrict__ w3,
    __nv_bfloat16* __restrict__ hi, __nv_bfloat16* __restrict__ lo)
{
    const int nw4 = (int)(NW / 4);
    int i = blockIdx.x * blockDim.x + threadIdx.x;
    if (i >= 4 * nw4) return;
    const int mat = i / nw4;
    const int j   = i - mat * nw4;
    const float* src = (mat == 0) ? w0 : (mat == 1) ? w1 : (mat == 2) ? w2 : w3;
    float4 v = reinterpret_cast<const float4*>(src)[j];
    __nv_bfloat162 h0 = __float22bfloat162_rn(make_float2(v.x, v.y));
    __nv_bfloat162 h1 = __float22bfloat162_rn(make_float2(v.z, v.w));
    float2 f0 = __bfloat1622float2(h0), f1 = __bfloat1622float2(h1);
    __nv_bfloat162 l0 = __float22bfloat162_rn(make_float2(v.x - f0.x, v.y - f0.y));
    __nv_bfloat162 l1 = __float22bfloat162_rn(make_float2(v.z - f1.x, v.w - f1.y));
    uint2 hv, lv;
    hv.x = *reinterpret_cast<uint32_t*>(&h0); hv.y = *reinterpret_cast<uint32_t*>(&h1);
    lv.x = *reinterpret_cast<uint32_t*>(&l0); lv.y = *reinterpret_cast<uint32_t*>(&l1);
    reinterpret_cast<uint2*>(hi)[i] = hv;
    reinterpret_cast<uint2*>(lo)[i] = lv;
}

// ---------------------------------------------------------------------------
// bf16-split GEMM (NT), K = 1024. 128x128 CTA tile, BK=32, 3-stage ring,
// single barrier per k-step, 2 CTAs/SM (96KB smem, 128-reg cap).
// ---------------------------------------------------------------------------
static constexpr int TILE_B    = 128 * 128;
static constexpr int STAGE_B   = 2 * TILE_B;          // 32 KB
static constexpr int GSTAGES   = 3;
static constexpr int GEMM_SMEM = GSTAGES * STAGE_B;   // 98304

template <bool SPLIT_OUT>
__global__ __launch_bounds__(256, 2) void gemm_mma_split_kernel(
    const __nv_bfloat16* __restrict__ Ah, const __nv_bfloat16* __restrict__ Al,
    const __nv_bfloat16* __restrict__ Bh, const __nv_bfloat16* __restrict__ Bl,
    float* __restrict__ C, __nv_bfloat16* __restrict__ Ch,
    __nv_bfloat16* __restrict__ Cl)
{
    extern __shared__ char smem[];
    const uint32_t sbase = smem_u32(smem);
    constexpr int K   = DM;
    constexpr int NKT = K / 32;

    const int tid   = threadIdx.x;
    const int wid   = tid >> 5;
    const int lane  = tid & 31;
    const int warpm = wid >> 2;
    const int warpn = wid & 3;
    const int row0  = blockIdx.y * 128;
    const int col0  = blockIdx.x * 128;

    auto load_stage = [&](int s, int kt) {
        const uint32_t As = sbase + s * STAGE_B;
        const uint32_t Bs = As + TILE_B;
        const size_t kofs = (size_t)kt * 32;
        const __nv_bfloat16* Ah0 = Ah + (size_t)row0 * K + kofs;
        const __nv_bfloat16* Al0 = Al + (size_t)row0 * K + kofs;
        const __nv_bfloat16* Bh0 = Bh + (size_t)col0 * K + kofs;
        const __nv_bfloat16* Bl0 = Bl + (size_t)col0 * K + kofs;
        #pragma unroll
        for (int t = 0; t < 4; t++) {
            int v = t * 256 + tid;
            int r = v >> 3;
            int c = v & 7;
            uint32_t soff = sw128((uint32_t)(r * 128 + c * 16));
            cp_async16(As + soff, (c < 4 ? Ah0 : Al0) + (size_t)r * K + (c & 3) * 8);
            cp_async16(Bs + soff, (c < 4 ? Bh0 : Bl0) + (size_t)r * K + (c & 3) * 8);
        }
    };

    float acc[4][4][4];
    #pragma unroll
    for (int i = 0; i < 4; i++)
        #pragma unroll
        for (int j = 0; j < 4; j++)
            #pragma unroll
            for (int k = 0; k < 4; k++) acc[i][j][k] = 0.0f;

    load_stage(0, 0); CP_COMMIT();
    load_stage(1, 1); CP_COMMIT();

    for (int kt = 0; kt < NKT; kt++) {
        CP_WAIT(1);
        __syncthreads();                  // single barrier per k-step

        const uint32_t As = sbase + (kt % 3) * STAGE_B;
        const uint32_t Bs = As + TILE_B;

        #pragma unroll
        for (int kc = 0; kc < 2; kc++) {
            const int jh = kc * 2;
            const int jl = 4 + kc * 2;

            uint32_t Ahf[4][4], Bhf[4][2];
            #pragma unroll
            for (int mt = 0; mt < 4; mt++) {
                int row = warpm * 64 + mt * 16 + (lane & 15);
                ldsm_x4(Ahf[mt], As + sw128((uint32_t)(row * 128 + (jh + (lane >> 4)) * 16)));
            }
            #pragma unroll
            for (int p = 0; p < 2; p++) {
                int row = warpn * 32 + p * 16 + ((lane >> 4) << 3) + (lane & 7);
                uint32_t t4[4];
                ldsm_x4(t4, Bs + sw128((uint32_t)(row * 128 + (jh + ((lane >> 3) & 1)) * 16)));
                Bhf[p * 2][0]     = t4[0]; Bhf[p * 2][1]     = t4[1];
                Bhf[p * 2 + 1][0] = t4[2]; Bhf[p * 2 + 1][1] = t4[3];
            }
            #pragma unroll
            for (int mt = 0; mt < 4; mt++)
                #pragma unroll
                for (int nt = 0; nt < 4; nt++)
                    mma_bf16(acc[mt][nt], Ahf[mt], Bhf[nt]);

            uint32_t Blf[4][2];
            #pragma unroll
            for (int p = 0; p < 2; p++) {
                int row = warpn * 32 + p * 16 + ((lane >> 4) << 3) + (lane & 7);
                uint32_t t4[4];
                ldsm_x4(t4, Bs + sw128((uint32_t)(row * 128 + (jl + ((lane >> 3) & 1)) * 16)));
                Blf[p * 2][0]     = t4[0]; Blf[p * 2][1]     = t4[1];
                Blf[p * 2 + 1][0] = t4[2]; Blf[p * 2 + 1][1] = t4[3];
            }
            #pragma unroll
            for (int mt = 0; mt < 4; mt++)
                #pragma unroll
                for (int nt = 0; nt < 4; nt++)
                    mma_bf16(acc[mt][nt], Ahf[mt], Blf[nt]);

            uint32_t Alf[4][4];
            #pragma unroll
            for (int mt = 0; mt < 4; mt++) {
                int row = warpm * 64 + mt * 16 + (lane & 15);
                ldsm_x4(Alf[mt], As + sw128((uint32_t)(row * 128 + (jl + (lane >> 4)) * 16)));
            }
            #pragma unroll
            for (int mt = 0; mt < 4; mt++)
                #pragma unroll
                for (int nt = 0; nt < 4; nt++)
                    mma_bf16(acc[mt][nt], Alf[mt], Bhf[nt]);
        }

        if (kt + 2 < NKT) load_stage((kt + 2) % 3, kt + 2);
        CP_COMMIT();                      // unconditional: uniform group counting
    }

    const int g = lane >> 2;
    const int t = lane & 3;
    if (SPLIT_OUT) {
        const int mat  = col0 >> 10;
        const int colb = col0 & 1023;
        __nv_bfloat16* ch = Ch + (size_t)mat * NX;
        __nv_bfloat16* cl = Cl + (size_t)mat * NX;
        #pragma unroll
        for (int mt = 0; mt < 4; mt++)
            #pragma unroll
            for (int nt = 0; nt < 4; nt++) {
                int row = row0 + warpm * 64 + mt * 16 + g;
                int col = colb + warpn * 32 + nt * 8 + t * 2;
                split_store_pair(acc[mt][nt][0], acc[mt][nt][1],
                                 ch + (size_t)row * DM + col, cl + (size_t)row * DM + col);
                split_store_pair(acc[mt][nt][2], acc[mt][nt][3],
                                 ch + (size_t)(row + 8) * DM + col,
                                 cl + (size_t)(row + 8) * DM + col);
            }
    } else {
        #pragma unroll
        for (int mt = 0; mt < 4; mt++)
            #pragma unroll
            for (int nt = 0; nt < 4; nt++) {
                int row = row0 + warpm * 64 + mt * 16 + g;
                int col = col0 + warpn * 32 + nt * 8 + t * 2;
                float2 v0 = make_float2(acc[mt][nt][0], acc[mt][nt][1]);
                float2 v1 = make_float2(acc[mt][nt][2], acc[mt][nt][3]);
                *reinterpret_cast<float2*>(&C[(size_t)row * DM + col])       = v0;
                *reinterpret_cast<float2*>(&C[(size_t)(row + 8) * DM + col]) = v1;
            }
    }
}

// ---------------------------------------------------------------------------
// Tensor-core flash attention (split-bf16, causal), BM=64, BN=64.
// Q staged through KV stage-0 (no dedicated Q smem) -> SMEM = 64KB -> 3 CTAs/SM.
// 4 warps x 16 rows, 128 thr, full 3-term P@V.
// ---------------------------------------------------------------------------
static constexpr int ATTN_SMEM = 2 * 32768;           // 65536
static constexpr float SCALE_L2E = 0.125f * 1.4426950408889634f;

__global__ __launch_bounds__(128, 3) void flash_attn_mma_kernel(
    const __nv_bfloat16* __restrict__ qh, const __nv_bfloat16* __restrict__ ql,
    const __nv_bfloat16* __restrict__ kh, const __nv_bfloat16* __restrict__ kl,
    const __nv_bfloat16* __restrict__ vh, const __nv_bfloat16* __restrict__ vl,
    __nv_bfloat16* __restrict__ th, __nv_bfloat16* __restrict__ tl)
{
    extern __shared__ char smem[];
    const uint32_t sbase = smem_u32(smem);

    const int tid  = threadIdx.x;
    const int wid  = tid >> 5;        // 0..3
    const int lane = tid & 31;
    const int g    = lane >> 2;
    const int t    = lane & 3;

    const int qb = (SEQ / 64 - 1) - blockIdx.x;    // heavy blocks first
    const int bh = blockIdx.y;
    const int b  = bh >> 4;
    const int h  = bh & 15;
    const int q0 = qb * 64;
    const int bofs = b * SEQ;
    const int NT = qb + 1;                          // kv tiles of 64
    const int rowg = q0 + wid * 16 + g;

    // ---- stage Q through stage-0 buffer, read fragments, then recycle ----
    #pragma unroll
    for (int term = 0; term < 2; term++) {
        const __nv_bfloat16* src = term ? ql : qh;
        #pragma unroll
        for (int tt = 0; tt < 4; tt++) {
            int v = tt * 128 + tid;
            int r = v >> 3;
            int c = v & 7;
            cp_async16(sbase + term * 8192 + sw128((uint32_t)(r * 128 + c * 16)),
                       src + (size_t)(bofs + q0 + r) * DM + h * 64 + c * 8);
        }
    }
    CP_COMMIT();
    CP_WAIT(0);
    __syncthreads();

    uint32_t qf[2][4][4];
    #pragma unroll
    for (int term = 0; term < 2; term++) {
        const uint32_t qbse = sbase + term * 8192;
        #pragma unroll
        for (int j = 0; j < 4; j++) {
            int row   = wid * 16 + (lane & 15);
            int chunk = j * 2 + (lane >> 4);
            ldsm_x4(qf[term][j], qbse + sw128((uint32_t)(row * 128 + chunk * 16)));
        }
    }
    __syncthreads();   // all warps have Q fragments; stage-0 is now free

    auto load_kv = [&](int stage, int kt2) {
        const int kv = kt2 * 64;
        const uint32_t base = sbase + stage * 32768;
        const __nv_bfloat16* bufs[4] = {kh, kl, vh, vl};
        #pragma unroll
        for (int buf = 0; buf < 4; buf++) {
            #pragma unroll
            for (int tt = 0; tt < 4; tt++) {
                int v = tt * 128 + tid;
                int r = v >> 3;
                int c = v & 7;
                cp_async16(base + buf * 8192 + sw128((uint32_t)(r * 128 + c * 16)),
                           bufs[buf] + (size_t)(bofs + kv + r) * DM + h * 64 + c * 8);
            }
        }
    };

    load_kv(0, 0); CP_COMMIT();
    load_kv(1, NT > 1 ? 1 : 0); CP_COMMIT();

    float m0 = -1e30f, m1 = -1e30f, l0 = 0.0f, l1 = 0.0f;
    float oacc[8][4];
    #pragma unroll
    for (int nt = 0; nt < 8; nt++)
        #pragma unroll
        for (int c = 0; c < 4; c++) oacc[nt][c] = 0.0f;

    for (int kt = 0; kt < NT; kt++) {
        if (kt + 1 < NT) { CP_WAIT(1); } else { CP_WAIT(0); }
        __syncthreads();

        const int kv0 = kt * 64;
        const uint32_t stg = sbase + (kt & 1) * 32768;

        // ---- S = (Qh+Ql) @ (Kh+Kl)^T ----
        float sacc[8][4];
        #pragma unroll
        for (int nt = 0; nt < 8; nt++)
            #pragma unroll
            for (int c = 0; c < 4; c++) sacc[nt][c] = 0.0f;

        #pragma unroll
        for (int j = 0; j < 4; j++) {
            uint32_t kf[2][8][2];
            #pragma unroll
            for (int term = 0; term < 2; term++) {
                const uint32_t kb = stg + term * 8192;
                #pragma unroll
                for (int np = 0; np < 4; np++) {
                    int row   = np * 16 + ((lane >> 4) << 3) + (lane & 7);
                    int chunk = j * 2 + ((lane >> 3) & 1);
                    uint32_t t4[4];
                    ldsm_x4(t4, kb + sw128((uint32_t)(row * 128 + chunk * 16)));
                    kf[term][np * 2][0]     = t4[0];
                    kf[term][np * 2][1]     = t4[1];
                    kf[term][np * 2 + 1][0] = t4[2];
                    kf[term][np * 2 + 1][1] = t4[3];
                }
            }
            #pragma unroll
            for (int nt = 0; nt < 8; nt++) {
                mma_bf16(sacc[nt], qf[0][j], kf[0][nt]);
                mma_bf16(sacc[nt], qf[0][j], kf[1][nt]);
                mma_bf16(sacc[nt], qf[1][j], kf[0][nt]);
            }
        }

        // ---- scale to log2 domain + causal mask (diagonal tile only) ----
        const bool lastt = (kt == NT - 1);
        #pragma unroll
        for (int nt = 0; nt < 8; nt++) {
            #pragma unroll
            for (int c = 0; c < 4; c++) {
                float s = sacc[nt][c] * SCALE_L2E;
                if (lastt) {
                    int col = kv0 + nt * 8 + t * 2 + (c & 1);
                    int row = (c < 2) ? rowg : rowg + 8;
                    if (col > row) s = -1e30f;
                }
                sacc[nt][c] = s;
            }
        }

        // ---- online softmax (base-2) ----
        float mx0 = -1e30f, mx1 = -1e30f;
        #pragma unroll
        for (int nt = 0; nt < 8; nt++) {
            mx0 = fmaxf(mx0, fmaxf(sacc[nt][0], sacc[nt][1]));
            mx1 = fmaxf(mx1, fmaxf(sacc[nt][2], sacc[nt][3]));
        }
        mx0 = fmaxf(mx0, __shfl_xor_sync(0xffffffffu, mx0, 1));
        mx0 = fmaxf(mx0, __shfl_xor_sync(0xffffffffu, mx0, 2));
        mx1 = fmaxf(mx1, __shfl_xor_sync(0xffffffffu, mx1, 1));
        mx1 = fmaxf(mx1, __shfl_xor_sync(0xffffffffu, mx1, 2));
        float mnew0 = fmaxf(m0, mx0), mnew1 = fmaxf(m1, mx1);
        float a0 = exp2f(m0 - mnew0), a1 = exp2f(m1 - mnew1);
        m0 = mnew0; m1 = mnew1;

        float rs0 = 0.0f, rs1 = 0.0f;
        #pragma unroll
        for (int nt = 0; nt < 8; nt++) {
            float p0 = exp2f(sacc[nt][0] - mnew0);
            float p1 = exp2f(sacc[nt][1] - mnew0);
            float p2 = exp2f(sacc[nt][2] - mnew1);
            float p3 = exp2f(sacc[nt][3] - mnew1);
            sacc[nt][0] = p0; sacc[nt][1] = p1;
            sacc[nt][2] = p2; sacc[nt][3] = p3;
            rs0 += p0 + p1; rs1 += p2 + p3;
        }
        rs0 += __shfl_xor_sync(0xffffffffu, rs0, 1);
        rs0 += __shfl_xor_sync(0xffffffffu, rs0, 2);
        rs1 += __shfl_xor_sync(0xffffffffu, rs1, 1);
        rs1 += __shfl_xor_sync(0xffffffffu, rs1, 2);
        l0 = l0 * a0 + rs0;
        l1 = l1 * a1 + rs1;
        #pragma unroll
        for (int nt = 0; nt < 8; nt++) {
            oacc[nt][0] *= a0; oacc[nt][1] *= a0;
            oacc[nt][2] *= a1; oacc[nt][3] *= a1;
        }

        // ---- O += (Ph+Pl) @ (Vh+Vl)  (full 3 terms) ----
        #pragma unroll
        for (int pj = 0; pj < 4; pj++) {
            const float* se = sacc[2 * pj];
            const float* so = sacc[2 * pj + 1];
            uint32_t ph[4], pl[4];
            pack_split(se[0], se[1], ph[0], pl[0]);
            pack_split(se[2], se[3], ph[1], pl[1]);
            pack_split(so[0], so[1], ph[2], pl[2]);
            pack_split(so[2], so[3], ph[3], pl[3]);

            uint32_t vf[2][8][2];
            #pragma unroll
            for (int term = 0; term < 2; term++) {
                const uint32_t vb = stg + 16384 + term * 8192;
                #pragma unroll
                for (int np = 0; np < 4; np++) {
                    int kvrow = pj * 16 + (lane & 15);
                    int dby   = np * 32 + ((lane >> 4) * 16);
                    uint32_t t4[4];
                    ldsm_x4_t(t4, vb + sw128((uint32_t)(kvrow * 128 + dby)));
                    vf[term][np * 2][0]     = t4[0];
                    vf[term][np * 2][1]     = t4[1];
                    vf[term][np * 2 + 1][0] = t4[2];
                    vf[term][np * 2 + 1][1] = t4[3];
                }
            }
            #pragma unroll
            for (int nt = 0; nt < 8; nt++) {
                mma_bf16(oacc[nt], ph, vf[0][nt]);
                mma_bf16(oacc[nt], ph, vf[1][nt]);
                mma_bf16(oacc[nt], pl, vf[0][nt]);
            }
        }

        __syncthreads();
        if (kt + 2 < NT) { load_kv(kt & 1, kt + 2); CP_COMMIT(); }
        else CP_COMMIT();
    }

    // ---- epilogue: normalize + split-write T ----
    const float inv0 = 1.0f / l0, inv1 = 1.0f / l1;
    const size_t rb0 = (size_t)(bofs + rowg) * DM + h * 64;
    const size_t rb1 = rb0 + (size_t)8 * DM;
    #pragma unroll
    for (int nt = 0; nt < 8; nt++) {
        int col = nt * 8 + t * 2;
        split_store_pair(oacc[nt][0] * inv0, oacc[nt][1] * inv0,
                         th + rb0 + col, tl + rb0 + col);
        split_store_pair(oacc[nt][2] * inv1, oacc[nt][3] * inv1,
                         th + rb1 + col, tl + rb1 + col);
    }
}

// ---------------------------------------------------------------------------
// Launcher — attention at launch index 3 (the one ncu captures)
// ---------------------------------------------------------------------------
extern "C" void kernel_launch(void* const* d_in, const int* in_sizes, int n_in,
                              void* d_out, int out_size)
{
    const float* x   = (const float*)d_in[0];
    const float* W_q = (const float*)d_in[1];
    const float* W_k = (const float*)d_in[2];
    const float* W_v = (const float*)d_in[3];
    const float* W_o = (const float*)d_in[4];
    float* out = (float*)d_out;

    __nv_bfloat16 *xh, *xl, *Wh, *Wl, *qkvh, *qkvl, *th, *tl;
    cudaGetSymbolAddress((void**)&xh, g_xh);
    cudaGetSymbolAddress((void**)&xl, g_xl);
    cudaGetSymbolAddress((void**)&Wh, g_Wh);
    cudaGetSymbolAddress((void**)&Wl, g_Wl);
    cudaGetSymbolAddress((void**)&qkvh, g_qkvh);
    cudaGetSymbolAddress((void**)&qkvl, g_qkvl);
    cudaGetSymbolAddress((void**)&th, g_th);
    cudaGetSymbolAddress((void**)&tl, g_tl);

    cudaFuncSetAttribute(gemm_mma_split_kernel<true>,
                         cudaFuncAttributeMaxDynamicSharedMemorySize, GEMM_SMEM);
    cudaFuncSetAttribute(gemm_mma_split_kernel<false>,
                         cudaFuncAttributeMaxDynamicSharedMemorySize, GEMM_SMEM);
    cudaFuncSetAttribute(flash_attn_mma_kernel,
                         cudaFuncAttributeMaxDynamicSharedMemorySize, ATTN_SMEM);

    const int nx4 = (int)(NX / 4);
    const int nw4all = (int)(NW);          // 4 * (NW/4)

    // launch 0: x split
    split_bf16_kernel<<<(nx4 + 255) / 256, 256>>>(x, xh, xl, nx4);
    // launch 1: all 4 weight splits fused
    split_w4_kernel<<<(nw4all + 255) / 256, 256>>>(W_q, W_k, W_v, W_o, Wh, Wl);

    // launch 2: fused QKV GEMM
    dim3 qkv_grid(3 * DM / 128, ROWS / 128);   // (24, 64)
    gemm_mma_split_kernel<true><<<qkv_grid, 256, GEMM_SMEM>>>(
        xh, xl, Wh, Wl, nullptr, qkvh, qkvl);

    // launch 3: attention  (<-- profiled launch)
    dim3 attn_grid(SEQ / 64, BATCH * NH);      // (32, 64)
    flash_attn_mma_kernel<<<attn_grid, 128, ATTN_SMEM>>>(
        qkvh, qkvl, qkvh + NX, qkvl + NX, qkvh + 2 * NX, qkvl + 2 * NX, th, tl);

    // launch 4: output projection
    dim3 o_grid(DM / 128, ROWS / 128);         // (8, 64)
    gemm_mma_split_kernel<false><<<o_grid, 256, GEMM_SMEM>>>(
        th, tl, Wh + 3 * NW, Wl + 3 * NW, out, nullptr, nullptr);
}

// round 12
// speedup vs baseline: 1.0779x; 1.0135x over previous
#include <cuda_runtime.h>
#include <cuda_bf16.h>
#include <cstdint>

// Problem constants
static constexpr int BATCH = 4;
static constexpr int SEQ   = 2048;
static constexpr int DM    = 1024;
static constexpr int NH    = 16;
static constexpr int DH    = 64;
static constexpr int ROWS  = BATCH * SEQ;        // 8192
static constexpr size_t NX = (size_t)ROWS * DM;  // 8388608
static constexpr size_t NW = (size_t)DM * DM;    // 1048576

// Scratch (device globals: allocation-free)
__device__ __nv_bfloat16 g_xh[NX];
__device__ __nv_bfloat16 g_xl[NX];
__device__ __nv_bfloat16 g_Wh[4 * NW];   // Wq|Wk|Wv|Wo
__device__ __nv_bfloat16 g_Wl[4 * NW];
__device__ __nv_bfloat16 g_qkvh[3 * NX]; // Q|K|V hi
__device__ __nv_bfloat16 g_qkvl[3 * NX]; // Q|K|V lo
__device__ __nv_bfloat16 g_th[NX];
__device__ __nv_bfloat16 g_tl[NX];

// ---------------------------------------------------------------------------
// Helpers
// ---------------------------------------------------------------------------
__device__ __forceinline__ uint32_t smem_u32(const void* p) {
    uint32_t a;
    asm("{ .reg .u64 t; cvta.to.shared.u64 t, %1; cvt.u32.u64 %0, t; }"
        : "=r"(a) : "l"(p));
    return a;
}
__device__ __forceinline__ uint32_t sw128(uint32_t off) {
    return off ^ ((off >> 3) & 0x70);
}
__device__ __forceinline__ void cp_async16(uint32_t saddr, const void* gaddr) {
    asm volatile("cp.async.cg.shared.global [%0], [%1], 16;"
                 :: "r"(saddr), "l"(gaddr));
}
#define CP_COMMIT() asm volatile("cp.async.commit_group;")
#define CP_WAIT(n)  asm volatile("cp.async.wait_group %0;" :: "n"(n))

__device__ __forceinline__ void ldsm_x4(uint32_t (&r)[4], uint32_t addr) {
    asm volatile("ldmatrix.sync.aligned.m8n8.x4.shared.b16 {%0,%1,%2,%3}, [%4];"
                 : "=r"(r[0]), "=r"(r[1]), "=r"(r[2]), "=r"(r[3]) : "r"(addr));
}
__device__ __forceinline__ void ldsm_x4_t(uint32_t (&r)[4], uint32_t addr) {
    asm volatile("ldmatrix.sync.aligned.m8n8.x4.trans.shared.b16 {%0,%1,%2,%3}, [%4];"
                 : "=r"(r[0]), "=r"(r[1]), "=r"(r[2]), "=r"(r[3]) : "r"(addr));
}
__device__ __forceinline__ void mma_bf16(float (&d)[4], const uint32_t (&a)[4],
                                         const uint32_t* b) {
    asm volatile(
        "mma.sync.aligned.m16n8k16.row.col.f32.bf16.bf16.f32 "
        "{%0,%1,%2,%3}, {%4,%5,%6,%7}, {%8,%9}, {%0,%1,%2,%3};"
        : "+f"(d[0]), "+f"(d[1]), "+f"(d[2]), "+f"(d[3])
        : "r"(a[0]), "r"(a[1]), "r"(a[2]), "r"(a[3]), "r"(b[0]), "r"(b[1]));
}

__device__ __forceinline__ void split_store_pair(float a, float b,
                                                 __nv_bfloat16* hp, __nv_bfloat16* lp) {
    __nv_bfloat162 h2 = __float22bfloat162_rn(make_float2(a, b));
    float2 hf = __bfloat1622float2(h2);
    __nv_bfloat162 l2 = __float22bfloat162_rn(make_float2(a - hf.x, b - hf.y));
    *reinterpret_cast<uint32_t*>(hp) = *reinterpret_cast<const uint32_t*>(&h2);
    *reinterpret_cast<uint32_t*>(lp) = *reinterpret_cast<const uint32_t*>(&l2);
}
__device__ __forceinline__ void pack_split(float a, float b, uint32_t& ph, uint32_t& pl) {
    __nv_bfloat162 h2 = __float22bfloat162_rn(make_float2(a, b));
    float2 hf = __bfloat1622float2(h2);
    __nv_bfloat162 l2 = __float22bfloat162_rn(make_float2(a - hf.x, b - hf.y));
    ph = *reinterpret_cast<const uint32_t*>(&h2);
    pl = *reinterpret_cast<const uint32_t*>(&l2);
}

// ---------------------------------------------------------------------------
// fp32 -> (hi, lo) bf16 split (single source)
// ---------------------------------------------------------------------------
__global__ __launch_bounds__(256) void split_bf16_kernel(
    const float* __restrict__ src, __nv_bfloat16* __restrict__ hi,
    __nv_bfloat16* __restrict__ lo, int n4)
{
    int i = blockIdx.x * blockDim.x + threadIdx.x;
    if (i >= n4) return;
    float4 v = reinterpret_cast<const float4*>(src)[i];
    __nv_bfloat162 h0 = __float22bfloat162_rn(make_float2(v.x, v.y));
    __nv_bfloat162 h1 = __float22bfloat162_rn(make_float2(v.z, v.w));
    float2 f0 = __bfloat1622float2(h0), f1 = __bfloat1622float2(h1);
    __nv_bfloat162 l0 = __float22bfloat162_rn(make_float2(v.x - f0.x, v.y - f0.y));
    __nv_bfloat162 l1 = __float22bfloat162_rn(make_float2(v.z - f1.x, v.w - f1.y));
    uint2 hv, lv;
    hv.x = *reinterpret_cast<uint32_t*>(&h0); hv.y = *reinterpret_cast<uint32_t*>(&h1);
    lv.x = *reinterpret_cast<uint32_t*>(&l0); lv.y = *reinterpret_cast<uint32_t*>(&l1);
    reinterpret_cast<uint2*>(hi)[i] = hv;
    reinterpret_cast<uint2*>(lo)[i] = lv;
}

// fp32 -> (hi,lo) for the 4 weight matrices in ONE launch
__global__ __launch_bounds__(256) void split_w4_kernel(
    const float* __restrict__ w0, const float* __restrict__ w1,
    const float* __restrict__ w2, const float* __restrict__ w3,
    __nv_bfloat16* __restrict__ hi, __nv_bfloat16* __restrict__ lo)
{
    const int nw4 = (int)(NW / 4);
    int i = blockIdx.x * blockDim.x + threadIdx.x;
    if (i >= 4 * nw4) return;
    const int mat = i / nw4;
    const int j   = i - mat * nw4;
    const float* src = (mat == 0) ? w0 : (mat == 1) ? w1 : (mat == 2) ? w2 : w3;
    float4 v = reinterpret_cast<const float4*>(src)[j];
    __nv_bfloat162 h0 = __float22bfloat162_rn(make_float2(v.x, v.y));
    __nv_bfloat162 h1 = __float22bfloat162_rn(make_float2(v.z, v.w));
    float2 f0 = __bfloat1622float2(h0), f1 = __bfloat1622float2(h1);
    __nv_bfloat162 l0 = __float22bfloat162_rn(make_float2(v.x - f0.x, v.y - f0.y));
    __nv_bfloat162 l1 = __float22bfloat162_rn(make_float2(v.z - f1.x, v.w - f1.y));
    uint2 hv, lv;
    hv.x = *reinterpret_cast<uint32_t*>(&h0); hv.y = *reinterpret_cast<uint32_t*>(&h1);
    lv.x = *reinterpret_cast<uint32_t*>(&l0); lv.y = *reinterpret_cast<uint32_t*>(&l1);
    reinterpret_cast<uint2*>(hi)[i] = hv;
    reinterpret_cast<uint2*>(lo)[i] = lv;
}

// ---------------------------------------------------------------------------
// bf16-split GEMM (NT), K = 1024. 128x128 CTA tile, BK=32, 3-stage ring,
// single barrier per k-step, 2 CTAs/SM. (R11-proven)
// ---------------------------------------------------------------------------
static constexpr int TILE_B    = 128 * 128;
static constexpr int STAGE_B   = 2 * TILE_B;          // 32 KB
static constexpr int GSTAGES   = 3;
static constexpr int GEMM_SMEM = GSTAGES * STAGE_B;   // 98304

template <bool SPLIT_OUT>
__global__ __launch_bounds__(256, 2) void gemm_mma_split_kernel(
    const __nv_bfloat16* __restrict__ Ah, const __nv_bfloat16* __restrict__ Al,
    const __nv_bfloat16* __restrict__ Bh, const __nv_bfloat16* __restrict__ Bl,
    float* __restrict__ C, __nv_bfloat16* __restrict__ Ch,
    __nv_bfloat16* __restrict__ Cl)
{
    extern __shared__ char smem[];
    const uint32_t sbase = smem_u32(smem);
    constexpr int K   = DM;
    constexpr int NKT = K / 32;

    const int tid   = threadIdx.x;
    const int wid   = tid >> 5;
    const int lane  = tid & 31;
    const int warpm = wid >> 2;
    const int warpn = wid & 3;
    const int row0  = blockIdx.y * 128;
    const int col0  = blockIdx.x * 128;

    auto load_stage = [&](int s, int kt) {
        const uint32_t As = sbase + s * STAGE_B;
        const uint32_t Bs = As + TILE_B;
        const size_t kofs = (size_t)kt * 32;
        const __nv_bfloat16* Ah0 = Ah + (size_t)row0 * K + kofs;
        const __nv_bfloat16* Al0 = Al + (size_t)row0 * K + kofs;
        const __nv_bfloat16* Bh0 = Bh + (size_t)col0 * K + kofs;
        const __nv_bfloat16* Bl0 = Bl + (size_t)col0 * K + kofs;
        #pragma unroll
        for (int t = 0; t < 4; t++) {
            int v = t * 256 + tid;
            int r = v >> 3;
            int c = v & 7;
            uint32_t soff = sw128((uint32_t)(r * 128 + c * 16));
            cp_async16(As + soff, (c < 4 ? Ah0 : Al0) + (size_t)r * K + (c & 3) * 8);
            cp_async16(Bs + soff, (c < 4 ? Bh0 : Bl0) + (size_t)r * K + (c & 3) * 8);
        }
    };

    float acc[4][4][4];
    #pragma unroll
    for (int i = 0; i < 4; i++)
        #pragma unroll
        for (int j = 0; j < 4; j++)
            #pragma unroll
            for (int k = 0; k < 4; k++) acc[i][j][k] = 0.0f;

    load_stage(0, 0); CP_COMMIT();
    load_stage(1, 1); CP_COMMIT();

    for (int kt = 0; kt < NKT; kt++) {
        CP_WAIT(1);
        __syncthreads();

        const uint32_t As = sbase + (kt % 3) * STAGE_B;
        const uint32_t Bs = As + TILE_B;

        #pragma unroll
        for (int kc = 0; kc < 2; kc++) {
            const int jh = kc * 2;
            const int jl = 4 + kc * 2;

            uint32_t Ahf[4][4], Bhf[4][2];
            #pragma unroll
            for (int mt = 0; mt < 4; mt++) {
                int row = warpm * 64 + mt * 16 + (lane & 15);
                ldsm_x4(Ahf[mt], As + sw128((uint32_t)(row * 128 + (jh + (lane >> 4)) * 16)));
            }
            #pragma unroll
            for (int p = 0; p < 2; p++) {
                int row = warpn * 32 + p * 16 + ((lane >> 4) << 3) + (lane & 7);
                uint32_t t4[4];
                ldsm_x4(t4, Bs + sw128((uint32_t)(row * 128 + (jh + ((lane >> 3) & 1)) * 16)));
                Bhf[p * 2][0]     = t4[0]; Bhf[p * 2][1]     = t4[1];
                Bhf[p * 2 + 1][0] = t4[2]; Bhf[p * 2 + 1][1] = t4[3];
            }
            #pragma unroll
            for (int mt = 0; mt < 4; mt++)
                #pragma unroll
                for (int nt = 0; nt < 4; nt++)
                    mma_bf16(acc[mt][nt], Ahf[mt], Bhf[nt]);

            uint32_t Blf[4][2];
            #pragma unroll
            for (int p = 0; p < 2; p++) {
                int row = warpn * 32 + p * 16 + ((lane >> 4) << 3) + (lane & 7);
                uint32_t t4[4];
                ldsm_x4(t4, Bs + sw128((uint32_t)(row * 128 + (jl + ((lane >> 3) & 1)) * 16)));
                Blf[p * 2][0]     = t4[0]; Blf[p * 2][1]     = t4[1];
                Blf[p * 2 + 1][0] = t4[2]; Blf[p * 2 + 1][1] = t4[3];
            }
            #pragma unroll
            for (int mt = 0; mt < 4; mt++)
                #pragma unroll
                for (int nt = 0; nt < 4; nt++)
                    mma_bf16(acc[mt][nt], Ahf[mt], Blf[nt]);

            uint32_t Alf[4][4];
            #pragma unroll
            for (int mt = 0; mt < 4; mt++) {
                int row = warpm * 64 + mt * 16 + (lane & 15);
                ldsm_x4(Alf[mt], As + sw128((uint32_t)(row * 128 + (jl + (lane >> 4)) * 16)));
            }
            #pragma unroll
            for (int mt = 0; mt < 4; mt++)
                #pragma unroll
                for (int nt = 0; nt < 4; nt++)
                    mma_bf16(acc[mt][nt], Alf[mt], Bhf[nt]);
        }

        if (kt + 2 < NKT) load_stage((kt + 2) % 3, kt + 2);
        CP_COMMIT();
    }

    const int g = lane >> 2;
    const int t = lane & 3;
    if (SPLIT_OUT) {
        const int mat  = col0 >> 10;
        const int colb = col0 & 1023;
        __nv_bfloat16* ch = Ch + (size_t)mat * NX;
        __nv_bfloat16* cl = Cl + (size_t)mat * NX;
        #pragma unroll
        for (int mt = 0; mt < 4; mt++)
            #pragma unroll
            for (int nt = 0; nt < 4; nt++) {
                int row = row0 + warpm * 64 + mt * 16 + g;
                int col = colb + warpn * 32 + nt * 8 + t * 2;
                split_store_pair(acc[mt][nt][0], acc[mt][nt][1],
                                 ch + (size_t)row * DM + col, cl + (size_t)row * DM + col);
                split_store_pair(acc[mt][nt][2], acc[mt][nt][3],
                                 ch + (size_t)(row + 8) * DM + col,
                                 cl + (size_t)(row + 8) * DM + col);
            }
    } else {
        #pragma unroll
        for (int mt = 0; mt < 4; mt++)
            #pragma unroll
            for (int nt = 0; nt < 4; nt++) {
                int row = row0 + warpm * 64 + mt * 16 + g;
                int col = col0 + warpn * 32 + nt * 8 + t * 2;
                float2 v0 = make_float2(acc[mt][nt][0], acc[mt][nt][1]);
                float2 v1 = make_float2(acc[mt][nt][2], acc[mt][nt][3]);
                *reinterpret_cast<float2*>(&C[(size_t)row * DM + col])       = v0;
                *reinterpret_cast<float2*>(&C[(size_t)(row + 8) * DM + col]) = v1;
            }
    }
}

// ---------------------------------------------------------------------------
// Tensor-core flash attention — software-pipelined S (FA3-style).
// BM=64, BN=64, 4 warps x 16 rows, 128 thr.
// K double-buffered (2x16KB), V triple-buffered (3x16KB) = 80KB -> 2 CTAs/SM.
// S(kt+1) MMAs issued during softmax/PV of tile kt.
// ---------------------------------------------------------------------------
static constexpr int ATTN_SMEM = 5 * 16384;           // 81920
static constexpr float SCALE_L2E = 0.125f * 1.4426950408889634f;

__global__ __launch_bounds__(128, 2) void flash_attn_mma_kernel(
    const __nv_bfloat16* __restrict__ qh, const __nv_bfloat16* __restrict__ ql,
    const __nv_bfloat16* __restrict__ kh, const __nv_bfloat16* __restrict__ kl,
    const __nv_bfloat16* __restrict__ vh, const __nv_bfloat16* __restrict__ vl,
    __nv_bfloat16* __restrict__ th, __nv_bfloat16* __restrict__ tl)
{
    extern __shared__ char smem[];
    const uint32_t sbase = smem_u32(smem);
    const uint32_t VBASE = sbase + 32768;          // vbuf[i] = VBASE + i*16384

    const int tid  = threadIdx.x;
    const int wid  = tid >> 5;        // 0..3
    const int lane = tid & 31;
    const int g    = lane >> 2;
    const int t    = lane & 3;

    const int qb = (SEQ / 64 - 1) - blockIdx.x;    // heavy blocks first
    const int bh = blockIdx.y;
    const int b  = bh >> 4;
    const int h  = bh & 15;
    const int q0 = qb * 64;
    const int bofs = b * SEQ;
    const int NT = qb + 1;                          // kv tiles of 64
    const int rowg = q0 + wid * 16 + g;

    // ---- stage Q through vbuf[2] (not written until iter 0's load of tile 2) ----
    {
        const uint32_t qstage = VBASE + 2 * 16384;
        #pragma unroll
        for (int term = 0; term < 2; term++) {
            const __nv_bfloat16* src = term ? ql : qh;
            #pragma unroll
            for (int tt = 0; tt < 4; tt++) {
                int v = tt * 128 + tid;
                int r = v >> 3;
                int c = v & 7;
                cp_async16(qstage + term * 8192 + sw128((uint32_t)(r * 128 + c * 16)),
                           src + (size_t)(bofs + q0 + r) * DM + h * 64 + c * 8);
            }
        }
    }
    CP_COMMIT();
    CP_WAIT(0);
    __syncthreads();

    uint32_t qf[2][4][4];
    #pragma unroll
    for (int term = 0; term < 2; term++) {
        const uint32_t qbse = VBASE + 2 * 16384 + term * 8192;
        #pragma unroll
        for (int j = 0; j < 4; j++) {
            int row   = wid * 16 + (lane & 15);
            int chunk = j * 2 + (lane >> 4);
            ldsm_x4(qf[term][j], qbse + sw128((uint32_t)(row * 128 + chunk * 16)));
        }
    }
    __syncthreads();   // Q fragments extracted; vbuf[2] free

    // loader: K -> kbuf[t&1], V -> vbuf[t%3]
    auto load_kv = [&](int tile) {
        const int kv = tile * 64;
        const uint32_t kb = sbase + (tile & 1) * 16384;
        const uint32_t vb = VBASE + (tile % 3) * 16384;
        const __nv_bfloat16* bufs[4] = {kh, kl, vh, vl};
        const uint32_t dsts[4] = {kb, kb + 8192, vb, vb + 8192};
        #pragma unroll
        for (int buf = 0; buf < 4; buf++) {
            #pragma unroll
            for (int tt = 0; tt < 4; tt++) {
                int v = tt * 128 + tid;
                int r = v >> 3;
                int c = v & 7;
                cp_async16(dsts[buf] + sw128((uint32_t)(r * 128 + c * 16)),
                           bufs[buf] + (size_t)(bofs + kv + r) * DM + h * 64 + c * 8);
            }
        }
    };

    // S-MMA for one tile: sout += (Qh+Ql)@(Kh+Kl)^T from K buffer kb
    auto s_mma = [&](float (&sout)[8][4], uint32_t kb) {
        #pragma unroll
        for (int nt = 0; nt < 8; nt++)
            #pragma unroll
            for (int c = 0; c < 4; c++) sout[nt][c] = 0.0f;
        #pragma unroll
        for (int j = 0; j < 4; j++) {
            uint32_t kf[2][8][2];
            #pragma unroll
            for (int term = 0; term < 2; term++) {
                const uint32_t kbb = kb + term * 8192;
                #pragma unroll
                for (int np = 0; np < 4; np++) {
                    int row   = np * 16 + ((lane >> 4) << 3) + (lane & 7);
                    int chunk = j * 2 + ((lane >> 3) & 1);
                    uint32_t t4[4];
                    ldsm_x4(t4, kbb + sw128((uint32_t)(row * 128 + chunk * 16)));
                    kf[term][np * 2][0]     = t4[0];
                    kf[term][np * 2][1]     = t4[1];
                    kf[term][np * 2 + 1][0] = t4[2];
                    kf[term][np * 2 + 1][1] = t4[3];
                }
            }
            #pragma unroll
            for (int nt = 0; nt < 8; nt++) {
                mma_bf16(sout[nt], qf[0][j], kf[0][nt]);
                mma_bf16(sout[nt], qf[0][j], kf[1][nt]);
                mma_bf16(sout[nt], qf[1][j], kf[0][nt]);
            }
        }
    };

    // prologue loads: tile 0 and tile 1 (tile 1 rows always valid; unused if NT==1)
    load_kv(0); CP_COMMIT();
    load_kv(1); CP_COMMIT();
    CP_WAIT(1);        // tile 0 ready (tile 1 in flight)
    __syncthreads();

    float m0 = -1e30f, m1 = -1e30f, l0 = 0.0f, l1 = 0.0f;
    float oacc[8][4];
    #pragma unroll
    for (int nt = 0; nt < 8; nt++)
        #pragma unroll
        for (int c = 0; c < 4; c++) oacc[nt][c] = 0.0f;

    float saccA[8][4], saccB[8][4];
    s_mma(saccA, sbase);               // S(0) from kbuf[0]

    // one pipelined iteration: cur = S(kt) raw scores; computes softmax+PV(kt),
    // issues S(kt+1) into next, prefetches tile kt+2.
    auto body = [&](float (&cur)[8][4], float (&next)[8][4], int kt) {
        CP_WAIT(0);                    // tile kt+1 data resident
        __syncthreads();               // all warps done with iter kt-1 buffers

        if (kt + 2 < NT) load_kv(kt + 2);   // K->kbuf[kt&1] (dead), V->vbuf[(kt+2)%3] (dead)
        CP_COMMIT();

        if (kt + 1 < NT) s_mma(next, sbase + ((kt + 1) & 1) * 16384);

        const int kv0 = kt * 64;
        const bool lastt = (kt == NT - 1);
        #pragma unroll
        for (int nt = 0; nt < 8; nt++) {
            #pragma unroll
            for (int c = 0; c < 4; c++) {
                float s = cur[nt][c] * SCALE_L2E;
                if (lastt) {
                    int col = kv0 + nt * 8 + t * 2 + (c & 1);
                    int row = (c < 2) ? rowg : rowg + 8;
                    if (col > row) s = -1e30f;
                }
                cur[nt][c] = s;
            }
        }

        float mx0 = -1e30f, mx1 = -1e30f;
        #pragma unroll
        for (int nt = 0; nt < 8; nt++) {
            mx0 = fmaxf(mx0, fmaxf(cur[nt][0], cur[nt][1]));
            mx1 = fmaxf(mx1, fmaxf(cur[nt][2], cur[nt][3]));
        }
        mx0 = fmaxf(mx0, __shfl_xor_sync(0xffffffffu, mx0, 1));
        mx0 = fmaxf(mx0, __shfl_xor_sync(0xffffffffu, mx0, 2));
        mx1 = fmaxf(mx1, __shfl_xor_sync(0xffffffffu, mx1, 1));
        mx1 = fmaxf(mx1, __shfl_xor_sync(0xffffffffu, mx1, 2));
        float mnew0 = fmaxf(m0, mx0), mnew1 = fmaxf(m1, mx1);
        float a0 = exp2f(m0 - mnew0), a1 = exp2f(m1 - mnew1);
        m0 = mnew0; m1 = mnew1;

        float rs0 = 0.0f, rs1 = 0.0f;
        #pragma unroll
        for (int nt = 0; nt < 8; nt++) {
            float p0 = exp2f(cur[nt][0] - mnew0);
            float p1 = exp2f(cur[nt][1] - mnew0);
            float p2 = exp2f(cur[nt][2] - mnew1);
            float p3 = exp2f(cur[nt][3] - mnew1);
            cur[nt][0] = p0; cur[nt][1] = p1;
            cur[nt][2] = p2; cur[nt][3] = p3;
            rs0 += p0 + p1; rs1 += p2 + p3;
        }
        rs0 += __shfl_xor_sync(0xffffffffu, rs0, 1);
        rs0 += __shfl_xor_sync(0xffffffffu, rs0, 2);
        rs1 += __shfl_xor_sync(0xffffffffu, rs1, 1);
        rs1 += __shfl_xor_sync(0xffffffffu, rs1, 2);
        l0 = l0 * a0 + rs0;
        l1 = l1 * a1 + rs1;
        #pragma unroll
        for (int nt = 0; nt < 8; nt++) {
            oacc[nt][0] *= a0; oacc[nt][1] *= a0;
            oacc[nt][2] *= a1; oacc[nt][3] *= a1;
        }

        // PV from cur and vbuf[kt%3]
        const uint32_t vb = VBASE + (kt % 3) * 16384;
        #pragma unroll
        for (int pj = 0; pj < 4; pj++) {
            const float* se = cur[2 * pj];
            const float* so = cur[2 * pj + 1];
            uint32_t ph[4], pl[4];
            pack_split(se[0], se[1], ph[0], pl[0]);
            pack_split(se[2], se[3], ph[1], pl[1]);
            pack_split(so[0], so[1], ph[2], pl[2]);
            pack_split(so[2], so[3], ph[3], pl[3]);

            uint32_t vf[2][8][2];
            #pragma unroll
            for (int term = 0; term < 2; term++) {
                const uint32_t vbb = vb + term * 8192;
                #pragma unroll
                for (int np = 0; np < 4; np++) {
                    int kvrow = pj * 16 + (lane & 15);
                    int dby   = np * 32 + ((lane >> 4) * 16);
                    uint32_t t4[4];
                    ldsm_x4_t(t4, vbb + sw128((uint32_t)(kvrow * 128 + dby)));
                    vf[term][np * 2][0]     = t4[0];
                    vf[term][np * 2][1]     = t4[1];
                    vf[term][np * 2 + 1][0] = t4[2];
                    vf[term][np * 2 + 1][1] = t4[3];
                }
            }
            #pragma unroll
            for (int nt = 0; nt < 8; nt++) {
                mma_bf16(oacc[nt], ph, vf[0][nt]);
                mma_bf16(oacc[nt], ph, vf[1][nt]);
                mma_bf16(oacc[nt], pl, vf[0][nt]);
            }
        }
    };

    for (int kt = 0; kt < NT; kt += 2) {
        body(saccA, saccB, kt);
        if (kt + 1 < NT) body(saccB, saccA, kt + 1);
    }

    // ---- epilogue: normalize + split-write T ----
    const float inv0 = 1.0f / l0, inv1 = 1.0f / l1;
    const size_t rb0 = (size_t)(bofs + rowg) * DM + h * 64;
    const size_t rb1 = rb0 + (size_t)8 * DM;
    #pragma unroll
    for (int nt = 0; nt < 8; nt++) {
        int col = nt * 8 + t * 2;
        split_store_pair(oacc[nt][0] * inv0, oacc[nt][1] * inv0,
                         th + rb0 + col, tl + rb0 + col);
        split_store_pair(oacc[nt][2] * inv1, oacc[nt][3] * inv1,
                         th + rb1 + col, tl + rb1 + col);
    }
}

// ---------------------------------------------------------------------------
// Launcher — attention at launch index 3 (the one ncu captures)
// ---------------------------------------------------------------------------
extern "C" void kernel_launch(void* const* d_in, const int* in_sizes, int n_in,
                              void* d_out, int out_size)
{
    const float* x   = (const float*)d_in[0];
    const float* W_q = (const float*)d_in[1];
    const float* W_k = (const float*)d_in[2];
    const float* W_v = (const float*)d_in[3];
    const float* W_o = (const float*)d_in[4];
    float* out = (float*)d_out;

    __nv_bfloat16 *xh, *xl, *Wh, *Wl, *qkvh, *qkvl, *th, *tl;
    cudaGetSymbolAddress((void**)&xh, g_xh);
    cudaGetSymbolAddress((void**)&xl, g_xl);
    cudaGetSymbolAddress((void**)&Wh, g_Wh);
    cudaGetSymbolAddress((void**)&Wl, g_Wl);
    cudaGetSymbolAddress((void**)&qkvh, g_qkvh);
    cudaGetSymbolAddress((void**)&qkvl, g_qkvl);
    cudaGetSymbolAddress((void**)&th, g_th);
    cudaGetSymbolAddress((void**)&tl, g_tl);

    cudaFuncSetAttribute(gemm_mma_split_kernel<true>,
                         cudaFuncAttributeMaxDynamicSharedMemorySize, GEMM_SMEM);
    cudaFuncSetAttribute(gemm_mma_split_kernel<false>,
                         cudaFuncAttributeMaxDynamicSharedMemorySize, GEMM_SMEM);
    cudaFuncSetAttribute(flash_attn_mma_kernel,
                         cudaFuncAttributeMaxDynamicSharedMemorySize, ATTN_SMEM);

    const int nx4 = (int)(NX / 4);
    const int nw4all = (int)(NW);          // 4 * (NW/4)

    // launch 0: x split
    split_bf16_kernel<<<(nx4 + 255) / 256, 256>>>(x, xh, xl, nx4);
    // launch 1: all 4 weight splits fused
    split_w4_kernel<<<(nw4all + 255) / 256, 256>>>(W_q, W_k, W_v, W_o, Wh, Wl);

    // launch 2: fused QKV GEMM
    dim3 qkv_grid(3 * DM / 128, ROWS / 128);   // (24, 64)
    gemm_mma_split_kernel<true><<<qkv_grid, 256, GEMM_SMEM>>>(
        xh, xl, Wh, Wl, nullptr, qkvh, qkvl);

    // launch 3: attention  (<-- profiled launch)
    dim3 attn_grid(SEQ / 64, BATCH * NH);      // (32, 64)
    flash_attn_mma_kernel<<<attn_grid, 128, ATTN_SMEM>>>(
        qkvh, qkvl, qkvh + NX, qkvl + NX, qkvh + 2 * NX, qkvl + 2 * NX, th, tl);

    // launch 4: output projection
    dim3 o_grid(DM / 128, ROWS / 128);         // (8, 64)
    gemm_mma_split_kernel<false><<<o_grid, 256, GEMM_SMEM>>>(
        th, tl, Wh + 3 * NW, Wl + 3 * NW, out, nullptr, nullptr);
}

// round 13
// speedup vs baseline: 1.1402x; 1.0578x over previous
#include <cuda_runtime.h>
#include <cuda_bf16.h>
#include <cuda_fp16.h>
#include <cstdint>

// Problem constants
static constexpr int BATCH = 4;
static constexpr int SEQ   = 2048;
static constexpr int DM    = 1024;
static constexpr int NH    = 16;
static constexpr int DH    = 64;
static constexpr int ROWS  = BATCH * SEQ;        // 8192
static constexpr size_t NX = (size_t)ROWS * DM;  // 8388608
static constexpr size_t NW = (size_t)DM * DM;    // 1048576

// Scratch (device globals: allocation-free)
__device__ __nv_bfloat16 g_xh[NX];
__device__ __nv_bfloat16 g_xl[NX];
__device__ __nv_bfloat16 g_Wh[4 * NW];   // Wq|Wk|Wv|Wo
__device__ __nv_bfloat16 g_Wl[4 * NW];
__device__ __nv_bfloat16 g_qkvh[3 * NX]; // Q|K bf16 hi, V fp16 hi
__device__ __nv_bfloat16 g_qkvl[3 * NX]; // Q|K bf16 lo, V fp16 lo
__device__ __nv_bfloat16 g_th[NX];
__device__ __nv_bfloat16 g_tl[NX];

// ---------------------------------------------------------------------------
// Helpers
// ---------------------------------------------------------------------------
__device__ __forceinline__ uint32_t smem_u32(const void* p) {
    uint32_t a;
    asm("{ .reg .u64 t; cvta.to.shared.u64 t, %1; cvt.u32.u64 %0, t; }"
        : "=r"(a) : "l"(p));
    return a;
}
__device__ __forceinline__ uint32_t sw128(uint32_t off) {
    return off ^ ((off >> 3) & 0x70);
}
__device__ __forceinline__ void cp_async16(uint32_t saddr, const void* gaddr) {
    asm volatile("cp.async.cg.shared.global [%0], [%1], 16;"
                 :: "r"(saddr), "l"(gaddr));
}
#define CP_COMMIT() asm volatile("cp.async.commit_group;")
#define CP_WAIT(n)  asm volatile("cp.async.wait_group %0;" :: "n"(n))

__device__ __forceinline__ void ldsm_x4(uint32_t (&r)[4], uint32_t addr) {
    asm volatile("ldmatrix.sync.aligned.m8n8.x4.shared.b16 {%0,%1,%2,%3}, [%4];"
                 : "=r"(r[0]), "=r"(r[1]), "=r"(r[2]), "=r"(r[3]) : "r"(addr));
}
__device__ __forceinline__ void ldsm_x4_t(uint32_t (&r)[4], uint32_t addr) {
    asm volatile("ldmatrix.sync.aligned.m8n8.x4.trans.shared.b16 {%0,%1,%2,%3}, [%4];"
                 : "=r"(r[0]), "=r"(r[1]), "=r"(r[2]), "=r"(r[3]) : "r"(addr));
}
__device__ __forceinline__ void mma_bf16(float (&d)[4], const uint32_t (&a)[4],
                                         const uint32_t* b) {
    asm volatile(
        "mma.sync.aligned.m16n8k16.row.col.f32.bf16.bf16.f32 "
        "{%0,%1,%2,%3}, {%4,%5,%6,%7}, {%8,%9}, {%0,%1,%2,%3};"
        : "+f"(d[0]), "+f"(d[1]), "+f"(d[2]), "+f"(d[3])
        : "r"(a[0]), "r"(a[1]), "r"(a[2]), "r"(a[3]), "r"(b[0]), "r"(b[1]));
}
__device__ __forceinline__ void mma_f16(float (&d)[4], const uint32_t (&a)[4],
                                        const uint32_t* b) {
    asm volatile(
        "mma.sync.aligned.m16n8k16.row.col.f32.f16.f16.f32 "
        "{%0,%1,%2,%3}, {%4,%5,%6,%7}, {%8,%9}, {%0,%1,%2,%3};"
        : "+f"(d[0]), "+f"(d[1]), "+f"(d[2]), "+f"(d[3])
        : "r"(a[0]), "r"(a[1]), "r"(a[2]), "r"(a[3]), "r"(b[0]), "r"(b[1]));
}

__device__ __forceinline__ void split_store_pair(float a, float b,
                                                 __nv_bfloat16* hp, __nv_bfloat16* lp) {
    __nv_bfloat162 h2 = __float22bfloat162_rn(make_float2(a, b));
    float2 hf = __bfloat1622float2(h2);
    __nv_bfloat162 l2 = __float22bfloat162_rn(make_float2(a - hf.x, b - hf.y));
    *reinterpret_cast<uint32_t*>(hp) = *reinterpret_cast<const uint32_t*>(&h2);
    *reinterpret_cast<uint32_t*>(lp) = *reinterpret_cast<const uint32_t*>(&l2);
}
// fp16 (hi,lo) split store — for the V buffer
__device__ __forceinline__ void split_store_pair_f16(float a, float b,
                                                     __nv_bfloat16* hp, __nv_bfloat16* lp) {
    __half2 h2 = __float22half2_rn(make_float2(a, b));
    float2 hf = __half22float2(h2);
    __half2 l2 = __float22half2_rn(make_float2(a - hf.x, b - hf.y));
    *reinterpret_cast<uint32_t*>(hp) = *reinterpret_cast<const uint32_t*>(&h2);
    *reinterpret_cast<uint32_t*>(lp) = *reinterpret_cast<const uint32_t*>(&l2);
}
__device__ __forceinline__ void pack_split(float a, float b, uint32_t& ph, uint32_t& pl) {
    __nv_bfloat162 h2 = __float22bfloat162_rn(make_float2(a, b));
    float2 hf = __bfloat1622float2(h2);
    __nv_bfloat162 l2 = __float22bfloat162_rn(make_float2(a - hf.x, b - hf.y));
    ph = *reinterpret_cast<const uint32_t*>(&h2);
    pl = *reinterpret_cast<const uint32_t*>(&l2);
}
__device__ __forceinline__ uint32_t pack_half2(float a, float b) {
    __half2 h2 = __float22half2_rn(make_float2(a, b));
    return *reinterpret_cast<const uint32_t*>(&h2);
}

// ---------------------------------------------------------------------------
// fp32 -> (hi, lo) bf16 split (single source)
// ---------------------------------------------------------------------------
__global__ __launch_bounds__(256) void split_bf16_kernel(
    const float* __restrict__ src, __nv_bfloat16* __restrict__ hi,
    __nv_bfloat16* __restrict__ lo, int n4)
{
    int i = blockIdx.x * blockDim.x + threadIdx.x;
    if (i >= n4) return;
    float4 v = reinterpret_cast<const float4*>(src)[i];
    __nv_bfloat162 h0 = __float22bfloat162_rn(make_float2(v.x, v.y));
    __nv_bfloat162 h1 = __float22bfloat162_rn(make_float2(v.z, v.w));
    float2 f0 = __bfloat1622float2(h0), f1 = __bfloat1622float2(h1);
    __nv_bfloat162 l0 = __float22bfloat162_rn(make_float2(v.x - f0.x, v.y - f0.y));
    __nv_bfloat162 l1 = __float22bfloat162_rn(make_float2(v.z - f1.x, v.w - f1.y));
    uint2 hv, lv;
    hv.x = *reinterpret_cast<uint32_t*>(&h0); hv.y = *reinterpret_cast<uint32_t*>(&h1);
    lv.x = *reinterpret_cast<uint32_t*>(&l0); lv.y = *reinterpret_cast<uint32_t*>(&l1);
    reinterpret_cast<uint2*>(hi)[i] = hv;
    reinterpret_cast<uint2*>(lo)[i] = lv;
}

// fp32 -> (hi,lo) for the 4 weight matrices in ONE launch
__global__ __launch_bounds__(256) void split_w4_kernel(
    const float* __restrict__ w0, const float* __restrict__ w1,
    const float* __restrict__ w2, const float* __restrict__ w3,
    __nv_bfloat16* __restrict__ hi, __nv_bfloat16* __restrict__ lo)
{
    const int nw4 = (int)(NW / 4);
    int i = blockIdx.x * blockDim.x + threadIdx.x;
    if (i >= 4 * nw4) return;
    const int mat = i / nw4;
    const int j   = i - mat * nw4;
    const float* src = (mat == 0) ? w0 : (mat == 1) ? w1 : (mat == 2) ? w2 : w3;
    float4 v = reinterpret_cast<const float4*>(src)[j];
    __nv_bfloat162 h0 = __float22bfloat162_rn(make_float2(v.x, v.y));
    __nv_bfloat162 h1 = __float22bfloat162_rn(make_float2(v.z, v.w));
    float2 f0 = __bfloat1622float2(h0), f1 = __bfloat1622float2(h1);
    __nv_bfloat162 l0 = __float22bfloat162_rn(make_float2(v.x - f0.x, v.y - f0.y));
    __nv_bfloat162 l1 = __float22bfloat162_rn(make_float2(v.z - f1.x, v.w - f1.y));
    uint2 hv, lv;
    hv.x = *reinterpret_cast<uint32_t*>(&h0); hv.y = *reinterpret_cast<uint32_t*>(&h1);
    lv.x = *reinterpret_cast<uint32_t*>(&l0); lv.y = *reinterpret_cast<uint32_t*>(&l1);
    reinterpret_cast<uint2*>(hi)[i] = hv;
    reinterpret_cast<uint2*>(lo)[i] = lv;
}

// ---------------------------------------------------------------------------
// bf16-split GEMM (NT), K = 1024. 128x128 CTA tile, BK=32, 3-stage ring,
// single barrier per k-step, 2 CTAs/SM. (R11/R12-proven)
// V output (mat==2) stored as fp16 (hi,lo); Q/K as bf16 (hi,lo).
// ---------------------------------------------------------------------------
static constexpr int TILE_B    = 128 * 128;
static constexpr int STAGE_B   = 2 * TILE_B;          // 32 KB
static constexpr int GSTAGES   = 3;
static constexpr int GEMM_SMEM = GSTAGES * STAGE_B;   // 98304

template <bool SPLIT_OUT>
__global__ __launch_bounds__(256, 2) void gemm_mma_split_kernel(
    const __nv_bfloat16* __restrict__ Ah, const __nv_bfloat16* __restrict__ Al,
    const __nv_bfloat16* __restrict__ Bh, const __nv_bfloat16* __restrict__ Bl,
    float* __restrict__ C, __nv_bfloat16* __restrict__ Ch,
    __nv_bfloat16* __restrict__ Cl)
{
    extern __shared__ char smem[];
    const uint32_t sbase = smem_u32(smem);
    constexpr int K   = DM;
    constexpr int NKT = K / 32;

    const int tid   = threadIdx.x;
    const int wid   = tid >> 5;
    const int lane  = tid & 31;
    const int warpm = wid >> 2;
    const int warpn = wid & 3;
    const int row0  = blockIdx.y * 128;
    const int col0  = blockIdx.x * 128;

    auto load_stage = [&](int s, int kt) {
        const uint32_t As = sbase + s * STAGE_B;
        const uint32_t Bs = As + TILE_B;
        const size_t kofs = (size_t)kt * 32;
        const __nv_bfloat16* Ah0 = Ah + (size_t)row0 * K + kofs;
        const __nv_bfloat16* Al0 = Al + (size_t)row0 * K + kofs;
        const __nv_bfloat16* Bh0 = Bh + (size_t)col0 * K + kofs;
        const __nv_bfloat16* Bl0 = Bl + (size_t)col0 * K + kofs;
        #pragma unroll
        for (int t = 0; t < 4; t++) {
            int v = t * 256 + tid;
            int r = v >> 3;
            int c = v & 7;
            uint32_t soff = sw128((uint32_t)(r * 128 + c * 16));
            cp_async16(As + soff, (c < 4 ? Ah0 : Al0) + (size_t)r * K + (c & 3) * 8);
            cp_async16(Bs + soff, (c < 4 ? Bh0 : Bl0) + (size_t)r * K + (c & 3) * 8);
        }
    };

    float acc[4][4][4];
    #pragma unroll
    for (int i = 0; i < 4; i++)
        #pragma unroll
        for (int j = 0; j < 4; j++)
            #pragma unroll
            for (int k = 0; k < 4; k++) acc[i][j][k] = 0.0f;

    load_stage(0, 0); CP_COMMIT();
    load_stage(1, 1); CP_COMMIT();

    for (int kt = 0; kt < NKT; kt++) {
        CP_WAIT(1);
        __syncthreads();

        const uint32_t As = sbase + (kt % 3) * STAGE_B;
        const uint32_t Bs = As + TILE_B;

        #pragma unroll
        for (int kc = 0; kc < 2; kc++) {
            const int jh = kc * 2;
            const int jl = 4 + kc * 2;

            uint32_t Ahf[4][4], Bhf[4][2];
            #pragma unroll
            for (int mt = 0; mt < 4; mt++) {
                int row = warpm * 64 + mt * 16 + (lane & 15);
                ldsm_x4(Ahf[mt], As + sw128((uint32_t)(row * 128 + (jh + (lane >> 4)) * 16)));
            }
            #pragma unroll
            for (int p = 0; p < 2; p++) {
                int row = warpn * 32 + p * 16 + ((lane >> 4) << 3) + (lane & 7);
                uint32_t t4[4];
                ldsm_x4(t4, Bs + sw128((uint32_t)(row * 128 + (jh + ((lane >> 3) & 1)) * 16)));
                Bhf[p * 2][0]     = t4[0]; Bhf[p * 2][1]     = t4[1];
                Bhf[p * 2 + 1][0] = t4[2]; Bhf[p * 2 + 1][1] = t4[3];
            }
            #pragma unroll
            for (int mt = 0; mt < 4; mt++)
                #pragma unroll
                for (int nt = 0; nt < 4; nt++)
                    mma_bf16(acc[mt][nt], Ahf[mt], Bhf[nt]);

            uint32_t Blf[4][2];
            #pragma unroll
            for (int p = 0; p < 2; p++) {
                int row = warpn * 32 + p * 16 + ((lane >> 4) << 3) + (lane & 7);
                uint32_t t4[4];
                ldsm_x4(t4, Bs + sw128((uint32_t)(row * 128 + (jl + ((lane >> 3) & 1)) * 16)));
                Blf[p * 2][0]     = t4[0]; Blf[p * 2][1]     = t4[1];
                Blf[p * 2 + 1][0] = t4[2]; Blf[p * 2 + 1][1] = t4[3];
            }
            #pragma unroll
            for (int mt = 0; mt < 4; mt++)
                #pragma unroll
                for (int nt = 0; nt < 4; nt++)
                    mma_bf16(acc[mt][nt], Ahf[mt], Blf[nt]);

            uint32_t Alf[4][4];
            #pragma unroll
            for (int mt = 0; mt < 4; mt++) {
                int row = warpm * 64 + mt * 16 + (lane & 15);
                ldsm_x4(Alf[mt], As + sw128((uint32_t)(row * 128 + (jl + (lane >> 4)) * 16)));
            }
            #pragma unroll
            for (int mt = 0; mt < 4; mt++)
                #pragma unroll
                for (int nt = 0; nt < 4; nt++)
                    mma_bf16(acc[mt][nt], Alf[mt], Bhf[nt]);
        }

        if (kt + 2 < NKT) load_stage((kt + 2) % 3, kt + 2);
        CP_COMMIT();
    }

    const int g = lane >> 2;
    const int t = lane & 3;
    if (SPLIT_OUT) {
        const int mat  = col0 >> 10;
        const int colb = col0 & 1023;
        const bool f16out = (mat == 2);      // V -> fp16 split
        __nv_bfloat16* ch = Ch + (size_t)mat * NX;
        __nv_bfloat16* cl = Cl + (size_t)mat * NX;
        #pragma unroll
        for (int mt = 0; mt < 4; mt++)
            #pragma unroll
            for (int nt = 0; nt < 4; nt++) {
                int row = row0 + warpm * 64 + mt * 16 + g;
                int col = colb + warpn * 32 + nt * 8 + t * 2;
                if (f16out) {
                    split_store_pair_f16(acc[mt][nt][0], acc[mt][nt][1],
                                         ch + (size_t)row * DM + col,
                                         cl + (size_t)row * DM + col);
                    split_store_pair_f16(acc[mt][nt][2], acc[mt][nt][3],
                                         ch + (size_t)(row + 8) * DM + col,
                                         cl + (size_t)(row + 8) * DM + col);
                } else {
                    split_store_pair(acc[mt][nt][0], acc[mt][nt][1],
                                     ch + (size_t)row * DM + col,
                                     cl + (size_t)row * DM + col);
                    split_store_pair(acc[mt][nt][2], acc[mt][nt][3],
                                     ch + (size_t)(row + 8) * DM + col,
                                     cl + (size_t)(row + 8) * DM + col);
                }
            }
    } else {
        #pragma unroll
        for (int mt = 0; mt < 4; mt++)
            #pragma unroll
            for (int nt = 0; nt < 4; nt++) {
                int row = row0 + warpm * 64 + mt * 16 + g;
                int col = col0 + warpn * 32 + nt * 8 + t * 2;
                float2 v0 = make_float2(acc[mt][nt][0], acc[mt][nt][1]);
                float2 v1 = make_float2(acc[mt][nt][2], acc[mt][nt][3]);
                *reinterpret_cast<float2*>(&C[(size_t)row * DM + col])       = v0;
                *reinterpret_cast<float2*>(&C[(size_t)(row + 8) * DM + col]) = v1;
            }
    }
}

// ---------------------------------------------------------------------------
// Tensor-core flash attention — pipelined S (R12) + fp16 2-term PV.
// BM=64, BN=64, 4 warps x 16 rows, 128 thr.
// K double-buffered (bf16), V triple-buffered (fp16) = 80KB -> 2 CTAs/SM.
// PV: O += P_fp16 @ (Vh + Vl)_fp16   (2 MMAs; error calibrated vs R9: ~2.9e-4)
// ---------------------------------------------------------------------------
static constexpr int ATTN_SMEM = 5 * 16384;           // 81920
static constexpr float SCALE_L2E = 0.125f * 1.4426950408889634f;

__global__ __launch_bounds__(128, 2) void flash_attn_mma_kernel(
    const __nv_bfloat16* __restrict__ qh, const __nv_bfloat16* __restrict__ ql,
    const __nv_bfloat16* __restrict__ kh, const __nv_bfloat16* __restrict__ kl,
    const __nv_bfloat16* __restrict__ vh, const __nv_bfloat16* __restrict__ vl,
    __nv_bfloat16* __restrict__ th, __nv_bfloat16* __restrict__ tl)
{
    extern __shared__ char smem[];
    const uint32_t sbase = smem_u32(smem);
    const uint32_t VBASE = sbase + 32768;          // vbuf[i] = VBASE + i*16384

    const int tid  = threadIdx.x;
    const int wid  = tid >> 5;        // 0..3
    const int lane = tid & 31;
    const int g    = lane >> 2;
    const int t    = lane & 3;

    const int qb = (SEQ / 64 - 1) - blockIdx.x;    // heavy blocks first
    const int bh = blockIdx.y;
    const int b  = bh >> 4;
    const int h  = bh & 15;
    const int q0 = qb * 64;
    const int bofs = b * SEQ;
    const int NT = qb + 1;                          // kv tiles of 64
    const int rowg = q0 + wid * 16 + g;

    // ---- stage Q through vbuf[2] (free until iter 0 loads tile 2) ----
    {
        const uint32_t qstage = VBASE + 2 * 16384;
        #pragma unroll
        for (int term = 0; term < 2; term++) {
            const __nv_bfloat16* src = term ? ql : qh;
            #pragma unroll
            for (int tt = 0; tt < 4; tt++) {
                int v = tt * 128 + tid;
                int r = v >> 3;
                int c = v & 7;
                cp_async16(qstage + term * 8192 + sw128((uint32_t)(r * 128 + c * 16)),
                           src + (size_t)(bofs + q0 + r) * DM + h * 64 + c * 8);
            }
        }
    }
    CP_COMMIT();
    CP_WAIT(0);
    __syncthreads();

    uint32_t qf[2][4][4];
    #pragma unroll
    for (int term = 0; term < 2; term++) {
        const uint32_t qbse = VBASE + 2 * 16384 + term * 8192;
        #pragma unroll
        for (int j = 0; j < 4; j++) {
            int row   = wid * 16 + (lane & 15);
            int chunk = j * 2 + (lane >> 4);
            ldsm_x4(qf[term][j], qbse + sw128((uint32_t)(row * 128 + chunk * 16)));
        }
    }
    __syncthreads();   // Q fragments extracted; vbuf[2] free

    // loader: K -> kbuf[t&1], V -> vbuf[t%3]
    auto load_kv = [&](int tile) {
        const int kv = tile * 64;
        const uint32_t kb = sbase + (tile & 1) * 16384;
        const uint32_t vb = VBASE + (tile % 3) * 16384;
        const __nv_bfloat16* bufs[4] = {kh, kl, vh, vl};
        const uint32_t dsts[4] = {kb, kb + 8192, vb, vb + 8192};
        #pragma unroll
        for (int buf = 0; buf < 4; buf++) {
            #pragma unroll
            for (int tt = 0; tt < 4; tt++) {
                int v = tt * 128 + tid;
                int r = v >> 3;
                int c = v & 7;
                cp_async16(dsts[buf] + sw128((uint32_t)(r * 128 + c * 16)),
                           bufs[buf] + (size_t)(bofs + kv + r) * DM + h * 64 + c * 8);
            }
        }
    };

    // S-MMA for one tile (bf16 3-term, unchanged)
    auto s_mma = [&](float (&sout)[8][4], uint32_t kb) {
        #pragma unroll
        for (int nt = 0; nt < 8; nt++)
            #pragma unroll
            for (int c = 0; c < 4; c++) sout[nt][c] = 0.0f;
        #pragma unroll
        for (int j = 0; j < 4; j++) {
            uint32_t kf[2][8][2];
            #pragma unroll
            for (int term = 0; term < 2; term++) {
                const uint32_t kbb = kb + term * 8192;
                #pragma unroll
                for (int np = 0; np < 4; np++) {
                    int row   = np * 16 + ((lane >> 4) << 3) + (lane & 7);
                    int chunk = j * 2 + ((lane >> 3) & 1);
                    uint32_t t4[4];
                    ldsm_x4(t4, kbb + sw128((uint32_t)(row * 128 + chunk * 16)));
                    kf[term][np * 2][0]     = t4[0];
                    kf[term][np * 2][1]     = t4[1];
                    kf[term][np * 2 + 1][0] = t4[2];
                    kf[term][np * 2 + 1][1] = t4[3];
                }
            }
            #pragma unroll
            for (int nt = 0; nt < 8; nt++) {
                mma_bf16(sout[nt], qf[0][j], kf[0][nt]);
                mma_bf16(sout[nt], qf[0][j], kf[1][nt]);
                mma_bf16(sout[nt], qf[1][j], kf[0][nt]);
            }
        }
    };

    load_kv(0); CP_COMMIT();
    load_kv(1); CP_COMMIT();
    CP_WAIT(1);
    __syncthreads();

    float m0 = -1e30f, m1 = -1e30f, l0 = 0.0f, l1 = 0.0f;
    float oacc[8][4];
    #pragma unroll
    for (int nt = 0; nt < 8; nt++)
        #pragma unroll
        for (int c = 0; c < 4; c++) oacc[nt][c] = 0.0f;

    float saccA[8][4], saccB[8][4];
    s_mma(saccA, sbase);               // S(0) from kbuf[0]

    auto body = [&](float (&cur)[8][4], float (&next)[8][4], int kt) {
        CP_WAIT(0);
        __syncthreads();

        if (kt + 2 < NT) load_kv(kt + 2);
        CP_COMMIT();

        if (kt + 1 < NT) s_mma(next, sbase + ((kt + 1) & 1) * 16384);

        const int kv0 = kt * 64;
        const bool lastt = (kt == NT - 1);
        #pragma unroll
        for (int nt = 0; nt < 8; nt++) {
            #pragma unroll
            for (int c = 0; c < 4; c++) {
                float s = cur[nt][c] * SCALE_L2E;
                if (lastt) {
                    int col = kv0 + nt * 8 + t * 2 + (c & 1);
                    int row = (c < 2) ? rowg : rowg + 8;
                    if (col > row) s = -1e30f;
                }
                cur[nt][c] = s;
            }
        }

        float mx0 = -1e30f, mx1 = -1e30f;
        #pragma unroll
        for (int nt = 0; nt < 8; nt++) {
            mx0 = fmaxf(mx0, fmaxf(cur[nt][0], cur[nt][1]));
            mx1 = fmaxf(mx1, fmaxf(cur[nt][2], cur[nt][3]));
        }
        mx0 = fmaxf(mx0, __shfl_xor_sync(0xffffffffu, mx0, 1));
        mx0 = fmaxf(mx0, __shfl_xor_sync(0xffffffffu, mx0, 2));
        mx1 = fmaxf(mx1, __shfl_xor_sync(0xffffffffu, mx1, 1));
        mx1 = fmaxf(mx1, __shfl_xor_sync(0xffffffffu, mx1, 2));
        float mnew0 = fmaxf(m0, mx0), mnew1 = fmaxf(m1, mx1);
        float a0 = exp2f(m0 - mnew0), a1 = exp2f(m1 - mnew1);
        m0 = mnew0; m1 = mnew1;

        float rs0 = 0.0f, rs1 = 0.0f;
        #pragma unroll
        for (int nt = 0; nt < 8; nt++) {
            float p0 = exp2f(cur[nt][0] - mnew0);
            float p1 = exp2f(cur[nt][1] - mnew0);
            float p2 = exp2f(cur[nt][2] - mnew1);
            float p3 = exp2f(cur[nt][3] - mnew1);
            cur[nt][0] = p0; cur[nt][1] = p1;
            cur[nt][2] = p2; cur[nt][3] = p3;
            rs0 += p0 + p1; rs1 += p2 + p3;
        }
        rs0 += __shfl_xor_sync(0xffffffffu, rs0, 1);
        rs0 += __shfl_xor_sync(0xffffffffu, rs0, 2);
        rs1 += __shfl_xor_sync(0xffffffffu, rs1, 1);
        rs1 += __shfl_xor_sync(0xffffffffu, rs1, 2);
        l0 = l0 * a0 + rs0;
        l1 = l1 * a1 + rs1;
        #pragma unroll
        for (int nt = 0; nt < 8; nt++) {
            oacc[nt][0] *= a0; oacc[nt][1] *= a0;
            oacc[nt][2] *= a1; oacc[nt][3] *= a1;
        }

        // ---- PV: O += P_fp16 @ (Vh + Vl)_fp16  (2 MMAs per n-tile) ----
        const uint32_t vb = VBASE + (kt % 3) * 16384;
        #pragma unroll
        for (int pj = 0; pj < 4; pj++) {
            const float* se = cur[2 * pj];
            const float* so = cur[2 * pj + 1];
            uint32_t pf[4];
            pf[0] = pack_half2(se[0], se[1]);
            pf[1] = pack_half2(se[2], se[3]);
            pf[2] = pack_half2(so[0], so[1]);
            pf[3] = pack_half2(so[2], so[3]);

            uint32_t vf[2][8][2];
            #pragma unroll
            for (int term = 0; term < 2; term++) {
                const uint32_t vbb = vb + term * 8192;
                #pragma unroll
                for (int np = 0; np < 4; np++) {
                    int kvrow = pj * 16 + (lane & 15);
                    int dby   = np * 32 + ((lane >> 4) * 16);
                    uint32_t t4[4];
                    ldsm_x4_t(t4, vbb + sw128((uint32_t)(kvrow * 128 + dby)));
                    vf[term][np * 2][0]     = t4[0];
                    vf[term][np * 2][1]     = t4[1];
                    vf[term][np * 2 + 1][0] = t4[2];
                    vf[term][np * 2 + 1][1] = t4[3];
                }
            }
            #pragma unroll
            for (int nt = 0; nt < 8; nt++) {
                mma_f16(oacc[nt], pf, vf[0][nt]);
                mma_f16(oacc[nt], pf, vf[1][nt]);
            }
        }
    };

    for (int kt = 0; kt < NT; kt += 2) {
        body(saccA, saccB, kt);
        if (kt + 1 < NT) body(saccB, saccA, kt + 1);
    }

    // ---- epilogue: normalize + split-write T (bf16 pair, unchanged) ----
    const float inv0 = 1.0f / l0, inv1 = 1.0f / l1;
    const size_t rb0 = (size_t)(bofs + rowg) * DM + h * 64;
    const size_t rb1 = rb0 + (size_t)8 * DM;
    #pragma unroll
    for (int nt = 0; nt < 8; nt++) {
        int col = nt * 8 + t * 2;
        split_store_pair(oacc[nt][0] * inv0, oacc[nt][1] * inv0,
                         th + rb0 + col, tl + rb0 + col);
        split_store_pair(oacc[nt][2] * inv1, oacc[nt][3] * inv1,
                         th + rb1 + col, tl + rb1 + col);
    }
}

// ---------------------------------------------------------------------------
// Launcher — attention at launch index 3 (the one ncu captures)
// ---------------------------------------------------------------------------
extern "C" void kernel_launch(void* const* d_in, const int* in_sizes, int n_in,
                              void* d_out, int out_size)
{
    const float* x   = (const float*)d_in[0];
    const float* W_q = (const float*)d_in[1];
    const float* W_k = (const float*)d_in[2];
    const float* W_v = (const float*)d_in[3];
    const float* W_o = (const float*)d_in[4];
    float* out = (float*)d_out;

    __nv_bfloat16 *xh, *xl, *Wh, *Wl, *qkvh, *qkvl, *th, *tl;
    cudaGetSymbolAddress((void**)&xh, g_xh);
    cudaGetSymbolAddress((void**)&xl, g_xl);
    cudaGetSymbolAddress((void**)&Wh, g_Wh);
    cudaGetSymbolAddress((void**)&Wl, g_Wl);
    cudaGetSymbolAddress((void**)&qkvh, g_qkvh);
    cudaGetSymbolAddress((void**)&qkvl, g_qkvl);
    cudaGetSymbolAddress((void**)&th, g_th);
    cudaGetSymbolAddress((void**)&tl, g_tl);

    cudaFuncSetAttribute(gemm_mma_split_kernel<true>,
                         cudaFuncAttributeMaxDynamicSharedMemorySize, GEMM_SMEM);
    cudaFuncSetAttribute(gemm_mma_split_kernel<false>,
                         cudaFuncAttributeMaxDynamicSharedMemorySize, GEMM_SMEM);
    cudaFuncSetAttribute(flash_attn_mma_kernel,
                         cudaFuncAttributeMaxDynamicSharedMemorySize, ATTN_SMEM);

    const int nx4 = (int)(NX / 4);
    const int nw4all = (int)(NW);          // 4 * (NW/4)

    // launch 0: x split
    split_bf16_kernel<<<(nx4 + 255) / 256, 256>>>(x, xh, xl, nx4);
    // launch 1: all 4 weight splits fused
    split_w4_kernel<<<(nw4all + 255) / 256, 256>>>(W_q, W_k, W_v, W_o, Wh, Wl);

    // launch 2: fused QKV GEMM (V epilogue writes fp16 pair)
    dim3 qkv_grid(3 * DM / 128, ROWS / 128);   // (24, 64)
    gemm_mma_split_kernel<true><<<qkv_grid, 256, GEMM_SMEM>>>(
        xh, xl, Wh, Wl, nullptr, qkvh, qkvl);

    // launch 3: attention  (<-- profiled launch)
    dim3 attn_grid(SEQ / 64, BATCH * NH);      // (32, 64)
    flash_attn_mma_kernel<<<attn_grid, 128, ATTN_SMEM>>>(
        qkvh, qkvl, qkvh + NX, qkvl + NX, qkvh + 2 * NX, qkvl + 2 * NX, th, tl);

    // launch 4: output projection
    dim3 o_grid(DM / 128, ROWS / 128);         // (8, 64)
    gemm_mma_split_kernel<false><<<o_grid, 256, GEMM_SMEM>>>(
        th, tl, Wh + 3 * NW, Wl + 3 * NW, out, nullptr, nullptr);
}

// round 14
// speedup vs baseline: 1.5491x; 1.3587x over previous
#include <cuda_runtime.h>
#include <cuda_bf16.h>
#include <cuda_fp16.h>
#include <cstdint>

// Problem constants
static constexpr int BATCH = 4;
static constexpr int SEQ   = 2048;
static constexpr int DM    = 1024;
static constexpr int NH    = 16;
static constexpr int DH    = 64;
static constexpr int ROWS  = BATCH * SEQ;        // 8192
static constexpr size_t NX = (size_t)ROWS * DM;  // 8388608
static constexpr size_t NW = (size_t)DM * DM;    // 1048576

// Scratch (device globals: allocation-free) — all fp16 now
__device__ __half g_xh[NX];
__device__ __half g_xl[NX];
__device__ __half g_Wh[4 * NW];       // Wq|Wk|Wv|Wo, hi only (single-fp16 B)
__device__ __half g_qkvh[3 * NX];     // Q|K|V hi
__device__ __half g_qkvl[3 * NX];     // Q|K|V lo (K lo unused)
__device__ __half g_th[NX];
__device__ __half g_tl[NX];

// ---------------------------------------------------------------------------
// Helpers
// ---------------------------------------------------------------------------
__device__ __forceinline__ uint32_t smem_u32(const void* p) {
    uint32_t a;
    asm("{ .reg .u64 t; cvta.to.shared.u64 t, %1; cvt.u32.u64 %0, t; }"
        : "=r"(a) : "l"(p));
    return a;
}
__device__ __forceinline__ uint32_t sw128(uint32_t off) {
    return off ^ ((off >> 3) & 0x70);
}
__device__ __forceinline__ void cp_async16(uint32_t saddr, const void* gaddr) {
    asm volatile("cp.async.cg.shared.global [%0], [%1], 16;"
                 :: "r"(saddr), "l"(gaddr));
}
#define CP_COMMIT() asm volatile("cp.async.commit_group;")
#define CP_WAIT(n)  asm volatile("cp.async.wait_group %0;" :: "n"(n))

__device__ __forceinline__ void ldsm_x4(uint32_t (&r)[4], uint32_t addr) {
    asm volatile("ldmatrix.sync.aligned.m8n8.x4.shared.b16 {%0,%1,%2,%3}, [%4];"
                 : "=r"(r[0]), "=r"(r[1]), "=r"(r[2]), "=r"(r[3]) : "r"(addr));
}
__device__ __forceinline__ void ldsm_x4_t(uint32_t (&r)[4], uint32_t addr) {
    asm volatile("ldmatrix.sync.aligned.m8n8.x4.trans.shared.b16 {%0,%1,%2,%3}, [%4];"
                 : "=r"(r[0]), "=r"(r[1]), "=r"(r[2]), "=r"(r[3]) : "r"(addr));
}
__device__ __forceinline__ void mma_f16(float (&d)[4], const uint32_t (&a)[4],
                                        const uint32_t* b) {
    asm volatile(
        "mma.sync.aligned.m16n8k16.row.col.f32.f16.f16.f32 "
        "{%0,%1,%2,%3}, {%4,%5,%6,%7}, {%8,%9}, {%0,%1,%2,%3};"
        : "+f"(d[0]), "+f"(d[1]), "+f"(d[2]), "+f"(d[3])
        : "r"(a[0]), "r"(a[1]), "r"(a[2]), "r"(a[3]), "r"(b[0]), "r"(b[1]));
}

__device__ __forceinline__ void split_store_pair_f16(float a, float b,
                                                     __half* hp, __half* lp) {
    __half2 h2 = __float22half2_rn(make_float2(a, b));
    float2 hf = __half22float2(h2);
    __half2 l2 = __float22half2_rn(make_float2(a - hf.x, b - hf.y));
    *reinterpret_cast<uint32_t*>(hp) = *reinterpret_cast<const uint32_t*>(&h2);
    *reinterpret_cast<uint32_t*>(lp) = *reinterpret_cast<const uint32_t*>(&l2);
}
__device__ __forceinline__ uint32_t pack_half2(float a, float b) {
    __half2 h2 = __float22half2_rn(make_float2(a, b));
    return *reinterpret_cast<const uint32_t*>(&h2);
}

// ---------------------------------------------------------------------------
// fp32 -> (hi, lo) fp16 split (x and generic)
// ---------------------------------------------------------------------------
__global__ __launch_bounds__(256) void split_f16_kernel(
    const float* __restrict__ src, __half* __restrict__ hi,
    __half* __restrict__ lo, int n4)
{
    int i = blockIdx.x * blockDim.x + threadIdx.x;
    if (i >= n4) return;
    float4 v = reinterpret_cast<const float4*>(src)[i];
    __half2 h0 = __float22half2_rn(make_float2(v.x, v.y));
    __half2 h1 = __float22half2_rn(make_float2(v.z, v.w));
    float2 f0 = __half22float2(h0), f1 = __half22float2(h1);
    __half2 l0 = __float22half2_rn(make_float2(v.x - f0.x, v.y - f0.y));
    __half2 l1 = __float22half2_rn(make_float2(v.z - f1.x, v.w - f1.y));
    uint2 hv, lv;
    hv.x = *reinterpret_cast<uint32_t*>(&h0); hv.y = *reinterpret_cast<uint32_t*>(&h1);
    lv.x = *reinterpret_cast<uint32_t*>(&l0); lv.y = *reinterpret_cast<uint32_t*>(&l1);
    reinterpret_cast<uint2*>(hi)[i] = hv;
    reinterpret_cast<uint2*>(lo)[i] = lv;
}

// fp32 -> fp16 hi only, 4 weight matrices in ONE launch
__global__ __launch_bounds__(256) void split_w4_kernel(
    const float* __restrict__ w0, const float* __restrict__ w1,
    const float* __restrict__ w2, const float* __restrict__ w3,
    __half* __restrict__ hi)
{
    const int nw4 = (int)(NW / 4);
    int i = blockIdx.x * blockDim.x + threadIdx.x;
    if (i >= 4 * nw4) return;
    const int mat = i / nw4;
    const int j   = i - mat * nw4;
    const float* src = (mat == 0) ? w0 : (mat == 1) ? w1 : (mat == 2) ? w2 : w3;
    float4 v = reinterpret_cast<const float4*>(src)[j];
    __half2 h0 = __float22half2_rn(make_float2(v.x, v.y));
    __half2 h1 = __float22half2_rn(make_float2(v.z, v.w));
    uint2 hv;
    hv.x = *reinterpret_cast<uint32_t*>(&h0); hv.y = *reinterpret_cast<uint32_t*>(&h1);
    reinterpret_cast<uint2*>(hi)[i] = hv;
}

// ---------------------------------------------------------------------------
// fp16 GEMM (NT), K = 1024: C = (Ah+Al) @ Bh^T — 2 MMAs per k-chunk.
// 128x128 CTA tile, BK=32, 3-stage ring, single barrier, 2 CTAs/SM.
// B tile: hi only (chunks 0-3 of each 128B row; 4-7 unused).
// ---------------------------------------------------------------------------
static constexpr int TILE_B    = 128 * 128;
static constexpr int STAGE_B   = 2 * TILE_B;          // 32 KB (A 16K + B 16K)
static constexpr int GSTAGES   = 3;
static constexpr int GEMM_SMEM = GSTAGES * STAGE_B;   // 98304

template <bool SPLIT_OUT>
__global__ __launch_bounds__(256, 2) void gemm_f16_kernel(
    const __half* __restrict__ Ah, const __half* __restrict__ Al,
    const __half* __restrict__ Bh,
    float* __restrict__ C, __half* __restrict__ Ch, __half* __restrict__ Cl)
{
    extern __shared__ char smem[];
    const uint32_t sbase = smem_u32(smem);
    constexpr int K   = DM;
    constexpr int NKT = K / 32;

    const int tid   = threadIdx.x;
    const int wid   = tid >> 5;
    const int lane  = tid & 31;
    const int warpm = wid >> 2;
    const int warpn = wid & 3;
    const int row0  = blockIdx.y * 128;
    const int col0  = blockIdx.x * 128;

    auto load_stage = [&](int s, int kt) {
        const uint32_t As = sbase + s * STAGE_B;
        const uint32_t Bs = As + TILE_B;
        const size_t kofs = (size_t)kt * 32;
        const __half* Ah0 = Ah + (size_t)row0 * K + kofs;
        const __half* Al0 = Al + (size_t)row0 * K + kofs;
        const __half* Bh0 = Bh + (size_t)col0 * K + kofs;
        #pragma unroll
        for (int t = 0; t < 4; t++) {        // A: 128 rows x 8 chunks (hi|lo)
            int v = t * 256 + tid;
            int r = v >> 3;
            int c = v & 7;
            uint32_t soff = sw128((uint32_t)(r * 128 + c * 16));
            cp_async16(As + soff, (c < 4 ? Ah0 : Al0) + (size_t)r * K + (c & 3) * 8);
        }
        #pragma unroll
        for (int t = 0; t < 2; t++) {        // B: 128 rows x 4 chunks (hi only)
            int v = t * 256 + tid;
            int r = v >> 2;
            int c = v & 3;
            uint32_t soff = sw128((uint32_t)(r * 128 + c * 16));
            cp_async16(Bs + soff, Bh0 + (size_t)r * K + c * 8);
        }
    };

    float acc[4][4][4];
    #pragma unroll
    for (int i = 0; i < 4; i++)
        #pragma unroll
        for (int j = 0; j < 4; j++)
            #pragma unroll
            for (int k = 0; k < 4; k++) acc[i][j][k] = 0.0f;

    load_stage(0, 0); CP_COMMIT();
    load_stage(1, 1); CP_COMMIT();

    for (int kt = 0; kt < NKT; kt++) {
        CP_WAIT(1);
        __syncthreads();

        const uint32_t As = sbase + (kt % 3) * STAGE_B;
        const uint32_t Bs = As + TILE_B;

        #pragma unroll
        for (int kc = 0; kc < 2; kc++) {
            const int jh = kc * 2;           // A/B hi chunks
            const int jl = 4 + kc * 2;       // A lo chunks

            uint32_t Ahf[4][4], Bhf[4][2];
            #pragma unroll
            for (int mt = 0; mt < 4; mt++) {
                int row = warpm * 64 + mt * 16 + (lane & 15);
                ldsm_x4(Ahf[mt], As + sw128((uint32_t)(row * 128 + (jh + (lane >> 4)) * 16)));
            }
            #pragma unroll
            for (int p = 0; p < 2; p++) {
                int row = warpn * 32 + p * 16 + ((lane >> 4) << 3) + (lane & 7);
                uint32_t t4[4];
                ldsm_x4(t4, Bs + sw128((uint32_t)(row * 128 + (jh + ((lane >> 3) & 1)) * 16)));
                Bhf[p * 2][0]     = t4[0]; Bhf[p * 2][1]     = t4[1];
                Bhf[p * 2 + 1][0] = t4[2]; Bhf[p * 2 + 1][1] = t4[3];
            }
            #pragma unroll
            for (int mt = 0; mt < 4; mt++)
                #pragma unroll
                for (int nt = 0; nt < 4; nt++)
                    mma_f16(acc[mt][nt], Ahf[mt], Bhf[nt]);

            uint32_t Alf[4][4];
            #pragma unroll
            for (int mt = 0; mt < 4; mt++) {
                int row = warpm * 64 + mt * 16 + (lane & 15);
                ldsm_x4(Alf[mt], As + sw128((uint32_t)(row * 128 + (jl + (lane >> 4)) * 16)));
            }
            #pragma unroll
            for (int mt = 0; mt < 4; mt++)
                #pragma unroll
                for (int nt = 0; nt < 4; nt++)
                    mma_f16(acc[mt][nt], Alf[mt], Bhf[nt]);
        }

        if (kt + 2 < NKT) load_stage((kt + 2) % 3, kt + 2);
        CP_COMMIT();
    }

    const int g = lane >> 2;
    const int t = lane & 3;
    if (SPLIT_OUT) {
        const int mat  = col0 >> 10;
        const int colb = col0 & 1023;
        __half* ch = Ch + (size_t)mat * NX;
        __half* cl = Cl + (size_t)mat * NX;
        #pragma unroll
        for (int mt = 0; mt < 4; mt++)
            #pragma unroll
            for (int nt = 0; nt < 4; nt++) {
                int row = row0 + warpm * 64 + mt * 16 + g;
                int col = colb + warpn * 32 + nt * 8 + t * 2;
                split_store_pair_f16(acc[mt][nt][0], acc[mt][nt][1],
                                     ch + (size_t)row * DM + col,
                                     cl + (size_t)row * DM + col);
                split_store_pair_f16(acc[mt][nt][2], acc[mt][nt][3],
                                     ch + (size_t)(row + 8) * DM + col,
                                     cl + (size_t)(row + 8) * DM + col);
            }
    } else {
        #pragma unroll
        for (int mt = 0; mt < 4; mt++)
            #pragma unroll
            for (int nt = 0; nt < 4; nt++) {
                int row = row0 + warpm * 64 + mt * 16 + g;
                int col = col0 + warpn * 32 + nt * 8 + t * 2;
                float2 v0 = make_float2(acc[mt][nt][0], acc[mt][nt][1]);
                float2 v1 = make_float2(acc[mt][nt][2], acc[mt][nt][3]);
                *reinterpret_cast<float2*>(&C[(size_t)row * DM + col])       = v0;
                *reinterpret_cast<float2*>(&C[(size_t)(row + 8) * DM + col]) = v1;
            }
    }
}

// ---------------------------------------------------------------------------
// Flash attention — pipelined S, all fp16:
// S = (Qh+Ql) @ Kh^T (2 MMAs), PV = P @ (Vh+Vl) (2 MMAs).
// kbuf[2] 8KB (K hi only), vbuf[3] 16KB -> SMEM 64KB, 2 CTAs/SM.
// ---------------------------------------------------------------------------
static constexpr int ATTN_SMEM = 2 * 8192 + 3 * 16384;   // 65536
static constexpr float SCALE_L2E = 0.125f * 1.4426950408889634f;

__global__ __launch_bounds__(128, 2) void flash_attn_mma_kernel(
    const __half* __restrict__ qh, const __half* __restrict__ ql,
    const __half* __restrict__ kh,
    const __half* __restrict__ vh, const __half* __restrict__ vl,
    __half* __restrict__ th, __half* __restrict__ tl)
{
    extern __shared__ char smem[];
    const uint32_t sbase = smem_u32(smem);
    const uint32_t VBASE = sbase + 16384;          // vbuf[i] = VBASE + i*16384

    const int tid  = threadIdx.x;
    const int wid  = tid >> 5;        // 0..3
    const int lane = tid & 31;
    const int g    = lane >> 2;
    const int t    = lane & 3;

    const int qb = (SEQ / 64 - 1) - blockIdx.x;    // heavy blocks first
    const int bh = blockIdx.y;
    const int b  = bh >> 4;
    const int h  = bh & 15;
    const int q0 = qb * 64;
    const int bofs = b * SEQ;
    const int NT = qb + 1;                          // kv tiles of 64
    const int rowg = q0 + wid * 16 + g;

    // ---- stage Q (fp16 pair) through vbuf[2] ----
    {
        const uint32_t qstage = VBASE + 2 * 16384;
        #pragma unroll
        for (int term = 0; term < 2; term++) {
            const __half* src = term ? ql : qh;
            #pragma unroll
            for (int tt = 0; tt < 4; tt++) {
                int v = tt * 128 + tid;
                int r = v >> 3;
                int c = v & 7;
                cp_async16(qstage + term * 8192 + sw128((uint32_t)(r * 128 + c * 16)),
                           src + (size_t)(bofs + q0 + r) * DM + h * 64 + c * 8);
            }
        }
    }
    CP_COMMIT();
    CP_WAIT(0);
    __syncthreads();

    uint32_t qf[2][4][4];
    #pragma unroll
    for (int term = 0; term < 2; term++) {
        const uint32_t qbse = VBASE + 2 * 16384 + term * 8192;
        #pragma unroll
        for (int j = 0; j < 4; j++) {
            int row   = wid * 16 + (lane & 15);
            int chunk = j * 2 + (lane >> 4);
            ldsm_x4(qf[term][j], qbse + sw128((uint32_t)(row * 128 + chunk * 16)));
        }
    }
    __syncthreads();   // Q fragments extracted; vbuf[2] free

    // loader: K hi -> kbuf[t&1] (8KB), V pair -> vbuf[t%3] (16KB)
    auto load_kv = [&](int tile) {
        const int kv = tile * 64;
        const uint32_t kb = sbase + (tile & 1) * 8192;
        const uint32_t vb = VBASE + (tile % 3) * 16384;
        #pragma unroll
        for (int tt = 0; tt < 4; tt++) {       // K hi: 64 rows x 8 chunks
            int v = tt * 128 + tid;
            int r = v >> 3;
            int c = v & 7;
            cp_async16(kb + sw128((uint32_t)(r * 128 + c * 16)),
                       kh + (size_t)(bofs + kv + r) * DM + h * 64 + c * 8);
        }
        const __half* vbufs[2] = {vh, vl};
        #pragma unroll
        for (int buf = 0; buf < 2; buf++) {
            #pragma unroll
            for (int tt = 0; tt < 4; tt++) {
                int v = tt * 128 + tid;
                int r = v >> 3;
                int c = v & 7;
                cp_async16(vb + buf * 8192 + sw128((uint32_t)(r * 128 + c * 16)),
                           vbufs[buf] + (size_t)(bofs + kv + r) * DM + h * 64 + c * 8);
            }
        }
    };

    // S-MMA for one tile: sout = (Qh+Ql) @ Kh^T  (2 MMAs per n-tile)
    auto s_mma = [&](float (&sout)[8][4], uint32_t kb) {
        #pragma unroll
        for (int nt = 0; nt < 8; nt++)
            #pragma unroll
            for (int c = 0; c < 4; c++) sout[nt][c] = 0.0f;
        #pragma unroll
        for (int j = 0; j < 4; j++) {
            uint32_t kf[8][2];
            #pragma unroll
            for (int np = 0; np < 4; np++) {
                int row   = np * 16 + ((lane >> 4) << 3) + (lane & 7);
                int chunk = j * 2 + ((lane >> 3) & 1);
                uint32_t t4[4];
                ldsm_x4(t4, kb + sw128((uint32_t)(row * 128 + chunk * 16)));
                kf[np * 2][0]     = t4[0];
                kf[np * 2][1]     = t4[1];
                kf[np * 2 + 1][0] = t4[2];
                kf[np * 2 + 1][1] = t4[3];
            }
            #pragma unroll
            for (int nt = 0; nt < 8; nt++) {
                mma_f16(sout[nt], qf[0][j], kf[nt]);
                mma_f16(sout[nt], qf[1][j], kf[nt]);
            }
        }
    };

    load_kv(0); CP_COMMIT();
    load_kv(1); CP_COMMIT();
    CP_WAIT(1);
    __syncthreads();

    float m0 = -1e30f, m1 = -1e30f, l0 = 0.0f, l1 = 0.0f;
    float oacc[8][4];
    #pragma unroll
    for (int nt = 0; nt < 8; nt++)
        #pragma unroll
        for (int c = 0; c < 4; c++) oacc[nt][c] = 0.0f;

    float saccA[8][4], saccB[8][4];
    s_mma(saccA, sbase);               // S(0) from kbuf[0]

    auto body = [&](float (&cur)[8][4], float (&next)[8][4], int kt) {
        CP_WAIT(0);
        __syncthreads();

        if (kt + 2 < NT) load_kv(kt + 2);
        CP_COMMIT();

        if (kt + 1 < NT) s_mma(next, sbase + ((kt + 1) & 1) * 8192);

        const int kv0 = kt * 64;
        const bool lastt = (kt == NT - 1);
        #pragma unroll
        for (int nt = 0; nt < 8; nt++) {
            #pragma unroll
            for (int c = 0; c < 4; c++) {
                float s = cur[nt][c] * SCALE_L2E;
                if (lastt) {
                    int col = kv0 + nt * 8 + t * 2 + (c & 1);
                    int row = (c < 2) ? rowg : rowg + 8;
                    if (col > row) s = -1e30f;
                }
                cur[nt][c] = s;
            }
        }

        float mx0 = -1e30f, mx1 = -1e30f;
        #pragma unroll
        for (int nt = 0; nt < 8; nt++) {
            mx0 = fmaxf(mx0, fmaxf(cur[nt][0], cur[nt][1]));
            mx1 = fmaxf(mx1, fmaxf(cur[nt][2], cur[nt][3]));
        }
        mx0 = fmaxf(mx0, __shfl_xor_sync(0xffffffffu, mx0, 1));
        mx0 = fmaxf(mx0, __shfl_xor_sync(0xffffffffu, mx0, 2));
        mx1 = fmaxf(mx1, __shfl_xor_sync(0xffffffffu, mx1, 1));
        mx1 = fmaxf(mx1, __shfl_xor_sync(0xffffffffu, mx1, 2));
        float mnew0 = fmaxf(m0, mx0), mnew1 = fmaxf(m1, mx1);
        float a0 = exp2f(m0 - mnew0), a1 = exp2f(m1 - mnew1);
        m0 = mnew0; m1 = mnew1;

        float rs0 = 0.0f, rs1 = 0.0f;
        #pragma unroll
        for (int nt = 0; nt < 8; nt++) {
            float p0 = exp2f(cur[nt][0] - mnew0);
            float p1 = exp2f(cur[nt][1] - mnew0);
            float p2 = exp2f(cur[nt][2] - mnew1);
            float p3 = exp2f(cur[nt][3] - mnew1);
            cur[nt][0] = p0; cur[nt][1] = p1;
            cur[nt][2] = p2; cur[nt][3] = p3;
            rs0 += p0 + p1; rs1 += p2 + p3;
        }
        rs0 += __shfl_xor_sync(0xffffffffu, rs0, 1);
        rs0 += __shfl_xor_sync(0xffffffffu, rs0, 2);
        rs1 += __shfl_xor_sync(0xffffffffu, rs1, 1);
        rs1 += __shfl_xor_sync(0xffffffffu, rs1, 2);
        l0 = l0 * a0 + rs0;
        l1 = l1 * a1 + rs1;
        #pragma unroll
        for (int nt = 0; nt < 8; nt++) {
            oacc[nt][0] *= a0; oacc[nt][1] *= a0;
            oacc[nt][2] *= a1; oacc[nt][3] *= a1;
        }

        // ---- PV: O += P_fp16 @ (Vh + Vl)_fp16 ----
        const uint32_t vb = VBASE + (kt % 3) * 16384;
        #pragma unroll
        for (int pj = 0; pj < 4; pj++) {
            const float* se = cur[2 * pj];
            const float* so = cur[2 * pj + 1];
            uint32_t pf[4];
            pf[0] = pack_half2(se[0], se[1]);
            pf[1] = pack_half2(se[2], se[3]);
            pf[2] = pack_half2(so[0], so[1]);
            pf[3] = pack_half2(so[2], so[3]);

            uint32_t vf[2][8][2];
            #pragma unroll
            for (int term = 0; term < 2; term++) {
                const uint32_t vbb = vb + term * 8192;
                #pragma unroll
                for (int np = 0; np < 4; np++) {
                    int kvrow = pj * 16 + (lane & 15);
                    int dby   = np * 32 + ((lane >> 4) * 16);
                    uint32_t t4[4];
                    ldsm_x4_t(t4, vbb + sw128((uint32_t)(kvrow * 128 + dby)));
                    vf[term][np * 2][0]     = t4[0];
                    vf[term][np * 2][1]     = t4[1];
                    vf[term][np * 2 + 1][0] = t4[2];
                    vf[term][np * 2 + 1][1] = t4[3];
                }
            }
            #pragma unroll
            for (int nt = 0; nt < 8; nt++) {
                mma_f16(oacc[nt], pf, vf[0][nt]);
                mma_f16(oacc[nt], pf, vf[1][nt]);
            }
        }
    };

    for (int kt = 0; kt < NT; kt += 2) {
        body(saccA, saccB, kt);
        if (kt + 1 < NT) body(saccB, saccA, kt + 1);
    }

    // ---- epilogue: normalize + fp16 split-write T ----
    const float inv0 = 1.0f / l0, inv1 = 1.0f / l1;
    const size_t rb0 = (size_t)(bofs + rowg) * DM + h * 64;
    const size_t rb1 = rb0 + (size_t)8 * DM;
    #pragma unroll
    for (int nt = 0; nt < 8; nt++) {
        int col = nt * 8 + t * 2;
        split_store_pair_f16(oacc[nt][0] * inv0, oacc[nt][1] * inv0,
                             th + rb0 + col, tl + rb0 + col);
        split_store_pair_f16(oacc[nt][2] * inv1, oacc[nt][3] * inv1,
                             th + rb1 + col, tl + rb1 + col);
    }
}

// ---------------------------------------------------------------------------
// Launcher — attention at launch index 3 (the one ncu captures)
// ---------------------------------------------------------------------------
extern "C" void kernel_launch(void* const* d_in, const int* in_sizes, int n_in,
                              void* d_out, int out_size)
{
    const float* x   = (const float*)d_in[0];
    const float* W_q = (const float*)d_in[1];
    const float* W_k = (const float*)d_in[2];
    const float* W_v = (const float*)d_in[3];
    const float* W_o = (const float*)d_in[4];
    float* out = (float*)d_out;

    __half *xh, *xl, *Wh, *qkvh, *qkvl, *th, *tl;
    cudaGetSymbolAddress((void**)&xh, g_xh);
    cudaGetSymbolAddress((void**)&xl, g_xl);
    cudaGetSymbolAddress((void**)&Wh, g_Wh);
    cudaGetSymbolAddress((void**)&qkvh, g_qkvh);
    cudaGetSymbolAddress((void**)&qkvl, g_qkvl);
    cudaGetSymbolAddress((void**)&th, g_th);
    cudaGetSymbolAddress((void**)&tl, g_tl);

    cudaFuncSetAttribute(gemm_f16_kernel<true>,
                         cudaFuncAttributeMaxDynamicSharedMemorySize, GEMM_SMEM);
    cudaFuncSetAttribute(gemm_f16_kernel<false>,
                         cudaFuncAttributeMaxDynamicSharedMemorySize, GEMM_SMEM);
    cudaFuncSetAttribute(flash_attn_mma_kernel,
                         cudaFuncAttributeMaxDynamicSharedMemorySize, ATTN_SMEM);

    const int nx4 = (int)(NX / 4);
    const int nw4all = (int)(NW);          // 4 * (NW/4)

    // launch 0: x split (fp16 pair)
    split_f16_kernel<<<(nx4 + 255) / 256, 256>>>(x, xh, xl, nx4);
    // launch 1: all 4 weight splits (fp16 hi only)
    split_w4_kernel<<<(nw4all + 255) / 256, 256>>>(W_q, W_k, W_v, W_o, Wh);

    // launch 2: fused QKV GEMM (fp16, 2-MMA)
    dim3 qkv_grid(3 * DM / 128, ROWS / 128);   // (24, 64)
    gemm_f16_kernel<true><<<qkv_grid, 256, GEMM_SMEM>>>(
        xh, xl, Wh, nullptr, qkvh, qkvl);

    // launch 3: attention  (<-- profiled launch)
    dim3 attn_grid(SEQ / 64, BATCH * NH);      // (32, 64)
    flash_attn_mma_kernel<<<attn_grid, 128, ATTN_SMEM>>>(
        qkvh, qkvl, qkvh + NX, qkvh + 2 * NX, qkvl + 2 * NX, th, tl);

    // launch 4: output projection (fp16, 2-MMA, fp32 out)
    dim3 o_grid(DM / 128, ROWS / 128);         // (8, 64)
    gemm_f16_kernel<false><<<o_grid, 256, GEMM_SMEM>>>(
        th, tl, Wh + 3 * NW, out, nullptr, nullptr);
}

// round 16
// speedup vs baseline: 2.5922x; 1.6733x over previous
#include <cuda_runtime.h>
#include <cuda_fp16.h>
#include <cstdint>

// Problem constants
static constexpr int BATCH = 4;
static constexpr int SEQ   = 2048;
static constexpr int DM    = 1024;
static constexpr int NH    = 16;
static constexpr int DH    = 64;
static constexpr int ROWS  = BATCH * SEQ;        // 8192
static constexpr size_t NX = (size_t)ROWS * DM;  // 8388608
static constexpr size_t NW = (size_t)DM * DM;    // 1048576

// Scratch (device globals: allocation-free) — single fp16 everywhere
__device__ __half g_x[NX];
__device__ __half g_W[4 * NW];       // Wq|Wk|Wv|Wo
__device__ __half g_qkv[3 * NX];     // Q|K|V
__device__ __half g_t[NX];

// ---------------------------------------------------------------------------
// Helpers
// ---------------------------------------------------------------------------
__device__ __forceinline__ uint32_t smem_u32(const void* p) {
    uint32_t a;
    asm("{ .reg .u64 t; cvta.to.shared.u64 t, %1; cvt.u32.u64 %0, t; }"
        : "=r"(a) : "l"(p));
    return a;
}
__device__ __forceinline__ uint32_t sw128(uint32_t off) {
    return off ^ ((off >> 3) & 0x70);
}
__device__ __forceinline__ void cp_async16(uint32_t saddr, const void* gaddr) {
    asm volatile("cp.async.cg.shared.global [%0], [%1], 16;"
                 :: "r"(saddr), "l"(gaddr));
}
#define CP_COMMIT() asm volatile("cp.async.commit_group;")
#define CP_WAIT(n)  asm volatile("cp.async.wait_group %0;" :: "n"(n))

__device__ __forceinline__ void ldsm_x4(uint32_t (&r)[4], uint32_t addr) {
    asm volatile("ldmatrix.sync.aligned.m8n8.x4.shared.b16 {%0,%1,%2,%3}, [%4];"
                 : "=r"(r[0]), "=r"(r[1]), "=r"(r[2]), "=r"(r[3]) : "r"(addr));
}
__device__ __forceinline__ void ldsm_x4_t(uint32_t (&r)[4], uint32_t addr) {
    asm volatile("ldmatrix.sync.aligned.m8n8.x4.trans.shared.b16 {%0,%1,%2,%3}, [%4];"
                 : "=r"(r[0]), "=r"(r[1]), "=r"(r[2]), "=r"(r[3]) : "r"(addr));
}
__device__ __forceinline__ void mma_f16(float (&d)[4], const uint32_t (&a)[4],
                                        const uint32_t* b) {
    asm volatile(
        "mma.sync.aligned.m16n8k16.row.col.f32.f16.f16.f32 "
        "{%0,%1,%2,%3}, {%4,%5,%6,%7}, {%8,%9}, {%0,%1,%2,%3};"
        : "+f"(d[0]), "+f"(d[1]), "+f"(d[2]), "+f"(d[3])
        : "r"(a[0]), "r"(a[1]), "r"(a[2]), "r"(a[3]), "r"(b[0]), "r"(b[1]));
}
__device__ __forceinline__ uint32_t pack_half2(float a, float b) {
    __half2 h2 = __float22half2_rn(make_float2(a, b));
    return *reinterpret_cast<const uint32_t*>(&h2);
}

// ---------------------------------------------------------------------------
// fp32 -> fp16 convert (x)
// ---------------------------------------------------------------------------
__global__ __launch_bounds__(256) void conv_f16_kernel(
    const float* __restrict__ src, __half* __restrict__ dst, int n4)
{
    int i = blockIdx.x * blockDim.x + threadIdx.x;
    if (i >= n4) return;
    float4 v = reinterpret_cast<const float4*>(src)[i];
    __half2 h0 = __float22half2_rn(make_float2(v.x, v.y));
    __half2 h1 = __float22half2_rn(make_float2(v.z, v.w));
    uint2 hv;
    hv.x = *reinterpret_cast<uint32_t*>(&h0); hv.y = *reinterpret_cast<uint32_t*>(&h1);
    reinterpret_cast<uint2*>(dst)[i] = hv;
}

// fp32 -> fp16, 4 weight matrices in ONE launch
__global__ __launch_bounds__(256) void conv_w4_kernel(
    const float* __restrict__ w0, const float* __restrict__ w1,
    const float* __restrict__ w2, const float* __restrict__ w3,
    __half* __restrict__ dst)
{
    const int nw4 = (int)(NW / 4);
    int i = blockIdx.x * blockDim.x + threadIdx.x;
    if (i >= 4 * nw4) return;
    const int mat = i / nw4;
    const int j   = i - mat * nw4;
    const float* src = (mat == 0) ? w0 : (mat == 1) ? w1 : (mat == 2) ? w2 : w3;
    float4 v = reinterpret_cast<const float4*>(src)[j];
    __half2 h0 = __float22half2_rn(make_float2(v.x, v.y));
    __half2 h1 = __float22half2_rn(make_float2(v.z, v.w));
    uint2 hv;
    hv.x = *reinterpret_cast<uint32_t*>(&h0); hv.y = *reinterpret_cast<uint32_t*>(&h1);
    reinterpret_cast<uint2*>(dst)[i] = hv;
}

// ---------------------------------------------------------------------------
// Pure fp16 GEMM (NT), K = 1024: C = A @ B^T, 1 MMA per product.
// 128x128 CTA tile, BK=64 (128B fp16 rows), 3-stage ring, 2 CTAs/SM.
// F16_OUT: write into per-matrix buffer (col0>>10 selects Q/K/V).
// ---------------------------------------------------------------------------
static constexpr int TILE_B    = 128 * 128;           // 16 KB (128 rows x 64 fp16)
static constexpr int STAGE_B   = 2 * TILE_B;          // 32 KB (A + B)
static constexpr int GSTAGES   = 3;
static constexpr int GEMM_SMEM = GSTAGES * STAGE_B;   // 98304

template <bool F16_OUT>
__global__ __launch_bounds__(256, 2) void gemm_f16_kernel(
    const __half* __restrict__ A, const __half* __restrict__ B,
    float* __restrict__ C, __half* __restrict__ Ch)
{
    extern __shared__ char smem[];
    const uint32_t sbase = smem_u32(smem);
    constexpr int K   = DM;
    constexpr int NKT = K / 64;          // 16 k-steps of 64

    const int tid   = threadIdx.x;
    const int wid   = tid >> 5;
    const int lane  = tid & 31;
    const int warpm = wid >> 2;
    const int warpn = wid & 3;
    const int row0  = blockIdx.y * 128;
    const int col0  = blockIdx.x * 128;

    auto load_stage = [&](int s, int kt) {
        const uint32_t As = sbase + s * STAGE_B;
        const uint32_t Bs = As + TILE_B;
        const size_t kofs = (size_t)kt * 64;
        const __half* A0 = A + (size_t)row0 * K + kofs;
        const __half* B0 = B + (size_t)col0 * K + kofs;
        #pragma unroll
        for (int t = 0; t < 4; t++) {        // 128 rows x 8 chunks (16B each)
            int v = t * 256 + tid;
            int r = v >> 3;
            int c = v & 7;
            uint32_t soff = sw128((uint32_t)(r * 128 + c * 16));
            cp_async16(As + soff, A0 + (size_t)r * K + c * 8);
            cp_async16(Bs + soff, B0 + (size_t)r * K + c * 8);
        }
    };

    float acc[4][4][4];
    #pragma unroll
    for (int i = 0; i < 4; i++)
        #pragma unroll
        for (int j = 0; j < 4; j++)
            #pragma unroll
            for (int k = 0; k < 4; k++) acc[i][j][k] = 0.0f;

    load_stage(0, 0); CP_COMMIT();
    load_stage(1, 1); CP_COMMIT();

    for (int kt = 0; kt < NKT; kt++) {
        CP_WAIT(1);
        __syncthreads();

        const uint32_t As = sbase + (kt % 3) * STAGE_B;
        const uint32_t Bs = As + TILE_B;

        #pragma unroll
        for (int j = 0; j < 4; j++) {        // 4 k-chunks of 16 fp16
            uint32_t Af[4][4], Bf[4][2];
            #pragma unroll
            for (int mt = 0; mt < 4; mt++) {
                int row = warpm * 64 + mt * 16 + (lane & 15);
                ldsm_x4(Af[mt], As + sw128((uint32_t)(row * 128 + (j * 2 + (lane >> 4)) * 16)));
            }
            #pragma unroll
            for (int p = 0; p < 2; p++) {
                int row = warpn * 32 + p * 16 + ((lane >> 4) << 3) + (lane & 7);
                uint32_t t4[4];
                ldsm_x4(t4, Bs + sw128((uint32_t)(row * 128 + (j * 2 + ((lane >> 3) & 1)) * 16)));
                Bf[p * 2][0]     = t4[0]; Bf[p * 2][1]     = t4[1];
                Bf[p * 2 + 1][0] = t4[2]; Bf[p * 2 + 1][1] = t4[3];
            }
            #pragma unroll
            for (int mt = 0; mt < 4; mt++)
                #pragma unroll
                for (int nt = 0; nt < 4; nt++)
                    mma_f16(acc[mt][nt], Af[mt], Bf[nt]);
        }

        if (kt + 2 < NKT) load_stage((kt + 2) % 3, kt + 2);
        CP_COMMIT();
    }

    const int g = lane >> 2;
    const int t = lane & 3;
    if (F16_OUT) {
        // fused-QKV output: select the target matrix buffer (BUGFIX vs R15)
        const int mat  = col0 >> 10;
        const int colb = col0 & 1023;
        __half* ch = Ch + (size_t)mat * NX;
        #pragma unroll
        for (int mt = 0; mt < 4; mt++)
            #pragma unroll
            for (int nt = 0; nt < 4; nt++) {
                int row = row0 + warpm * 64 + mt * 16 + g;
                int col = colb + warpn * 32 + nt * 8 + t * 2;
                uint32_t v0 = pack_half2(acc[mt][nt][0], acc[mt][nt][1]);
                uint32_t v1 = pack_half2(acc[mt][nt][2], acc[mt][nt][3]);
                *reinterpret_cast<uint32_t*>(ch + (size_t)row * DM + col)       = v0;
                *reinterpret_cast<uint32_t*>(ch + (size_t)(row + 8) * DM + col) = v1;
            }
    } else {
        #pragma unroll
        for (int mt = 0; mt < 4; mt++)
            #pragma unroll
            for (int nt = 0; nt < 4; nt++) {
                int row = row0 + warpm * 64 + mt * 16 + g;
                int col = col0 + warpn * 32 + nt * 8 + t * 2;
                float2 v0 = make_float2(acc[mt][nt][0], acc[mt][nt][1]);
                float2 v1 = make_float2(acc[mt][nt][2], acc[mt][nt][3]);
                *reinterpret_cast<float2*>(&C[(size_t)row * DM + col])       = v0;
                *reinterpret_cast<float2*>(&C[(size_t)(row + 8) * DM + col]) = v1;
            }
    }
}

// ---------------------------------------------------------------------------
// Flash attention — pipelined S, pure fp16 (1 MMA per product).
// BM=64, BN=64, 4 warps x 16 rows, 128 thr.
// kbuf 2x8KB, vbuf 3x8KB = 40KB.
// ---------------------------------------------------------------------------
static constexpr int ATTN_SMEM = 2 * 8192 + 3 * 8192;   // 40960
static constexpr float SCALE_L2E = 0.125f * 1.4426950408889634f;

__global__ __launch_bounds__(128, 2) void flash_attn_mma_kernel(
    const __half* __restrict__ q, const __half* __restrict__ k,
    const __half* __restrict__ v, __half* __restrict__ tout)
{
    extern __shared__ char smem[];
    const uint32_t sbase = smem_u32(smem);
    const uint32_t VBASE = sbase + 16384;          // vbuf[i] = VBASE + i*8192

    const int tid  = threadIdx.x;
    const int wid  = tid >> 5;        // 0..3
    const int lane = tid & 31;
    const int g    = lane >> 2;
    const int t    = lane & 3;

    const int qb = (SEQ / 64 - 1) - blockIdx.x;    // heavy blocks first
    const int bh = blockIdx.y;
    const int b  = bh >> 4;
    const int h  = bh & 15;
    const int q0 = qb * 64;
    const int bofs = b * SEQ;
    const int NT = qb + 1;                          // kv tiles of 64
    const int rowg = q0 + wid * 16 + g;

    // ---- stage Q through vbuf[2] ----
    {
        const uint32_t qstage = VBASE + 2 * 8192;
        #pragma unroll
        for (int tt = 0; tt < 4; tt++) {
            int vv = tt * 128 + tid;
            int r = vv >> 3;
            int c = vv & 7;
            cp_async16(qstage + sw128((uint32_t)(r * 128 + c * 16)),
                       q + (size_t)(bofs + q0 + r) * DM + h * 64 + c * 8);
        }
    }
    CP_COMMIT();
    CP_WAIT(0);
    __syncthreads();

    uint32_t qf[4][4];
    #pragma unroll
    for (int j = 0; j < 4; j++) {
        int row   = wid * 16 + (lane & 15);
        int chunk = j * 2 + (lane >> 4);
        ldsm_x4(qf[j], VBASE + 2 * 8192 + sw128((uint32_t)(row * 128 + chunk * 16)));
    }
    __syncthreads();   // Q fragments extracted; vbuf[2] free

    // loader: K -> kbuf[t&1], V -> vbuf[t%3]
    auto load_kv = [&](int tile) {
        const int kv = tile * 64;
        const uint32_t kb = sbase + (tile & 1) * 8192;
        const uint32_t vb = VBASE + (tile % 3) * 8192;
        #pragma unroll
        for (int tt = 0; tt < 4; tt++) {
            int vv = tt * 128 + tid;
            int r = vv >> 3;
            int c = vv & 7;
            uint32_t soff = sw128((uint32_t)(r * 128 + c * 16));
            cp_async16(kb + soff, k + (size_t)(bofs + kv + r) * DM + h * 64 + c * 8);
            cp_async16(vb + soff, v + (size_t)(bofs + kv + r) * DM + h * 64 + c * 8);
        }
    };

    // S-MMA: sout = Q @ K^T (1 MMA per n-tile per j)
    auto s_mma = [&](float (&sout)[8][4], uint32_t kb) {
        #pragma unroll
        for (int nt = 0; nt < 8; nt++)
            #pragma unroll
            for (int c = 0; c < 4; c++) sout[nt][c] = 0.0f;
        #pragma unroll
        for (int j = 0; j < 4; j++) {
            uint32_t kf[8][2];
            #pragma unroll
            for (int np = 0; np < 4; np++) {
                int row   = np * 16 + ((lane >> 4) << 3) + (lane & 7);
                int chunk = j * 2 + ((lane >> 3) & 1);
                uint32_t t4[4];
                ldsm_x4(t4, kb + sw128((uint32_t)(row * 128 + chunk * 16)));
                kf[np * 2][0]     = t4[0];
                kf[np * 2][1]     = t4[1];
                kf[np * 2 + 1][0] = t4[2];
                kf[np * 2 + 1][1] = t4[3];
            }
            #pragma unroll
            for (int nt = 0; nt < 8; nt++)
                mma_f16(sout[nt], qf[j], kf[nt]);
        }
    };

    load_kv(0); CP_COMMIT();
    load_kv(1); CP_COMMIT();
    CP_WAIT(1);
    __syncthreads();

    float m0 = -1e30f, m1 = -1e30f, l0 = 0.0f, l1 = 0.0f;
    float oacc[8][4];
    #pragma unroll
    for (int nt = 0; nt < 8; nt++)
        #pragma unroll
        for (int c = 0; c < 4; c++) oacc[nt][c] = 0.0f;

    float saccA[8][4], saccB[8][4];
    s_mma(saccA, sbase);               // S(0) from kbuf[0]

    auto body = [&](float (&cur)[8][4], float (&next)[8][4], int kt) {
        CP_WAIT(0);
        __syncthreads();

        if (kt + 2 < NT) load_kv(kt + 2);
        CP_COMMIT();

        if (kt + 1 < NT) s_mma(next, sbase + ((kt + 1) & 1) * 8192);

        const int kv0 = kt * 64;
        const bool lastt = (kt == NT - 1);
        #pragma unroll
        for (int nt = 0; nt < 8; nt++) {
            #pragma unroll
            for (int c = 0; c < 4; c++) {
                float s = cur[nt][c] * SCALE_L2E;
                if (lastt) {
                    int col = kv0 + nt * 8 + t * 2 + (c & 1);
                    int row = (c < 2) ? rowg : rowg + 8;
                    if (col > row) s = -1e30f;
                }
                cur[nt][c] = s;
            }
        }

        float mx0 = -1e30f, mx1 = -1e30f;
        #pragma unroll
        for (int nt = 0; nt < 8; nt++) {
            mx0 = fmaxf(mx0, fmaxf(cur[nt][0], cur[nt][1]));
            mx1 = fmaxf(mx1, fmaxf(cur[nt][2], cur[nt][3]));
        }
        mx0 = fmaxf(mx0, __shfl_xor_sync(0xffffffffu, mx0, 1));
        mx0 = fmaxf(mx0, __shfl_xor_sync(0xffffffffu, mx0, 2));
        mx1 = fmaxf(mx1, __shfl_xor_sync(0xffffffffu, mx1, 1));
        mx1 = fmaxf(mx1, __shfl_xor_sync(0xffffffffu, mx1, 2));
        float mnew0 = fmaxf(m0, mx0), mnew1 = fmaxf(m1, mx1);
        float a0 = exp2f(m0 - mnew0), a1 = exp2f(m1 - mnew1);
        m0 = mnew0; m1 = mnew1;

        float rs0 = 0.0f, rs1 = 0.0f;
        #pragma unroll
        for (int nt = 0; nt < 8; nt++) {
            float p0 = exp2f(cur[nt][0] - mnew0);
            float p1 = exp2f(cur[nt][1] - mnew0);
            float p2 = exp2f(cur[nt][2] - mnew1);
            float p3 = exp2f(cur[nt][3] - mnew1);
            cur[nt][0] = p0; cur[nt][1] = p1;
            cur[nt][2] = p2; cur[nt][3] = p3;
            rs0 += p0 + p1; rs1 += p2 + p3;
        }
        rs0 += __shfl_xor_sync(0xffffffffu, rs0, 1);
        rs0 += __shfl_xor_sync(0xffffffffu, rs0, 2);
        rs1 += __shfl_xor_sync(0xffffffffu, rs1, 1);
        rs1 += __shfl_xor_sync(0xffffffffu, rs1, 2);
        l0 = l0 * a0 + rs0;
        l1 = l1 * a1 + rs1;
        #pragma unroll
        for (int nt = 0; nt < 8; nt++) {
            oacc[nt][0] *= a0; oacc[nt][1] *= a0;
            oacc[nt][2] *= a1; oacc[nt][3] *= a1;
        }

        // ---- PV: O += P @ V (1 MMA per n-tile) ----
        const uint32_t vb = VBASE + (kt % 3) * 8192;
        #pragma unroll
        for (int pj = 0; pj < 4; pj++) {
            const float* se = cur[2 * pj];
            const float* so = cur[2 * pj + 1];
            uint32_t pf[4];
            pf[0] = pack_half2(se[0], se[1]);
            pf[1] = pack_half2(se[2], se[3]);
            pf[2] = pack_half2(so[0], so[1]);
            pf[3] = pack_half2(so[2], so[3]);

            uint32_t vf[8][2];
            #pragma unroll
            for (int np = 0; np < 4; np++) {
                int kvrow = pj * 16 + (lane & 15);
                int dby   = np * 32 + ((lane >> 4) * 16);
                uint32_t t4[4];
                ldsm_x4_t(t4, vb + sw128((uint32_t)(kvrow * 128 + dby)));
                vf[np * 2][0]     = t4[0];
                vf[np * 2][1]     = t4[1];
                vf[np * 2 + 1][0] = t4[2];
                vf[np * 2 + 1][1] = t4[3];
            }
            #pragma unroll
            for (int nt = 0; nt < 8; nt++)
                mma_f16(oacc[nt], pf, vf[nt]);
        }
    };

    for (int kt = 0; kt < NT; kt += 2) {
        body(saccA, saccB, kt);
        if (kt + 1 < NT) body(saccB, saccA, kt + 1);
    }

    // ---- epilogue: normalize + fp16 write T ----
    const float inv0 = 1.0f / l0, inv1 = 1.0f / l1;
    const size_t rb0 = (size_t)(bofs + rowg) * DM + h * 64;
    const size_t rb1 = rb0 + (size_t)8 * DM;
    #pragma unroll
    for (int nt = 0; nt < 8; nt++) {
        int col = nt * 8 + t * 2;
        *reinterpret_cast<uint32_t*>(tout + rb0 + col) =
            pack_half2(oacc[nt][0] * inv0, oacc[nt][1] * inv0);
        *reinterpret_cast<uint32_t*>(tout + rb1 + col) =
            pack_half2(oacc[nt][2] * inv1, oacc[nt][3] * inv1);
    }
}

// ---------------------------------------------------------------------------
// Launcher — attention at launch index 3 (the one ncu captures)
// ---------------------------------------------------------------------------
extern "C" void kernel_launch(void* const* d_in, const int* in_sizes, int n_in,
                              void* d_out, int out_size)
{
    const float* x   = (const float*)d_in[0];
    const float* W_q = (const float*)d_in[1];
    const float* W_k = (const float*)d_in[2];
    const float* W_v = (const float*)d_in[3];
    const float* W_o = (const float*)d_in[4];
    float* out = (float*)d_out;

    __half *xp, *Wp, *qkvp, *tp;
    cudaGetSymbolAddress((void**)&xp, g_x);
    cudaGetSymbolAddress((void**)&Wp, g_W);
    cudaGetSymbolAddress((void**)&qkvp, g_qkv);
    cudaGetSymbolAddress((void**)&tp, g_t);

    cudaFuncSetAttribute(gemm_f16_kernel<true>,
                         cudaFuncAttributeMaxDynamicSharedMemorySize, GEMM_SMEM);
    cudaFuncSetAttribute(gemm_f16_kernel<false>,
                         cudaFuncAttributeMaxDynamicSharedMemorySize, GEMM_SMEM);
    cudaFuncSetAttribute(flash_attn_mma_kernel,
                         cudaFuncAttributeMaxDynamicSharedMemorySize, ATTN_SMEM);

    const int nx4 = (int)(NX / 4);
    const int nw4all = (int)(NW);          // 4 * (NW/4)

    // launch 0: x convert
    conv_f16_kernel<<<(nx4 + 255) / 256, 256>>>(x, xp, nx4);
    // launch 1: all 4 weight converts fused
    conv_w4_kernel<<<(nw4all + 255) / 256, 256>>>(W_q, W_k, W_v, W_o, Wp);

    // launch 2: fused QKV GEMM (pure fp16)
    dim3 qkv_grid(3 * DM / 128, ROWS / 128);   // (24, 64)
    gemm_f16_kernel<true><<<qkv_grid, 256, GEMM_SMEM>>>(
        xp, Wp, nullptr, qkvp);

    // launch 3: attention  (<-- profiled launch)
    dim3 attn_grid(SEQ / 64, BATCH * NH);      // (32, 64)
    flash_attn_mma_kernel<<<attn_grid, 128, ATTN_SMEM>>>(
        qkvp, qkvp + NX, qkvp + 2 * NX, tp);

    // launch 4: output projection (fp32 out)
    dim3 o_grid(DM / 128, ROWS / 128);         // (8, 64)
    gemm_f16_kernel<false><<<o_grid, 256, GEMM_SMEM>>>(
        tp, Wp + 3 * NW, out, nullptr);
}

// round 17
// speedup vs baseline: 2.6797x; 1.0338x over previous
#include <cuda_runtime.h>
#include <cuda_fp16.h>
#include <cstdint>

// Problem constants
static constexpr int BATCH = 4;
static constexpr int SEQ   = 2048;
static constexpr int DM    = 1024;
static constexpr int NH    = 16;
static constexpr int DH    = 64;
static constexpr int ROWS  = BATCH * SEQ;        // 8192
static constexpr size_t NX = (size_t)ROWS * DM;  // 8388608
static constexpr size_t NW = (size_t)DM * DM;    // 1048576

static constexpr float SCALE_L2E = 0.125f * 1.4426950408889634f;

// Scratch (device globals: allocation-free) — single fp16 everywhere
__device__ __half g_x[NX];
__device__ __half g_W[4 * NW];       // Wq|Wk|Wv|Wo
__device__ __half g_qkv[3 * NX];     // Q(pre-scaled)|K|V
__device__ __half g_t[NX];

// ---------------------------------------------------------------------------
// Helpers
// ---------------------------------------------------------------------------
__device__ __forceinline__ uint32_t smem_u32(const void* p) {
    uint32_t a;
    asm("{ .reg .u64 t; cvta.to.shared.u64 t, %1; cvt.u32.u64 %0, t; }"
        : "=r"(a) : "l"(p));
    return a;
}
__device__ __forceinline__ uint32_t sw128(uint32_t off) {
    return off ^ ((off >> 3) & 0x70);
}
__device__ __forceinline__ void cp_async16(uint32_t saddr, const void* gaddr) {
    asm volatile("cp.async.cg.shared.global [%0], [%1], 16;"
                 :: "r"(saddr), "l"(gaddr));
}
#define CP_COMMIT() asm volatile("cp.async.commit_group;")
#define CP_WAIT(n)  asm volatile("cp.async.wait_group %0;" :: "n"(n))

__device__ __forceinline__ void ldsm_x4(uint32_t (&r)[4], uint32_t addr) {
    asm volatile("ldmatrix.sync.aligned.m8n8.x4.shared.b16 {%0,%1,%2,%3}, [%4];"
                 : "=r"(r[0]), "=r"(r[1]), "=r"(r[2]), "=r"(r[3]) : "r"(addr));
}
__device__ __forceinline__ void ldsm_x4_t(uint32_t (&r)[4], uint32_t addr) {
    asm volatile("ldmatrix.sync.aligned.m8n8.x4.trans.shared.b16 {%0,%1,%2,%3}, [%4];"
                 : "=r"(r[0]), "=r"(r[1]), "=r"(r[2]), "=r"(r[3]) : "r"(addr));
}
__device__ __forceinline__ void mma_f16(float (&d)[4], const uint32_t (&a)[4],
                                        const uint32_t* b) {
    asm volatile(
        "mma.sync.aligned.m16n8k16.row.col.f32.f16.f16.f32 "
        "{%0,%1,%2,%3}, {%4,%5,%6,%7}, {%8,%9}, {%0,%1,%2,%3};"
        : "+f"(d[0]), "+f"(d[1]), "+f"(d[2]), "+f"(d[3])
        : "r"(a[0]), "r"(a[1]), "r"(a[2]), "r"(a[3]), "r"(b[0]), "r"(b[1]));
}
__device__ __forceinline__ uint32_t pack_half2(float a, float b) {
    __half2 h2 = __float22half2_rn(make_float2(a, b));
    return *reinterpret_cast<const uint32_t*>(&h2);
}

// ---------------------------------------------------------------------------
// fp32 -> fp16 convert (x)
// ---------------------------------------------------------------------------
__global__ __launch_bounds__(256) void conv_f16_kernel(
    const float* __restrict__ src, __half* __restrict__ dst, int n4)
{
    int i = blockIdx.x * blockDim.x + threadIdx.x;
    if (i >= n4) return;
    float4 v = reinterpret_cast<const float4*>(src)[i];
    __half2 h0 = __float22half2_rn(make_float2(v.x, v.y));
    __half2 h1 = __float22half2_rn(make_float2(v.z, v.w));
    uint2 hv;
    hv.x = *reinterpret_cast<uint32_t*>(&h0); hv.y = *reinterpret_cast<uint32_t*>(&h1);
    reinterpret_cast<uint2*>(dst)[i] = hv;
}

// fp32 -> fp16, 4 weight matrices in ONE launch
__global__ __launch_bounds__(256) void conv_w4_kernel(
    const float* __restrict__ w0, const float* __restrict__ w1,
    const float* __restrict__ w2, const float* __restrict__ w3,
    __half* __restrict__ dst)
{
    const int nw4 = (int)(NW / 4);
    int i = blockIdx.x * blockDim.x + threadIdx.x;
    if (i >= 4 * nw4) return;
    const int mat = i / nw4;
    const int j   = i - mat * nw4;
    const float* src = (mat == 0) ? w0 : (mat == 1) ? w1 : (mat == 2) ? w2 : w3;
    float4 v = reinterpret_cast<const float4*>(src)[j];
    __half2 h0 = __float22half2_rn(make_float2(v.x, v.y));
    __half2 h1 = __float22half2_rn(make_float2(v.z, v.w));
    uint2 hv;
    hv.x = *reinterpret_cast<uint32_t*>(&h0); hv.y = *reinterpret_cast<uint32_t*>(&h1);
    reinterpret_cast<uint2*>(dst)[i] = hv;
}

// ---------------------------------------------------------------------------
// Pure fp16 GEMM (NT), K = 1024: C = A @ B^T, 1 MMA per product.
// 128x128 CTA tile, BK=64, 3-stage ring, 2 CTAs/SM.
// F16_OUT: per-matrix buffer select; Q (mat 0) pre-scaled by SCALE_L2E.
// ---------------------------------------------------------------------------
static constexpr int TILE_B    = 128 * 128;
static constexpr int STAGE_B   = 2 * TILE_B;          // 32 KB
static constexpr int GSTAGES   = 3;
static constexpr int GEMM_SMEM = GSTAGES * STAGE_B;   // 98304

template <bool F16_OUT>
__global__ __launch_bounds__(256, 2) void gemm_f16_kernel(
    const __half* __restrict__ A, const __half* __restrict__ B,
    float* __restrict__ C, __half* __restrict__ Ch)
{
    extern __shared__ char smem[];
    const uint32_t sbase = smem_u32(smem);
    constexpr int K   = DM;
    constexpr int NKT = K / 64;

    const int tid   = threadIdx.x;
    const int wid   = tid >> 5;
    const int lane  = tid & 31;
    const int warpm = wid >> 2;
    const int warpn = wid & 3;
    const int row0  = blockIdx.y * 128;
    const int col0  = blockIdx.x * 128;

    auto load_stage = [&](int s, int kt) {
        const uint32_t As = sbase + s * STAGE_B;
        const uint32_t Bs = As + TILE_B;
        const size_t kofs = (size_t)kt * 64;
        const __half* A0 = A + (size_t)row0 * K + kofs;
        const __half* B0 = B + (size_t)col0 * K + kofs;
        #pragma unroll
        for (int t = 0; t < 4; t++) {
            int v = t * 256 + tid;
            int r = v >> 3;
            int c = v & 7;
            uint32_t soff = sw128((uint32_t)(r * 128 + c * 16));
            cp_async16(As + soff, A0 + (size_t)r * K + c * 8);
            cp_async16(Bs + soff, B0 + (size_t)r * K + c * 8);
        }
    };

    float acc[4][4][4];
    #pragma unroll
    for (int i = 0; i < 4; i++)
        #pragma unroll
        for (int j = 0; j < 4; j++)
            #pragma unroll
            for (int k = 0; k < 4; k++) acc[i][j][k] = 0.0f;

    load_stage(0, 0); CP_COMMIT();
    load_stage(1, 1); CP_COMMIT();

    for (int kt = 0; kt < NKT; kt++) {
        CP_WAIT(1);
        __syncthreads();

        const uint32_t As = sbase + (kt % 3) * STAGE_B;
        const uint32_t Bs = As + TILE_B;

        #pragma unroll
        for (int j = 0; j < 4; j++) {
            uint32_t Af[4][4], Bf[4][2];
            #pragma unroll
            for (int mt = 0; mt < 4; mt++) {
                int row = warpm * 64 + mt * 16 + (lane & 15);
                ldsm_x4(Af[mt], As + sw128((uint32_t)(row * 128 + (j * 2 + (lane >> 4)) * 16)));
            }
            #pragma unroll
            for (int p = 0; p < 2; p++) {
                int row = warpn * 32 + p * 16 + ((lane >> 4) << 3) + (lane & 7);
                uint32_t t4[4];
                ldsm_x4(t4, Bs + sw128((uint32_t)(row * 128 + (j * 2 + ((lane >> 3) & 1)) * 16)));
                Bf[p * 2][0]     = t4[0]; Bf[p * 2][1]     = t4[1];
                Bf[p * 2 + 1][0] = t4[2]; Bf[p * 2 + 1][1] = t4[3];
            }
            #pragma unroll
            for (int mt = 0; mt < 4; mt++)
                #pragma unroll
                for (int nt = 0; nt < 4; nt++)
                    mma_f16(acc[mt][nt], Af[mt], Bf[nt]);
        }

        if (kt + 2 < NKT) load_stage((kt + 2) % 3, kt + 2);
        CP_COMMIT();
    }

    const int g = lane >> 2;
    const int t = lane & 3;
    if (F16_OUT) {
        const int mat  = col0 >> 10;
        const int colb = col0 & 1023;
        const float sc = (mat == 0) ? SCALE_L2E : 1.0f;   // pre-scale Q
        __half* ch = Ch + (size_t)mat * NX;
        #pragma unroll
        for (int mt = 0; mt < 4; mt++)
            #pragma unroll
            for (int nt = 0; nt < 4; nt++) {
                int row = row0 + warpm * 64 + mt * 16 + g;
                int col = colb + warpn * 32 + nt * 8 + t * 2;
                uint32_t v0 = pack_half2(acc[mt][nt][0] * sc, acc[mt][nt][1] * sc);
                uint32_t v1 = pack_half2(acc[mt][nt][2] * sc, acc[mt][nt][3] * sc);
                *reinterpret_cast<uint32_t*>(ch + (size_t)row * DM + col)       = v0;
                *reinterpret_cast<uint32_t*>(ch + (size_t)(row + 8) * DM + col) = v1;
            }
    } else {
        #pragma unroll
        for (int mt = 0; mt < 4; mt++)
            #pragma unroll
            for (int nt = 0; nt < 4; nt++) {
                int row = row0 + warpm * 64 + mt * 16 + g;
                int col = col0 + warpn * 32 + nt * 8 + t * 2;
                float2 v0 = make_float2(acc[mt][nt][0], acc[mt][nt][1]);
                float2 v1 = make_float2(acc[mt][nt][2], acc[mt][nt][3]);
                *reinterpret_cast<float2*>(&C[(size_t)row * DM + col])       = v0;
                *reinterpret_cast<float2*>(&C[(size_t)(row + 8) * DM + col]) = v1;
            }
    }
}

// ---------------------------------------------------------------------------
// Flash attention — pipelined S, pure fp16, lean softmax:
// Q pre-scaled (no per-tile scale pass), l via ones-MMA, skip-rescale.
// BM=64, BN=64, 4 warps x 16 rows, 128 thr. kbuf 2x8KB, vbuf 3x8KB = 40KB.
// ---------------------------------------------------------------------------
static constexpr int ATTN_SMEM = 2 * 8192 + 3 * 8192;   // 40960

__global__ __launch_bounds__(128, 2) void flash_attn_mma_kernel(
    const __half* __restrict__ q, const __half* __restrict__ k,
    const __half* __restrict__ v, __half* __restrict__ tout)
{
    extern __shared__ char smem[];
    const uint32_t sbase = smem_u32(smem);
    const uint32_t VBASE = sbase + 16384;          // vbuf[i] = VBASE + i*8192

    const int tid  = threadIdx.x;
    const int wid  = tid >> 5;        // 0..3
    const int lane = tid & 31;
    const int g    = lane >> 2;
    const int t    = lane & 3;

    const int qb = (SEQ / 64 - 1) - blockIdx.x;    // heavy blocks first
    const int bh = blockIdx.y;
    const int b  = bh >> 4;
    const int h  = bh & 15;
    const int q0 = qb * 64;
    const int bofs = b * SEQ;
    const int NT = qb + 1;                          // kv tiles of 64
    const int rowg = q0 + wid * 16 + g;

    // ---- stage Q through vbuf[2] ----
    {
        const uint32_t qstage = VBASE + 2 * 8192;
        #pragma unroll
        for (int tt = 0; tt < 4; tt++) {
            int vv = tt * 128 + tid;
            int r = vv >> 3;
            int c = vv & 7;
            cp_async16(qstage + sw128((uint32_t)(r * 128 + c * 16)),
                       q + (size_t)(bofs + q0 + r) * DM + h * 64 + c * 8);
        }
    }
    CP_COMMIT();
    CP_WAIT(0);
    __syncthreads();

    uint32_t qf[4][4];
    #pragma unroll
    for (int j = 0; j < 4; j++) {
        int row   = wid * 16 + (lane & 15);
        int chunk = j * 2 + (lane >> 4);
        ldsm_x4(qf[j], VBASE + 2 * 8192 + sw128((uint32_t)(row * 128 + chunk * 16)));
    }
    __syncthreads();   // Q fragments extracted; vbuf[2] free

    auto load_kv = [&](int tile) {
        const int kv = tile * 64;
        const uint32_t kb = sbase + (tile & 1) * 8192;
        const uint32_t vb = VBASE + (tile % 3) * 8192;
        #pragma unroll
        for (int tt = 0; tt < 4; tt++) {
            int vv = tt * 128 + tid;
            int r = vv >> 3;
            int c = vv & 7;
            uint32_t soff = sw128((uint32_t)(r * 128 + c * 16));
            cp_async16(kb + soff, k + (size_t)(bofs + kv + r) * DM + h * 64 + c * 8);
            cp_async16(vb + soff, v + (size_t)(bofs + kv + r) * DM + h * 64 + c * 8);
        }
    };

    auto s_mma = [&](float (&sout)[8][4], uint32_t kb) {
        #pragma unroll
        for (int nt = 0; nt < 8; nt++)
            #pragma unroll
            for (int c = 0; c < 4; c++) sout[nt][c] = 0.0f;
        #pragma unroll
        for (int j = 0; j < 4; j++) {
            uint32_t kf[8][2];
            #pragma unroll
            for (int np = 0; np < 4; np++) {
                int row   = np * 16 + ((lane >> 4) << 3) + (lane & 7);
                int chunk = j * 2 + ((lane >> 3) & 1);
                uint32_t t4[4];
                ldsm_x4(t4, kb + sw128((uint32_t)(row * 128 + chunk * 16)));
                kf[np * 2][0]     = t4[0];
                kf[np * 2][1]     = t4[1];
                kf[np * 2 + 1][0] = t4[2];
                kf[np * 2 + 1][1] = t4[3];
            }
            #pragma unroll
            for (int nt = 0; nt < 8; nt++)
                mma_f16(sout[nt], qf[j], kf[nt]);
        }
    };

    load_kv(0); CP_COMMIT();
    load_kv(1); CP_COMMIT();
    CP_WAIT(1);
    __syncthreads();

    float m0 = -1e30f, m1 = -1e30f;
    float oacc[8][4], lacc[4];
    #pragma unroll
    for (int nt = 0; nt < 8; nt++)
        #pragma unroll
        for (int c = 0; c < 4; c++) oacc[nt][c] = 0.0f;
    #pragma unroll
    for (int c = 0; c < 4; c++) lacc[c] = 0.0f;

    const uint32_t onef[2] = {0x3C003C00u, 0x3C003C00u};   // fp16 1.0 x4

    float saccA[8][4], saccB[8][4];
    s_mma(saccA, sbase);               // S(0) from kbuf[0]

    auto body = [&](float (&cur)[8][4], float (&next)[8][4], int kt) {
        CP_WAIT(0);
        __syncthreads();

        if (kt + 2 < NT) load_kv(kt + 2);
        CP_COMMIT();

        if (kt + 1 < NT) s_mma(next, sbase + ((kt + 1) & 1) * 8192);

        // causal mask only on the diagonal (last) tile; Q pre-scaled -> no scale pass
        if (kt == NT - 1) {
            const int kv0 = kt * 64;
            #pragma unroll
            for (int nt = 0; nt < 8; nt++)
                #pragma unroll
                for (int c = 0; c < 4; c++) {
                    int col = kv0 + nt * 8 + t * 2 + (c & 1);
                    int row = (c < 2) ? rowg : rowg + 8;
                    if (col > row) cur[nt][c] = -1e30f;
                }
        }

        // ---- online softmax (base-2, lean) ----
        float mx0 = -1e30f, mx1 = -1e30f;
        #pragma unroll
        for (int nt = 0; nt < 8; nt++) {
            mx0 = fmaxf(mx0, fmaxf(cur[nt][0], cur[nt][1]));
            mx1 = fmaxf(mx1, fmaxf(cur[nt][2], cur[nt][3]));
        }
        mx0 = fmaxf(mx0, __shfl_xor_sync(0xffffffffu, mx0, 1));
        mx0 = fmaxf(mx0, __shfl_xor_sync(0xffffffffu, mx0, 2));
        mx1 = fmaxf(mx1, __shfl_xor_sync(0xffffffffu, mx1, 1));
        mx1 = fmaxf(mx1, __shfl_xor_sync(0xffffffffu, mx1, 2));
        float mnew0 = fmaxf(m0, mx0), mnew1 = fmaxf(m1, mx1);
        float a0 = exp2f(m0 - mnew0), a1 = exp2f(m1 - mnew1);
        m0 = mnew0; m1 = mnew1;

        if (!__all_sync(0xffffffffu, (a0 == 1.0f) & (a1 == 1.0f))) {
            #pragma unroll
            for (int nt = 0; nt < 8; nt++) {
                oacc[nt][0] *= a0; oacc[nt][1] *= a0;
                oacc[nt][2] *= a1; oacc[nt][3] *= a1;
            }
            lacc[0] *= a0; lacc[1] *= a0; lacc[2] *= a1; lacc[3] *= a1;
        }

        #pragma unroll
        for (int nt = 0; nt < 8; nt++) {
            cur[nt][0] = exp2f(cur[nt][0] - mnew0);
            cur[nt][1] = exp2f(cur[nt][1] - mnew0);
            cur[nt][2] = exp2f(cur[nt][2] - mnew1);
            cur[nt][3] = exp2f(cur[nt][3] - mnew1);
        }

        // ---- PV + row-sum via ones-MMA ----
        const uint32_t vb = VBASE + (kt % 3) * 8192;
        #pragma unroll
        for (int pj = 0; pj < 4; pj++) {
            const float* se = cur[2 * pj];
            const float* so = cur[2 * pj + 1];
            uint32_t pf[4];
            pf[0] = pack_half2(se[0], se[1]);
            pf[1] = pack_half2(se[2], se[3]);
            pf[2] = pack_half2(so[0], so[1]);
            pf[3] = pack_half2(so[2], so[3]);

            mma_f16(lacc, pf, onef);           // l += P @ 1

            uint32_t vf[8][2];
            #pragma unroll
            for (int np = 0; np < 4; np++) {
                int kvrow = pj * 16 + (lane & 15);
                int dby   = np * 32 + ((lane >> 4) * 16);
                uint32_t t4[4];
                ldsm_x4_t(t4, vb + sw128((uint32_t)(kvrow * 128 + dby)));
                vf[np * 2][0]     = t4[0];
                vf[np * 2][1]     = t4[1];
                vf[np * 2 + 1][0] = t4[2];
                vf[np * 2 + 1][1] = t4[3];
            }
            #pragma unroll
            for (int nt = 0; nt < 8; nt++)
                mma_f16(oacc[nt], pf, vf[nt]);
        }
    };

    for (int kt = 0; kt < NT; kt += 2) {
        body(saccA, saccB, kt);
        if (kt + 1 < NT) body(saccB, saccA, kt + 1);
    }

    // ---- epilogue: normalize + fp16 write T ----
    const float inv0 = 1.0f / lacc[0], inv1 = 1.0f / lacc[2];
    const size_t rb0 = (size_t)(bofs + rowg) * DM + h * 64;
    const size_t rb1 = rb0 + (size_t)8 * DM;
    #pragma unroll
    for (int nt = 0; nt < 8; nt++) {
        int col = nt * 8 + t * 2;
        *reinterpret_cast<uint32_t*>(tout + rb0 + col) =
            pack_half2(oacc[nt][0] * inv0, oacc[nt][1] * inv0);
        *reinterpret_cast<uint32_t*>(tout + rb1 + col) =
            pack_half2(oacc[nt][2] * inv1, oacc[nt][3] * inv1);
    }
}

// ---------------------------------------------------------------------------
// Launcher — attention at launch index 3 (the one ncu captures)
// ---------------------------------------------------------------------------
extern "C" void kernel_launch(void* const* d_in, const int* in_sizes, int n_in,
                              void* d_out, int out_size)
{
    const float* x   = (const float*)d_in[0];
    const float* W_q = (const float*)d_in[1];
    const float* W_k = (const float*)d_in[2];
    const float* W_v = (const float*)d_in[3];
    const float* W_o = (const float*)d_in[4];
    float* out = (float*)d_out;

    __half *xp, *Wp, *qkvp, *tp;
    cudaGetSymbolAddress((void**)&xp, g_x);
    cudaGetSymbolAddress((void**)&Wp, g_W);
    cudaGetSymbolAddress((void**)&qkvp, g_qkv);
    cudaGetSymbolAddress((void**)&tp, g_t);

    cudaFuncSetAttribute(gemm_f16_kernel<true>,
                         cudaFuncAttributeMaxDynamicSharedMemorySize, GEMM_SMEM);
    cudaFuncSetAttribute(gemm_f16_kernel<false>,
                         cudaFuncAttributeMaxDynamicSharedMemorySize, GEMM_SMEM);
    cudaFuncSetAttribute(flash_attn_mma_kernel,
                         cudaFuncAttributeMaxDynamicSharedMemorySize, ATTN_SMEM);

    const int nx4 = (int)(NX / 4);
    const int nw4all = (int)(NW);

    // launch 0: x convert
    conv_f16_kernel<<<(nx4 + 255) / 256, 256>>>(x, xp, nx4);
    // launch 1: all 4 weight converts fused
    conv_w4_kernel<<<(nw4all + 255) / 256, 256>>>(W_q, W_k, W_v, W_o, Wp);

    // launch 2: fused QKV GEMM (Q epilogue pre-scales by SCALE_L2E)
    dim3 qkv_grid(3 * DM / 128, ROWS / 128);   // (24, 64)
    gemm_f16_kernel<true><<<qkv_grid, 256, GEMM_SMEM>>>(
        xp, Wp, nullptr, qkvp);

    // launch 3: attention  (<-- profiled launch)
    dim3 attn_grid(SEQ / 64, BATCH * NH);      // (32, 64)
    flash_attn_mma_kernel<<<attn_grid, 128, ATTN_SMEM>>>(
        qkvp, qkvp + NX, qkvp + 2 * NX, tp);

    // launch 4: output projection (fp32 out)
    dim3 o_grid(DM / 128, ROWS / 128);         // (8, 64)
    gemm_f16_kernel<false><<<o_grid, 256, GEMM_SMEM>>>(
        tp, Wp + 3 * NW, out, nullptr);
}